// round 4
// baseline (speedup 1.0000x reference)
#include <cuda_runtime.h>
#include <math.h>

// Problem constants
#define D_    1024
#define S_    1024
#define BB_   2
#define NTOK  2048
#define NH_   16
#define DH_   64
#define E_    8
#define KSEL  2
#define FF_   4096
#define NSLOT 4096

#define BM 128
#define BN 128
#define BK 32
#define AST 36            // A smem row stride (floats)
#define BST 136           // B smem row stride (floats)
#define ASZ (BM*AST)
#define BSZ_T (BM*AST)
#define BSZ_N (BK*BST)

// ---------------- static scratch ----------------
__device__ float g_xn[NTOK * D_];
__device__ float g_wqkv[3 * D_ * D_];
__device__ float g_woc[D_ * D_];
__device__ float g_qkv[3 * NTOK * D_];
__device__ float g_scores[(size_t)BB_ * NH_ * S_ * S_];
__device__ float g_attnout[NTOK * D_];
__device__ float g_x2[NTOK * D_];
__device__ float g_h[NTOK * D_];
__device__ float g_htf[NTOK * D_];
__device__ float g_act[(size_t)NSLOT * FF_];
__device__ float g_y[(size_t)NSLOT * D_];
__device__ float g_topval[NTOK * KSEL];
__device__ int   g_topidx[NTOK * KSEL];
__device__ int   g_slotof[NTOK * KSEL];
__device__ int   g_perm[NSLOT];
__device__ int   g_counts[E_];
__device__ int   g_offs[E_ + 1];
__device__ int   g_cursor[E_];
__device__ float g_probsum[E_];

// ---------------- helpers ----------------
__device__ __forceinline__ unsigned f2tf(float f) {
    unsigned u; asm("cvt.rna.tf32.f32 %0, %1;" : "=r"(u) : "f"(f)); return u;
}
__device__ __forceinline__ float rtf(float f) {
    return __uint_as_float(f2tf(f));
}
__device__ __forceinline__ void mma_tf32(float* d, const unsigned* a, const unsigned* b) {
    asm volatile(
        "mma.sync.aligned.m16n8k8.row.col.f32.tf32.tf32.f32 "
        "{%0,%1,%2,%3}, {%4,%5,%6,%7}, {%8,%9}, {%0,%1,%2,%3};"
        : "+f"(d[0]), "+f"(d[1]), "+f"(d[2]), "+f"(d[3])
        : "r"(a[0]), "r"(a[1]), "r"(a[2]), "r"(a[3]), "r"(b[0]), "r"(b[1]));
}
__device__ __forceinline__ void cpa16(unsigned dst, const float* src, bool p) {
    int sz = p ? 16 : 0;
    asm volatile("cp.async.cg.shared.global [%0], [%1], 16, %2;\n"
                 :: "r"(dst), "l"(src), "r"(sz));
}
__device__ __forceinline__ void cp_commit() {
    asm volatile("cp.async.commit_group;\n");
}
__device__ __forceinline__ float gelu_tanh(float v) {
    float v3 = v * v * v;
    return 0.5f * v * (1.f + tanhf(0.7978845608028654f * (v + 0.044715f * v3)));
}

// ---------------- small utility kernels ----------------
__global__ void init_kernel() {
    int i = threadIdx.x;
    if (i < E_) { g_counts[i] = 0; g_cursor[i] = 0; g_probsum[i] = 0.f; }
}

// pack wq|wk|wv (rounded) into g_wqkv, wo (rounded) into g_woc
__global__ void pack_w_kernel(const float* __restrict__ a,
                              const float* __restrict__ b,
                              const float* __restrict__ c,
                              const float* __restrict__ d) {
    int i = blockIdx.x * 256 + threadIdx.x;
    int n4 = D_ * D_ / 4;
    if (i < n4) {
        float4 va = ((const float4*)a)[i];
        float4 vb = ((const float4*)b)[i];
        float4 vc = ((const float4*)c)[i];
        float4 vd = ((const float4*)d)[i];
        va.x = rtf(va.x); va.y = rtf(va.y); va.z = rtf(va.z); va.w = rtf(va.w);
        vb.x = rtf(vb.x); vb.y = rtf(vb.y); vb.z = rtf(vb.z); vb.w = rtf(vb.w);
        vc.x = rtf(vc.x); vc.y = rtf(vc.y); vc.z = rtf(vc.z); vc.w = rtf(vc.w);
        vd.x = rtf(vd.x); vd.y = rtf(vd.y); vd.z = rtf(vd.z); vd.w = rtf(vd.w);
        float4* o = (float4*)g_wqkv;
        o[i] = va; o[n4 + i] = vb; o[2 * n4 + i] = vc;
        ((float4*)g_woc)[i] = vd;
    }
}

// O: exact output (nullable), OT: tf32-rounded output (nullable)
__global__ void rmsnorm_kernel(const float* __restrict__ X,
                               const float* __restrict__ W,
                               float* __restrict__ O,
                               float* __restrict__ OT) {
    int t = blockIdx.x;
    const float* x = X + (size_t)t * D_;
    float ss = 0.f;
    for (int d = threadIdx.x; d < D_; d += 256) { float v = x[d]; ss += v * v; }
    __shared__ float red[256];
    red[threadIdx.x] = ss;
    __syncthreads();
    for (int s = 128; s > 0; s >>= 1) {
        if (threadIdx.x < s) red[threadIdx.x] += red[threadIdx.x + s];
        __syncthreads();
    }
    float scale = rsqrtf(red[0] * (1.f / D_) + 1e-6f);
    for (int d = threadIdx.x; d < D_; d += 256) {
        float v = x[d] * scale * W[d];
        if (O)  O[(size_t)t * D_ + d] = v;
        if (OT) OT[(size_t)t * D_ + d] = rtf(v);
    }
}

__global__ void softmax_kernel(float* __restrict__ SC) {
    int row = blockIdx.x;
    int bh = row >> 10, q = row & 1023;
    float* s = SC + (size_t)bh * S_ * S_ + (size_t)q * S_;
    int len = q + 1;
    int tid = threadIdx.x;
    __shared__ float red[128];
    float mx = -1e30f;
    for (int j = tid; j < len; j += 128) mx = fmaxf(mx, s[j]);
    red[tid] = mx; __syncthreads();
    for (int st = 64; st > 0; st >>= 1) {
        if (tid < st) red[tid] = fmaxf(red[tid], red[tid + st]);
        __syncthreads();
    }
    mx = red[0] * 0.125f;
    __syncthreads();
    float sum = 0.f;
    for (int j = tid; j < len; j += 128) {
        float p = expf(s[j] * 0.125f - mx);
        s[j] = p;
        sum += p;
    }
    red[tid] = sum; __syncthreads();
    for (int st = 64; st > 0; st >>= 1) {
        if (tid < st) red[tid] += red[tid + st];
        __syncthreads();
    }
    float inv = 1.f / red[0];
    for (int j = tid; j < len; j += 128) s[j] = rtf(s[j] * inv);
    for (int j = len + tid; j < S_; j += 128) s[j] = 0.f;
}

__global__ void router_kernel(const float* __restrict__ H,
                              const float* __restrict__ RW) {
    int t = blockIdx.x;
    int tid = threadIdx.x;
    int e = tid >> 5, lane = tid & 31;
    const float* h = H + (size_t)t * D_;
    float p = 0.f;
    for (int d = lane; d < D_; d += 32) p += h[d] * RW[d * E_ + e];
    for (int o = 16; o > 0; o >>= 1) p += __shfl_down_sync(0xffffffff, p, o);
    __shared__ float lg[E_];
    if (lane == 0) lg[e] = p;
    __syncthreads();
    if (tid == 0) {
        float mx = lg[0];
        for (int i = 1; i < E_; i++) mx = fmaxf(mx, lg[i]);
        float pr[E_]; float s = 0.f;
        for (int i = 0; i < E_; i++) { pr[i] = expf(lg[i] - mx); s += pr[i]; }
        float inv = 1.f / s;
        float b1v = -1.f, b2v = -1.f; int b1i = 0, b2i = 0;
        for (int i = 0; i < E_; i++) {
            float v = pr[i] * inv;
            atomicAdd(&g_probsum[i], v);
            if (v > b1v) { b2v = b1v; b2i = b1i; b1v = v; b1i = i; }
            else if (v > b2v) { b2v = v; b2i = i; }
        }
        g_topidx[t * 2] = b1i; g_topidx[t * 2 + 1] = b2i;
        g_topval[t * 2] = b1v; g_topval[t * 2 + 1] = b2v;
        atomicAdd(&g_counts[b1i], 1);
        atomicAdd(&g_counts[b2i], 1);
    }
}

__global__ void scan_kernel() {
    if (threadIdx.x == 0) {
        g_offs[0] = 0;
        for (int e = 0; e < E_; e++) {
            g_offs[e + 1] = g_offs[e] + g_counts[e];
            g_cursor[e] = g_offs[e];
        }
    }
}

__global__ void place_kernel() {
    int t = blockIdx.x * blockDim.x + threadIdx.x;
    if (t >= NTOK) return;
    for (int kk = 0; kk < KSEL; kk++) {
        int e = g_topidx[t * 2 + kk];
        int slot = atomicAdd(&g_cursor[e], 1);
        g_perm[slot] = t;
        g_slotof[t * 2 + kk] = slot;
    }
}

__global__ void combine_kernel(float* __restrict__ out) {
    int idx = blockIdx.x * blockDim.x + threadIdx.x;
    if (idx >= NTOK * D_) return;
    int t = idx >> 10, d = idx & 1023;
    float v = g_x2[idx];
    v += g_topval[t * 2]     * g_y[(size_t)g_slotof[t * 2]     * D_ + d];
    v += g_topval[t * 2 + 1] * g_y[(size_t)g_slotof[t * 2 + 1] * D_ + d];
    out[idx] = v;
}

__global__ void finalize_kernel(float* __restrict__ out) {
    if (threadIdx.x == 0) {
        float loss = 0.f;
        for (int e = 0; e < E_; e++)
            loss += ((float)g_counts[e] / (float)NSLOT) * (g_probsum[e] / (float)NTOK);
        loss *= (float)E_;
        out[(size_t)NTOK * D_] = loss;
        for (int e = 0; e < E_; e++)
            out[(size_t)NTOK * D_ + 1 + e] = (float)g_counts[e];
    }
}

// ---------------- tf32 MMA GEMM: 128x128x32, 4 warps of 64x64, cp.async ---
// TB: B stored [N,K] (A*B^T).
// EPI: 0 exact store, 1 residual-add (exact), 2 tf32-rounded store.
// mode: 0 none, 1 causal tile-skip, 2 k-clip.
// NOTE: A and B in gmem must already be tf32-representable values.
template <bool TB, int EPI>
__global__ void __launch_bounds__(128, 2)
mgemm(const float* __restrict__ A, int lda,
      const float* __restrict__ Bmat, int ldb,
      float* __restrict__ C, int ldc,
      int M, int N, int K,
      long long aO, long long aI, long long bO, long long bI,
      long long cO, long long cI, int zdiv,
      const float* __restrict__ addp, int mode) {
    constexpr int BSZ = TB ? BSZ_T : BSZ_N;
    constexpr int STG = ASZ + BSZ;
    extern __shared__ float sm[];

    int z = blockIdx.z;
    int zo = z / zdiv, zi = z % zdiv;
    A += zo * aO + zi * aI;
    Bmat += zo * bO + zi * bI;
    C += zo * cO + zi * cI;

    int m0 = blockIdx.y * BM, n0 = blockIdx.x * BN;
    if (mode == 1 && n0 > m0 + (BM - 1)) return;
    int Keff = (mode == 2) ? min(K, m0 + BM) : K;

    int tid = threadIdx.x;
    int wid = tid >> 5, lane = tid & 31;
    int warpM = wid & 1, warpN = wid >> 1;
    int g = lane >> 2, t = lane & 3;

    unsigned smb;
    {
        unsigned long long p = __cvta_generic_to_shared(sm);
        smb = (unsigned)p;
    }

    bool av = (m0 + tid) < M;
    const float* aptr = A + (size_t)(av ? (m0 + tid) : 0) * lda;
    const float* bptr = nullptr;
    bool bv = true;
    if (TB) {
        bv = (n0 + tid) < N;
        bptr = Bmat + (size_t)(bv ? (n0 + tid) : 0) * ldb;
    }

    float acc[4][8][4];
#pragma unroll
    for (int mt = 0; mt < 4; mt++)
#pragma unroll
        for (int nt = 0; nt < 8; nt++)
#pragma unroll
            for (int r = 0; r < 4; r++) acc[mt][nt][r] = 0.f;

    int KT = (Keff + BK - 1) / BK;

    auto issue = [&](int s, int kt) {
        int k0 = kt * BK;
        unsigned abase = smb + (unsigned)(s * STG) * 4u;
        unsigned bbase = abase + ASZ * 4u;
#pragma unroll
        for (int c = 0; c < 8; c++)
            cpa16(abase + (unsigned)(tid * AST + c * 4) * 4u, aptr + k0 + c * 4, av);
        if (TB) {
#pragma unroll
            for (int c = 0; c < 8; c++)
                cpa16(bbase + (unsigned)(tid * AST + c * 4) * 4u, bptr + k0 + c * 4, bv);
        } else {
#pragma unroll
            for (int c = 0; c < 8; c++) {
                int idx = c * 128 + tid;
                int r = idx >> 5, c4 = (idx & 31) * 4;
                cpa16(bbase + (unsigned)(r * BST + c4) * 4u,
                      Bmat + (size_t)(k0 + r) * ldb + n0 + c4, (n0 + c4) < N);
            }
        }
        cp_commit();
    };

    issue(0, 0);
    for (int kt = 0; kt < KT; kt++) {
        int b = kt & 1;
        if (kt + 1 < KT) {
            issue(b ^ 1, kt + 1);
            asm volatile("cp.async.wait_group 1;\n");
        } else {
            asm volatile("cp.async.wait_group 0;\n");
        }
        __syncthreads();

        const float* As_ = sm + b * STG;
        const float* Bs_ = As_ + ASZ;
#pragma unroll
        for (int ks = 0; ks < 4; ks++) {
            int kk = ks * 8;
            unsigned afr[4][4];
#pragma unroll
            for (int mt = 0; mt < 4; mt++) {
                int am = warpM * 64 + mt * 16;
                afr[mt][0] = __float_as_uint(As_[(am + g) * AST + kk + t]);
                afr[mt][1] = __float_as_uint(As_[(am + g + 8) * AST + kk + t]);
                afr[mt][2] = __float_as_uint(As_[(am + g) * AST + kk + t + 4]);
                afr[mt][3] = __float_as_uint(As_[(am + g + 8) * AST + kk + t + 4]);
            }
            unsigned bfr[8][2];
#pragma unroll
            for (int nt = 0; nt < 8; nt++) {
                int bn = warpN * 64 + nt * 8;
                if (TB) {
                    bfr[nt][0] = __float_as_uint(Bs_[(bn + g) * AST + kk + t]);
                    bfr[nt][1] = __float_as_uint(Bs_[(bn + g) * AST + kk + t + 4]);
                } else {
                    bfr[nt][0] = __float_as_uint(Bs_[(kk + t) * BST + bn + g]);
                    bfr[nt][1] = __float_as_uint(Bs_[(kk + t + 4) * BST + bn + g]);
                }
            }
#pragma unroll
            for (int mt = 0; mt < 4; mt++)
#pragma unroll
                for (int nt = 0; nt < 8; nt++)
                    mma_tf32(acc[mt][nt], afr[mt], bfr[nt]);
        }
        __syncthreads();
    }

    // epilogue
#pragma unroll
    for (int mt = 0; mt < 4; mt++) {
#pragma unroll
        for (int nt = 0; nt < 8; nt++) {
            int row = m0 + warpM * 64 + mt * 16 + g;
            int col = n0 + warpN * 64 + nt * 8 + 2 * t;
#pragma unroll
            for (int half = 0; half < 2; half++) {
                int r = row + half * 8;
                if (r < M && col < N) {
                    float v0 = acc[mt][nt][half * 2 + 0];
                    float v1 = acc[mt][nt][half * 2 + 1];
                    if (EPI == 1) {
                        float2 ad = *(const float2*)(addp + (size_t)r * ldc + col);
                        v0 += ad.x; v1 += ad.y;
                    } else if (EPI == 2) {
                        v0 = rtf(v0); v1 = rtf(v1);
                    }
                    float2 o; o.x = v0; o.y = v1;
                    *(float2*)(C + (size_t)r * ldc + col) = o;
                }
            }
        }
    }
}

// ---------------- grouped MoE GEMMs (tf32 MMA, cp.async) ----------------
// EP 1: round(gelu(acc+b1)) -> g_act  (A = g_htf gathered, already tf32)
// EP 2: acc+b2 -> g_y (exact)         (A = g_act, already tf32)
// B (raw fp32 weights) is RNA-rounded in-register at fragment load.
template <int EP>
__global__ void __launch_bounds__(128, 2)
moe_mgemm(const float* __restrict__ H,
          const float* __restrict__ W,
          const float* __restrict__ Bias,
          int Kdim, int Ndim) {
    constexpr int STG = ASZ + BSZ_N;
    extern __shared__ float sm[];

    int e = blockIdx.z;
    int base = g_offs[e], cnt = g_offs[e + 1] - base;
    int m0 = blockIdx.y * BM;
    if (m0 >= cnt) return;
    int n0 = blockIdx.x * BN;
    const float* Bmat = W + (size_t)e * Kdim * Ndim;

    int tid = threadIdx.x;
    int wid = tid >> 5, lane = tid & 31;
    int warpM = wid & 1, warpN = wid >> 1;
    int g = lane >> 2, t = lane & 3;

    unsigned smb;
    {
        unsigned long long p = __cvta_generic_to_shared(sm);
        smb = (unsigned)p;
    }

    bool av = (m0 + tid) < cnt;
    const float* aptr;
    if (EP == 1) aptr = H + (size_t)(av ? g_perm[base + m0 + tid] : 0) * Kdim;
    else         aptr = g_act + (size_t)(av ? (base + m0 + tid) : 0) * Kdim;

    float acc[4][8][4];
#pragma unroll
    for (int mt = 0; mt < 4; mt++)
#pragma unroll
        for (int nt = 0; nt < 8; nt++)
#pragma unroll
            for (int r = 0; r < 4; r++) acc[mt][nt][r] = 0.f;

    int KT = Kdim / BK;

    auto issue = [&](int s, int kt) {
        int k0 = kt * BK;
        unsigned abase = smb + (unsigned)(s * STG) * 4u;
        unsigned bbase = abase + ASZ * 4u;
#pragma unroll
        for (int c = 0; c < 8; c++)
            cpa16(abase + (unsigned)(tid * AST + c * 4) * 4u, aptr + k0 + c * 4, av);
#pragma unroll
        for (int c = 0; c < 8; c++) {
            int idx = c * 128 + tid;
            int r = idx >> 5, c4 = (idx & 31) * 4;
            cpa16(bbase + (unsigned)(r * BST + c4) * 4u,
                  Bmat + (size_t)(k0 + r) * Ndim + n0 + c4, true);
        }
        cp_commit();
    };

    issue(0, 0);
    for (int kt = 0; kt < KT; kt++) {
        int b = kt & 1;
        if (kt + 1 < KT) {
            issue(b ^ 1, kt + 1);
            asm volatile("cp.async.wait_group 1;\n");
        } else {
            asm volatile("cp.async.wait_group 0;\n");
        }
        __syncthreads();

        const float* As_ = sm + b * STG;
        const float* Bs_ = As_ + ASZ;
#pragma unroll
        for (int ks = 0; ks < 4; ks++) {
            int kk = ks * 8;
            unsigned afr[4][4];
#pragma unroll
            for (int mt = 0; mt < 4; mt++) {
                int am = warpM * 64 + mt * 16;
                afr[mt][0] = __float_as_uint(As_[(am + g) * AST + kk + t]);
                afr[mt][1] = __float_as_uint(As_[(am + g + 8) * AST + kk + t]);
                afr[mt][2] = __float_as_uint(As_[(am + g) * AST + kk + t + 4]);
                afr[mt][3] = __float_as_uint(As_[(am + g + 8) * AST + kk + t + 4]);
            }
            unsigned bfr[8][2];
#pragma unroll
            for (int nt = 0; nt < 8; nt++) {
                int bn = warpN * 64 + nt * 8;
                bfr[nt][0] = f2tf(Bs_[(kk + t) * BST + bn + g]);
                bfr[nt][1] = f2tf(Bs_[(kk + t + 4) * BST + bn + g]);
            }
#pragma unroll
            for (int mt = 0; mt < 4; mt++)
#pragma unroll
                for (int nt = 0; nt < 8; nt++)
                    mma_tf32(acc[mt][nt], afr[mt], bfr[nt]);
        }
        __syncthreads();
    }

    // epilogue
#pragma unroll
    for (int mt = 0; mt < 4; mt++) {
#pragma unroll
        for (int nt = 0; nt < 8; nt++) {
            int rr = m0 + warpM * 64 + mt * 16 + g;
            int col = n0 + warpN * 64 + nt * 8 + 2 * t;
#pragma unroll
            for (int half = 0; half < 2; half++) {
                int r = rr + half * 8;
                if (r < cnt) {
                    float b0 = Bias[(size_t)e * Ndim + col];
                    float b1v = Bias[(size_t)e * Ndim + col + 1];
                    float v0 = acc[mt][nt][half * 2 + 0] + b0;
                    float v1 = acc[mt][nt][half * 2 + 1] + b1v;
                    float2 o;
                    if (EP == 1) {
                        o.x = rtf(gelu_tanh(v0)); o.y = rtf(gelu_tanh(v1));
                        *(float2*)(g_act + (size_t)(base + r) * FF_ + col) = o;
                    } else {
                        o.x = v0; o.y = v1;
                        *(float2*)(g_y + (size_t)(base + r) * D_ + col) = o;
                    }
                }
            }
        }
    }
}

// ---------------- launch ----------------
#define SMEM_N ((ASZ + BSZ_N) * 2 * 4)
#define SMEM_T ((ASZ + BSZ_T) * 2 * 4)

extern "C" void kernel_launch(void* const* d_in, const int* in_sizes, int n_in,
                              void* d_out, int out_size) {
    const float* x   = (const float*)d_in[0];
    const float* anw = (const float*)d_in[1];
    const float* wq  = (const float*)d_in[2];
    const float* wk  = (const float*)d_in[3];
    const float* wv  = (const float*)d_in[4];
    const float* wo  = (const float*)d_in[5];
    const float* mnw = (const float*)d_in[6];
    const float* rw  = (const float*)d_in[7];
    const float* w1  = (const float*)d_in[8];
    const float* b1  = (const float*)d_in[9];
    const float* w2  = (const float*)d_in[10];
    const float* b2  = (const float*)d_in[11];
    float* out = (float*)d_out;

    cudaFuncSetAttribute(mgemm<false, 0>, cudaFuncAttributeMaxDynamicSharedMemorySize, SMEM_N);
    cudaFuncSetAttribute(mgemm<false, 1>, cudaFuncAttributeMaxDynamicSharedMemorySize, SMEM_N);
    cudaFuncSetAttribute(mgemm<false, 2>, cudaFuncAttributeMaxDynamicSharedMemorySize, SMEM_N);
    cudaFuncSetAttribute(mgemm<true, 0>,  cudaFuncAttributeMaxDynamicSharedMemorySize, SMEM_T);
    cudaFuncSetAttribute(moe_mgemm<1>,    cudaFuncAttributeMaxDynamicSharedMemorySize, SMEM_N);
    cudaFuncSetAttribute(moe_mgemm<2>,    cudaFuncAttributeMaxDynamicSharedMemorySize, SMEM_N);

    float *xn, *wqkv, *woc, *qkv, *sc, *ao, *x2, *h, *htf;
    cudaGetSymbolAddress((void**)&xn,   g_xn);
    cudaGetSymbolAddress((void**)&wqkv, g_wqkv);
    cudaGetSymbolAddress((void**)&woc,  g_woc);
    cudaGetSymbolAddress((void**)&qkv,  g_qkv);
    cudaGetSymbolAddress((void**)&sc,   g_scores);
    cudaGetSymbolAddress((void**)&ao,   g_attnout);
    cudaGetSymbolAddress((void**)&x2,   g_x2);
    cudaGetSymbolAddress((void**)&h,    g_h);
    cudaGetSymbolAddress((void**)&htf,  g_htf);

    const float* q = qkv;
    const float* k = qkv + (size_t)NTOK * D_;
    const float* v = qkv + 2 * (size_t)NTOK * D_;

    init_kernel<<<1, 32>>>();
    pack_w_kernel<<<(D_ * D_ / 4 + 255) / 256, 256>>>(wq, wk, wv, wo);
    // xn: rounded only (feeds QKV gemm)
    rmsnorm_kernel<<<NTOK, 256>>>(x, anw, nullptr, xn);

    // fused QKV (z=3), outputs rounded (feed QK^T / PV gemms)
    {
        dim3 g(8, 16, 3);
        mgemm<false, 2><<<g, 128, SMEM_N>>>(xn, D_, wqkv, D_, qkv, D_, NTOK, D_, D_,
                                            0, 0, (long long)D_ * D_, 0,
                                            (long long)NTOK * D_, 0, 1, nullptr, 0);
    }

    // scores = Q @ K^T per (b,h), causal tile skip (output exact; softmax rounds)
    {
        dim3 g(8, 8, BB_ * NH_);
        long long sSD = (long long)S_ * D_;
        long long sSS = (long long)S_ * S_;
        mgemm<true, 0><<<g, 128, SMEM_T>>>(q, D_, k, D_, sc, S_, S_, S_, DH_,
                                           sSD, DH_, sSD, DH_, NH_ * sSS, sSS, NH_,
                                           nullptr, 1);
    }

    softmax_kernel<<<BB_ * NH_ * S_, 128>>>(sc);

    // attnout = P @ V per (b,h), k-clipped, output rounded (feeds WO gemm)
    {
        dim3 g(1, 8, BB_ * NH_);
        long long sSD = (long long)S_ * D_;
        long long sSS = (long long)S_ * S_;
        mgemm<false, 2><<<g, 128, SMEM_N>>>(sc, S_, v, D_, ao, D_, S_, DH_, S_,
                                            NH_ * sSS, sSS, sSD, DH_, sSD, DH_, NH_,
                                            nullptr, 2);
    }

    // x2 = x + attnout @ wo  (exact residual)
    {
        dim3 g(8, 16, 1);
        mgemm<false, 1><<<g, 128, SMEM_N>>>(ao, D_, woc, D_, x2, D_, NTOK, D_, D_,
                                            0, 0, 0, 0, 0, 0, 1, x, 0);
    }

    // h exact (router) + htf rounded (MoE gemm1 A-side)
    rmsnorm_kernel<<<NTOK, 256>>>(x2, mnw, h, htf);
    router_kernel<<<NTOK, 256>>>(h, rw);
    scan_kernel<<<1, 1>>>();
    place_kernel<<<(NTOK + 255) / 256, 256>>>();

    moe_mgemm<1><<<dim3(FF_ / 128, NSLOT / 128, E_), 128, SMEM_N>>>(htf, w1, b1, D_, FF_);
    moe_mgemm<2><<<dim3(D_ / 128, NSLOT / 128, E_), 128, SMEM_N>>>(nullptr, w2, b2, FF_, D_);

    combine_kernel<<<(NTOK * D_ + 255) / 256, 256>>>(out);
    finalize_kernel<<<1, 32>>>(out);
}

// round 5
// speedup vs baseline: 1.0005x; 1.0005x over previous
#include <cuda_runtime.h>
#include <math.h>

// Problem constants
#define D_    1024
#define S_    1024
#define BB_   2
#define NTOK  2048
#define NH_   16
#define DH_   64
#define E_    8
#define KSEL  2
#define FF_   4096
#define NSLOT 4096

#define BM 128
#define BN 128
#define BK 32
#define AST 36            // A smem row stride (floats)
#define BST 136           // B smem row stride (floats)
#define ASZ (BM*AST)
#define BSZ_T (BM*AST)
#define BSZ_N (BK*BST)

// ---------------- static scratch ----------------
__device__ float g_xn[NTOK * D_];
__device__ float g_wqkv[3 * D_ * D_];
__device__ float g_woc[D_ * D_];
__device__ float g_qkv[3 * NTOK * D_];
__device__ float g_scores[(size_t)BB_ * NH_ * S_ * S_];
__device__ float g_attnout[NTOK * D_];
__device__ float g_x2[NTOK * D_];
__device__ float g_h[NTOK * D_];
__device__ float g_htf[NTOK * D_];
__device__ float g_act[(size_t)NSLOT * FF_];
__device__ float g_y[(size_t)NSLOT * D_];
__device__ float g_topval[NTOK * KSEL];
__device__ int   g_topidx[NTOK * KSEL];
__device__ int   g_slotof[NTOK * KSEL];
__device__ int   g_perm[NSLOT];
__device__ int   g_counts[E_];
__device__ int   g_offs[E_ + 1];
__device__ int   g_cursor[E_];
__device__ float g_probsum[E_];

// ---------------- helpers ----------------
__device__ __forceinline__ unsigned f2tf(float f) {
    unsigned u; asm("cvt.rna.tf32.f32 %0, %1;" : "=r"(u) : "f"(f)); return u;
}
__device__ __forceinline__ float rtf(float f) {
    return __uint_as_float(f2tf(f));
}
__device__ __forceinline__ void mma_tf32(float* d, const unsigned* a, const unsigned* b) {
    asm volatile(
        "mma.sync.aligned.m16n8k8.row.col.f32.tf32.tf32.f32 "
        "{%0,%1,%2,%3}, {%4,%5,%6,%7}, {%8,%9}, {%0,%1,%2,%3};"
        : "+f"(d[0]), "+f"(d[1]), "+f"(d[2]), "+f"(d[3])
        : "r"(a[0]), "r"(a[1]), "r"(a[2]), "r"(a[3]), "r"(b[0]), "r"(b[1]));
}
__device__ __forceinline__ void cpa16(unsigned dst, const float* src, bool p) {
    int sz = p ? 16 : 0;
    asm volatile("cp.async.cg.shared.global [%0], [%1], 16, %2;\n"
                 :: "r"(dst), "l"(src), "r"(sz));
}
__device__ __forceinline__ void cp_commit() {
    asm volatile("cp.async.commit_group;\n");
}
__device__ __forceinline__ float gelu_tanh(float v) {
    float v3 = v * v * v;
    return 0.5f * v * (1.f + tanhf(0.7978845608028654f * (v + 0.044715f * v3)));
}

// ---------------- small utility kernels ----------------
__global__ void init_kernel() {
    int i = threadIdx.x;
    if (i < E_) { g_counts[i] = 0; g_cursor[i] = 0; g_probsum[i] = 0.f; }
}

// pack wq|wk|wv (rounded) into g_wqkv, wo (rounded) into g_woc
__global__ void pack_w_kernel(const float* __restrict__ a,
                              const float* __restrict__ b,
                              const float* __restrict__ c,
                              const float* __restrict__ d) {
    int i = blockIdx.x * 256 + threadIdx.x;
    int n4 = D_ * D_ / 4;
    if (i < n4) {
        float4 va = ((const float4*)a)[i];
        float4 vb = ((const float4*)b)[i];
        float4 vc = ((const float4*)c)[i];
        float4 vd = ((const float4*)d)[i];
        va.x = rtf(va.x); va.y = rtf(va.y); va.z = rtf(va.z); va.w = rtf(va.w);
        vb.x = rtf(vb.x); vb.y = rtf(vb.y); vb.z = rtf(vb.z); vb.w = rtf(vb.w);
        vc.x = rtf(vc.x); vc.y = rtf(vc.y); vc.z = rtf(vc.z); vc.w = rtf(vc.w);
        vd.x = rtf(vd.x); vd.y = rtf(vd.y); vd.z = rtf(vd.z); vd.w = rtf(vd.w);
        float4* o = (float4*)g_wqkv;
        o[i] = va; o[n4 + i] = vb; o[2 * n4 + i] = vc;
        ((float4*)g_woc)[i] = vd;
    }
}

// O: exact output (nullable), OT: tf32-rounded output (nullable)
__global__ void rmsnorm_kernel(const float* __restrict__ X,
                               const float* __restrict__ W,
                               float* __restrict__ O,
                               float* __restrict__ OT) {
    int t = blockIdx.x;
    const float* x = X + (size_t)t * D_;
    float ss = 0.f;
    for (int d = threadIdx.x; d < D_; d += 256) { float v = x[d]; ss += v * v; }
    __shared__ float red[256];
    red[threadIdx.x] = ss;
    __syncthreads();
    for (int s = 128; s > 0; s >>= 1) {
        if (threadIdx.x < s) red[threadIdx.x] += red[threadIdx.x + s];
        __syncthreads();
    }
    float scale = rsqrtf(red[0] * (1.f / D_) + 1e-6f);
    for (int d = threadIdx.x; d < D_; d += 256) {
        float v = x[d] * scale * W[d];
        if (O)  O[(size_t)t * D_ + d] = v;
        if (OT) OT[(size_t)t * D_ + d] = rtf(v);
    }
}

__global__ void softmax_kernel(float* __restrict__ SC) {
    int row = blockIdx.x;
    int bh = row >> 10, q = row & 1023;
    float* s = SC + (size_t)bh * S_ * S_ + (size_t)q * S_;
    int len = q + 1;
    int tid = threadIdx.x;
    __shared__ float red[128];
    float mx = -1e30f;
    for (int j = tid; j < len; j += 128) mx = fmaxf(mx, s[j]);
    red[tid] = mx; __syncthreads();
    for (int st = 64; st > 0; st >>= 1) {
        if (tid < st) red[tid] = fmaxf(red[tid], red[tid + st]);
        __syncthreads();
    }
    mx = red[0] * 0.125f;
    __syncthreads();
    float sum = 0.f;
    for (int j = tid; j < len; j += 128) {
        float p = expf(s[j] * 0.125f - mx);
        s[j] = p;
        sum += p;
    }
    red[tid] = sum; __syncthreads();
    for (int st = 64; st > 0; st >>= 1) {
        if (tid < st) red[tid] += red[tid + st];
        __syncthreads();
    }
    float inv = 1.f / red[0];
    for (int j = tid; j < len; j += 128) s[j] = rtf(s[j] * inv);
    for (int j = len + tid; j < S_; j += 128) s[j] = 0.f;
}

__global__ void router_kernel(const float* __restrict__ H,
                              const float* __restrict__ RW) {
    int t = blockIdx.x;
    int tid = threadIdx.x;
    int e = tid >> 5, lane = tid & 31;
    const float* h = H + (size_t)t * D_;
    float p = 0.f;
    for (int d = lane; d < D_; d += 32) p += h[d] * RW[d * E_ + e];
    for (int o = 16; o > 0; o >>= 1) p += __shfl_down_sync(0xffffffff, p, o);
    __shared__ float lg[E_];
    if (lane == 0) lg[e] = p;
    __syncthreads();
    if (tid == 0) {
        float mx = lg[0];
        for (int i = 1; i < E_; i++) mx = fmaxf(mx, lg[i]);
        float pr[E_]; float s = 0.f;
        for (int i = 0; i < E_; i++) { pr[i] = expf(lg[i] - mx); s += pr[i]; }
        float inv = 1.f / s;
        float b1v = -1.f, b2v = -1.f; int b1i = 0, b2i = 0;
        for (int i = 0; i < E_; i++) {
            float v = pr[i] * inv;
            atomicAdd(&g_probsum[i], v);
            if (v > b1v) { b2v = b1v; b2i = b1i; b1v = v; b1i = i; }
            else if (v > b2v) { b2v = v; b2i = i; }
        }
        g_topidx[t * 2] = b1i; g_topidx[t * 2 + 1] = b2i;
        g_topval[t * 2] = b1v; g_topval[t * 2 + 1] = b2v;
        atomicAdd(&g_counts[b1i], 1);
        atomicAdd(&g_counts[b2i], 1);
    }
}

__global__ void scan_kernel() {
    if (threadIdx.x == 0) {
        g_offs[0] = 0;
        for (int e = 0; e < E_; e++) {
            g_offs[e + 1] = g_offs[e] + g_counts[e];
            g_cursor[e] = g_offs[e];
        }
    }
}

__global__ void place_kernel() {
    int t = blockIdx.x * blockDim.x + threadIdx.x;
    if (t >= NTOK) return;
    for (int kk = 0; kk < KSEL; kk++) {
        int e = g_topidx[t * 2 + kk];
        int slot = atomicAdd(&g_cursor[e], 1);
        g_perm[slot] = t;
        g_slotof[t * 2 + kk] = slot;
    }
}

__global__ void combine_kernel(float* __restrict__ out) {
    int idx = blockIdx.x * blockDim.x + threadIdx.x;
    if (idx >= NTOK * D_) return;
    int t = idx >> 10, d = idx & 1023;
    float v = g_x2[idx];
    v += g_topval[t * 2]     * g_y[(size_t)g_slotof[t * 2]     * D_ + d];
    v += g_topval[t * 2 + 1] * g_y[(size_t)g_slotof[t * 2 + 1] * D_ + d];
    out[idx] = v;
}

__global__ void finalize_kernel(float* __restrict__ out) {
    if (threadIdx.x == 0) {
        float loss = 0.f;
        for (int e = 0; e < E_; e++)
            loss += ((float)g_counts[e] / (float)NSLOT) * (g_probsum[e] / (float)NTOK);
        loss *= (float)E_;
        out[(size_t)NTOK * D_] = loss;
        for (int e = 0; e < E_; e++)
            out[(size_t)NTOK * D_ + 1 + e] = (float)g_counts[e];
    }
}

// ---------------- tf32 MMA GEMM: 128x128x32, 4 warps of 64x64, cp.async ---
// TB: B stored [N,K] (A*B^T).
// EPI: 0 exact store, 1 residual-add (exact), 2 tf32-rounded store.
// mode: 0 none, 1 causal tile-skip, 2 k-clip.
// NOTE: A and B in gmem must already be tf32-representable values.
template <bool TB, int EPI>
__global__ void __launch_bounds__(128, 2)
mgemm(const float* __restrict__ A, int lda,
      const float* __restrict__ Bmat, int ldb,
      float* __restrict__ C, int ldc,
      int M, int N, int K,
      long long aO, long long aI, long long bO, long long bI,
      long long cO, long long cI, int zdiv,
      const float* __restrict__ addp, int mode) {
    constexpr int BSZ = TB ? BSZ_T : BSZ_N;
    constexpr int STG = ASZ + BSZ;
    extern __shared__ float sm[];

    int z = blockIdx.z;
    int zo = z / zdiv, zi = z % zdiv;
    A += zo * aO + zi * aI;
    Bmat += zo * bO + zi * bI;
    C += zo * cO + zi * cI;

    int m0 = blockIdx.y * BM, n0 = blockIdx.x * BN;
    if (mode == 1 && n0 > m0 + (BM - 1)) return;
    int Keff = (mode == 2) ? min(K, m0 + BM) : K;

    int tid = threadIdx.x;
    int wid = tid >> 5, lane = tid & 31;
    int warpM = wid & 1, warpN = wid >> 1;
    int g = lane >> 2, t = lane & 3;

    unsigned smb;
    {
        unsigned long long p = __cvta_generic_to_shared(sm);
        smb = (unsigned)p;
    }

    bool av = (m0 + tid) < M;
    const float* aptr = A + (size_t)(av ? (m0 + tid) : 0) * lda;
    const float* bptr = nullptr;
    bool bv = true;
    if (TB) {
        bv = (n0 + tid) < N;
        bptr = Bmat + (size_t)(bv ? (n0 + tid) : 0) * ldb;
    }

    float acc[4][8][4];
#pragma unroll
    for (int mt = 0; mt < 4; mt++)
#pragma unroll
        for (int nt = 0; nt < 8; nt++)
#pragma unroll
            for (int r = 0; r < 4; r++) acc[mt][nt][r] = 0.f;

    int KT = (Keff + BK - 1) / BK;

    auto issue = [&](int s, int kt) {
        int k0 = kt * BK;
        unsigned abase = smb + (unsigned)(s * STG) * 4u;
        unsigned bbase = abase + ASZ * 4u;
#pragma unroll
        for (int c = 0; c < 8; c++)
            cpa16(abase + (unsigned)(tid * AST + c * 4) * 4u, aptr + k0 + c * 4, av);
        if (TB) {
#pragma unroll
            for (int c = 0; c < 8; c++)
                cpa16(bbase + (unsigned)(tid * AST + c * 4) * 4u, bptr + k0 + c * 4, bv);
        } else {
#pragma unroll
            for (int c = 0; c < 8; c++) {
                int idx = c * 128 + tid;
                int r = idx >> 5, c4 = (idx & 31) * 4;
                cpa16(bbase + (unsigned)(r * BST + c4) * 4u,
                      Bmat + (size_t)(k0 + r) * ldb + n0 + c4, (n0 + c4) < N);
            }
        }
        cp_commit();
    };

    issue(0, 0);
    for (int kt = 0; kt < KT; kt++) {
        int b = kt & 1;
        if (kt + 1 < KT) {
            issue(b ^ 1, kt + 1);
            asm volatile("cp.async.wait_group 1;\n");
        } else {
            asm volatile("cp.async.wait_group 0;\n");
        }
        __syncthreads();

        const float* As_ = sm + b * STG;
        const float* Bs_ = As_ + ASZ;
#pragma unroll
        for (int ks = 0; ks < 4; ks++) {
            int kk = ks * 8;
            unsigned afr[4][4];
#pragma unroll
            for (int mt = 0; mt < 4; mt++) {
                int am = warpM * 64 + mt * 16;
                afr[mt][0] = __float_as_uint(As_[(am + g) * AST + kk + t]);
                afr[mt][1] = __float_as_uint(As_[(am + g + 8) * AST + kk + t]);
                afr[mt][2] = __float_as_uint(As_[(am + g) * AST + kk + t + 4]);
                afr[mt][3] = __float_as_uint(As_[(am + g + 8) * AST + kk + t + 4]);
            }
            unsigned bfr[8][2];
#pragma unroll
            for (int nt = 0; nt < 8; nt++) {
                int bn = warpN * 64 + nt * 8;
                if (TB) {
                    bfr[nt][0] = __float_as_uint(Bs_[(bn + g) * AST + kk + t]);
                    bfr[nt][1] = __float_as_uint(Bs_[(bn + g) * AST + kk + t + 4]);
                } else {
                    bfr[nt][0] = __float_as_uint(Bs_[(kk + t) * BST + bn + g]);
                    bfr[nt][1] = __float_as_uint(Bs_[(kk + t + 4) * BST + bn + g]);
                }
            }
#pragma unroll
            for (int mt = 0; mt < 4; mt++)
#pragma unroll
                for (int nt = 0; nt < 8; nt++)
                    mma_tf32(acc[mt][nt], afr[mt], bfr[nt]);
        }
        __syncthreads();
    }

    // epilogue
#pragma unroll
    for (int mt = 0; mt < 4; mt++) {
#pragma unroll
        for (int nt = 0; nt < 8; nt++) {
            int row = m0 + warpM * 64 + mt * 16 + g;
            int col = n0 + warpN * 64 + nt * 8 + 2 * t;
#pragma unroll
            for (int half = 0; half < 2; half++) {
                int r = row + half * 8;
                if (r < M && col < N) {
                    float v0 = acc[mt][nt][half * 2 + 0];
                    float v1 = acc[mt][nt][half * 2 + 1];
                    if (EPI == 1) {
                        float2 ad = *(const float2*)(addp + (size_t)r * ldc + col);
                        v0 += ad.x; v1 += ad.y;
                    } else if (EPI == 2) {
                        v0 = rtf(v0); v1 = rtf(v1);
                    }
                    float2 o; o.x = v0; o.y = v1;
                    *(float2*)(C + (size_t)r * ldc + col) = o;
                }
            }
        }
    }
}

// ---------------- grouped MoE GEMMs (tf32 MMA, cp.async) ----------------
// EP 1: round(gelu(acc+b1)) -> g_act  (A = g_htf gathered, already tf32)
// EP 2: acc+b2 -> g_y (exact)         (A = g_act, already tf32)
// B (raw fp32 weights) is RNA-rounded in-register at fragment load.
template <int EP>
__global__ void __launch_bounds__(128, 2)
moe_mgemm(const float* __restrict__ H,
          const float* __restrict__ W,
          const float* __restrict__ Bias,
          int Kdim, int Ndim) {
    constexpr int STG = ASZ + BSZ_N;
    extern __shared__ float sm[];

    int e = blockIdx.z;
    int base = g_offs[e], cnt = g_offs[e + 1] - base;
    int m0 = blockIdx.y * BM;
    if (m0 >= cnt) return;
    int n0 = blockIdx.x * BN;
    const float* Bmat = W + (size_t)e * Kdim * Ndim;

    int tid = threadIdx.x;
    int wid = tid >> 5, lane = tid & 31;
    int warpM = wid & 1, warpN = wid >> 1;
    int g = lane >> 2, t = lane & 3;

    unsigned smb;
    {
        unsigned long long p = __cvta_generic_to_shared(sm);
        smb = (unsigned)p;
    }

    bool av = (m0 + tid) < cnt;
    const float* aptr;
    if (EP == 1) aptr = H + (size_t)(av ? g_perm[base + m0 + tid] : 0) * Kdim;
    else         aptr = g_act + (size_t)(av ? (base + m0 + tid) : 0) * Kdim;

    float acc[4][8][4];
#pragma unroll
    for (int mt = 0; mt < 4; mt++)
#pragma unroll
        for (int nt = 0; nt < 8; nt++)
#pragma unroll
            for (int r = 0; r < 4; r++) acc[mt][nt][r] = 0.f;

    int KT = Kdim / BK;

    auto issue = [&](int s, int kt) {
        int k0 = kt * BK;
        unsigned abase = smb + (unsigned)(s * STG) * 4u;
        unsigned bbase = abase + ASZ * 4u;
#pragma unroll
        for (int c = 0; c < 8; c++)
            cpa16(abase + (unsigned)(tid * AST + c * 4) * 4u, aptr + k0 + c * 4, av);
#pragma unroll
        for (int c = 0; c < 8; c++) {
            int idx = c * 128 + tid;
            int r = idx >> 5, c4 = (idx & 31) * 4;
            cpa16(bbase + (unsigned)(r * BST + c4) * 4u,
                  Bmat + (size_t)(k0 + r) * Ndim + n0 + c4, true);
        }
        cp_commit();
    };

    issue(0, 0);
    for (int kt = 0; kt < KT; kt++) {
        int b = kt & 1;
        if (kt + 1 < KT) {
            issue(b ^ 1, kt + 1);
            asm volatile("cp.async.wait_group 1;\n");
        } else {
            asm volatile("cp.async.wait_group 0;\n");
        }
        __syncthreads();

        const float* As_ = sm + b * STG;
        const float* Bs_ = As_ + ASZ;
#pragma unroll
        for (int ks = 0; ks < 4; ks++) {
            int kk = ks * 8;
            unsigned afr[4][4];
#pragma unroll
            for (int mt = 0; mt < 4; mt++) {
                int am = warpM * 64 + mt * 16;
                afr[mt][0] = __float_as_uint(As_[(am + g) * AST + kk + t]);
                afr[mt][1] = __float_as_uint(As_[(am + g + 8) * AST + kk + t]);
                afr[mt][2] = __float_as_uint(As_[(am + g) * AST + kk + t + 4]);
                afr[mt][3] = __float_as_uint(As_[(am + g + 8) * AST + kk + t + 4]);
            }
            unsigned bfr[8][2];
#pragma unroll
            for (int nt = 0; nt < 8; nt++) {
                int bn = warpN * 64 + nt * 8;
                bfr[nt][0] = f2tf(Bs_[(kk + t) * BST + bn + g]);
                bfr[nt][1] = f2tf(Bs_[(kk + t + 4) * BST + bn + g]);
            }
#pragma unroll
            for (int mt = 0; mt < 4; mt++)
#pragma unroll
                for (int nt = 0; nt < 8; nt++)
                    mma_tf32(acc[mt][nt], afr[mt], bfr[nt]);
        }
        __syncthreads();
    }

    // epilogue
#pragma unroll
    for (int mt = 0; mt < 4; mt++) {
#pragma unroll
        for (int nt = 0; nt < 8; nt++) {
            int rr = m0 + warpM * 64 + mt * 16 + g;
            int col = n0 + warpN * 64 + nt * 8 + 2 * t;
#pragma unroll
            for (int half = 0; half < 2; half++) {
                int r = rr + half * 8;
                if (r < cnt) {
                    float b0 = Bias[(size_t)e * Ndim + col];
                    float b1v = Bias[(size_t)e * Ndim + col + 1];
                    float v0 = acc[mt][nt][half * 2 + 0] + b0;
                    float v1 = acc[mt][nt][half * 2 + 1] + b1v;
                    float2 o;
                    if (EP == 1) {
                        o.x = rtf(gelu_tanh(v0)); o.y = rtf(gelu_tanh(v1));
                        *(float2*)(g_act + (size_t)(base + r) * FF_ + col) = o;
                    } else {
                        o.x = v0; o.y = v1;
                        *(float2*)(g_y + (size_t)(base + r) * D_ + col) = o;
                    }
                }
            }
        }
    }
}

// ---------------- launch ----------------
#define SMEM_N ((ASZ + BSZ_N) * 2 * 4)
#define SMEM_T ((ASZ + BSZ_T) * 2 * 4)

extern "C" void kernel_launch(void* const* d_in, const int* in_sizes, int n_in,
                              void* d_out, int out_size) {
    const float* x   = (const float*)d_in[0];
    const float* anw = (const float*)d_in[1];
    const float* wq  = (const float*)d_in[2];
    const float* wk  = (const float*)d_in[3];
    const float* wv  = (const float*)d_in[4];
    const float* wo  = (const float*)d_in[5];
    const float* mnw = (const float*)d_in[6];
    const float* rw  = (const float*)d_in[7];
    const float* w1  = (const float*)d_in[8];
    const float* b1  = (const float*)d_in[9];
    const float* w2  = (const float*)d_in[10];
    const float* b2  = (const float*)d_in[11];
    float* out = (float*)d_out;

    cudaFuncSetAttribute(mgemm<false, 0>, cudaFuncAttributeMaxDynamicSharedMemorySize, SMEM_N);
    cudaFuncSetAttribute(mgemm<false, 1>, cudaFuncAttributeMaxDynamicSharedMemorySize, SMEM_N);
    cudaFuncSetAttribute(mgemm<false, 2>, cudaFuncAttributeMaxDynamicSharedMemorySize, SMEM_N);
    cudaFuncSetAttribute(mgemm<true, 0>,  cudaFuncAttributeMaxDynamicSharedMemorySize, SMEM_T);
    cudaFuncSetAttribute(moe_mgemm<1>,    cudaFuncAttributeMaxDynamicSharedMemorySize, SMEM_N);
    cudaFuncSetAttribute(moe_mgemm<2>,    cudaFuncAttributeMaxDynamicSharedMemorySize, SMEM_N);

    float *xn, *wqkv, *woc, *qkv, *sc, *ao, *x2, *h, *htf;
    cudaGetSymbolAddress((void**)&xn,   g_xn);
    cudaGetSymbolAddress((void**)&wqkv, g_wqkv);
    cudaGetSymbolAddress((void**)&woc,  g_woc);
    cudaGetSymbolAddress((void**)&qkv,  g_qkv);
    cudaGetSymbolAddress((void**)&sc,   g_scores);
    cudaGetSymbolAddress((void**)&ao,   g_attnout);
    cudaGetSymbolAddress((void**)&x2,   g_x2);
    cudaGetSymbolAddress((void**)&h,    g_h);
    cudaGetSymbolAddress((void**)&htf,  g_htf);

    const float* q = qkv;
    const float* k = qkv + (size_t)NTOK * D_;
    const float* v = qkv + 2 * (size_t)NTOK * D_;

    init_kernel<<<1, 32>>>();
    pack_w_kernel<<<(D_ * D_ / 4 + 255) / 256, 256>>>(wq, wk, wv, wo);
    // xn: rounded only (feeds QKV gemm)
    rmsnorm_kernel<<<NTOK, 256>>>(x, anw, nullptr, xn);

    // fused QKV (z=3), outputs rounded (feed QK^T / PV gemms)
    {
        dim3 g(8, 16, 3);
        mgemm<false, 2><<<g, 128, SMEM_N>>>(xn, D_, wqkv, D_, qkv, D_, NTOK, D_, D_,
                                            0, 0, (long long)D_ * D_, 0,
                                            (long long)NTOK * D_, 0, 1, nullptr, 0);
    }

    // scores = Q @ K^T per (b,h), causal tile skip (output exact; softmax rounds)
    {
        dim3 g(8, 8, BB_ * NH_);
        long long sSD = (long long)S_ * D_;
        long long sSS = (long long)S_ * S_;
        mgemm<true, 0><<<g, 128, SMEM_T>>>(q, D_, k, D_, sc, S_, S_, S_, DH_,
                                           sSD, DH_, sSD, DH_, NH_ * sSS, sSS, NH_,
                                           nullptr, 1);
    }

    softmax_kernel<<<BB_ * NH_ * S_, 128>>>(sc);

    // attnout = P @ V per (b,h), k-clipped, output rounded (feeds WO gemm)
    {
        dim3 g(1, 8, BB_ * NH_);
        long long sSD = (long long)S_ * D_;
        long long sSS = (long long)S_ * S_;
        mgemm<false, 2><<<g, 128, SMEM_N>>>(sc, S_, v, D_, ao, D_, S_, DH_, S_,
                                            NH_ * sSS, sSS, sSD, DH_, sSD, DH_, NH_,
                                            nullptr, 2);
    }

    // x2 = x + attnout @ wo  (exact residual)
    {
        dim3 g(8, 16, 1);
        mgemm<false, 1><<<g, 128, SMEM_N>>>(ao, D_, woc, D_, x2, D_, NTOK, D_, D_,
                                            0, 0, 0, 0, 0, 0, 1, x, 0);
    }

    // h exact (router) + htf rounded (MoE gemm1 A-side)
    rmsnorm_kernel<<<NTOK, 256>>>(x2, mnw, h, htf);
    router_kernel<<<NTOK, 256>>>(h, rw);
    scan_kernel<<<1, 1>>>();
    place_kernel<<<(NTOK + 255) / 256, 256>>>();

    moe_mgemm<1><<<dim3(FF_ / 128, NSLOT / 128, E_), 128, SMEM_N>>>(htf, w1, b1, D_, FF_);
    moe_mgemm<2><<<dim3(D_ / 128, NSLOT / 128, E_), 128, SMEM_N>>>(nullptr, w2, b2, FF_, D_);

    combine_kernel<<<(NTOK * D_ + 255) / 256, 256>>>(out);
    finalize_kernel<<<1, 32>>>(out);
}

// round 7
// speedup vs baseline: 1.3514x; 1.3508x over previous
#include <cuda_runtime.h>
#include <cuda_fp16.h>
#include <math.h>
#include <stdint.h>

#define D_    1024
#define S_    1024
#define BB_   2
#define NTOK  2048
#define NH_   16
#define DH_   64
#define E_    8
#define KSEL  2
#define FF_   4096
#define NSLOT 4096

#define BKH   64          // K halfs per stage (128B)
#define ASTH  72          // A smem row stride (halfs): 16B-unit step 9 -> conflict-free
#define ASZB  (128*ASTH*2)  // 18432 B

// ---------------- static scratch ----------------
__device__ __half g_xn[NTOK * D_];
__device__ __half g_wqkvh[3 * D_ * D_];
__device__ __half g_woh[D_ * D_];
__device__ __half g_w1h[(size_t)E_ * D_ * FF_];
__device__ __half g_w2h[(size_t)E_ * FF_ * D_];
__device__ __half g_qkv[3 * NTOK * D_];
__device__ float  g_scoresF[(size_t)BB_ * NH_ * S_ * S_];
__device__ __half g_probsH[(size_t)BB_ * NH_ * S_ * S_];
__device__ __half g_attnout[NTOK * D_];
__device__ float  g_x2[NTOK * D_];
__device__ float  g_h[NTOK * D_];
__device__ __half g_htf[NTOK * D_];
__device__ __half g_act[(size_t)NSLOT * FF_];
__device__ float  g_y[(size_t)NSLOT * D_];
__device__ float g_topval[NTOK * KSEL];
__device__ int   g_topidx[NTOK * KSEL];
__device__ int   g_slotof[NTOK * KSEL];
__device__ int   g_perm[NSLOT];
__device__ int   g_counts[E_];
__device__ int   g_offs[E_ + 1];
__device__ int   g_cursor[E_];
__device__ float g_probsum[E_];

// ---------------- helpers ----------------
__device__ __forceinline__ float gelu_tanh(float v) {
    float v3 = v * v * v;
    return 0.5f * v * (1.f + tanhf(0.7978845608028654f * (v + 0.044715f * v3)));
}
__device__ __forceinline__ void cpa16(unsigned dst, const void* src, bool p) {
    int sz = p ? 16 : 0;
    asm volatile("cp.async.cg.shared.global [%0], [%1], 16, %2;\n"
                 :: "r"(dst), "l"(src), "r"(sz));
}
__device__ __forceinline__ void cp_commit() { asm volatile("cp.async.commit_group;\n"); }
__device__ __forceinline__ void ldsm4(unsigned& r0, unsigned& r1, unsigned& r2, unsigned& r3,
                                      unsigned addr) {
    asm volatile("ldmatrix.sync.aligned.m8n8.x4.shared.b16 {%0,%1,%2,%3}, [%4];"
                 : "=r"(r0), "=r"(r1), "=r"(r2), "=r"(r3) : "r"(addr));
}
__device__ __forceinline__ void ldsm4t(unsigned& r0, unsigned& r1, unsigned& r2, unsigned& r3,
                                       unsigned addr) {
    asm volatile("ldmatrix.sync.aligned.m8n8.x4.trans.shared.b16 {%0,%1,%2,%3}, [%4];"
                 : "=r"(r0), "=r"(r1), "=r"(r2), "=r"(r3) : "r"(addr));
}
__device__ __forceinline__ void mma16816(float* d, const unsigned* a, const unsigned* b) {
    asm volatile(
        "mma.sync.aligned.m16n8k16.row.col.f32.f16.f16.f32 "
        "{%0,%1,%2,%3}, {%4,%5,%6,%7}, {%8,%9}, {%0,%1,%2,%3};"
        : "+f"(d[0]), "+f"(d[1]), "+f"(d[2]), "+f"(d[3])
        : "r"(a[0]), "r"(a[1]), "r"(a[2]), "r"(a[3]), "r"(b[0]), "r"(b[1]));
}

// ---------------- utility kernels ----------------
__global__ void init_kernel() {
    int i = threadIdx.x;
    if (i < E_) { g_counts[i] = 0; g_cursor[i] = 0; g_probsum[i] = 0.f; }
}

__global__ void f2h_kernel(const float* __restrict__ in, __half* __restrict__ out,
                           long long n2) {
    for (long long i = blockIdx.x * 256LL + threadIdx.x; i < n2; i += (long long)gridDim.x * 256) {
        float2 v = ((const float2*)in)[i];
        ((__half2*)out)[i] = __floats2half2_rn(v.x, v.y);
    }
}

__global__ void rmsnorm_kernel(const float* __restrict__ X, const float* __restrict__ W,
                               float* __restrict__ O, __half* __restrict__ OT) {
    int t = blockIdx.x;
    const float* x = X + (size_t)t * D_;
    float ss = 0.f;
    for (int d = threadIdx.x; d < D_; d += 256) { float v = x[d]; ss += v * v; }
    __shared__ float red[256];
    red[threadIdx.x] = ss; __syncthreads();
    for (int s = 128; s > 0; s >>= 1) {
        if (threadIdx.x < s) red[threadIdx.x] += red[threadIdx.x + s];
        __syncthreads();
    }
    float scale = rsqrtf(red[0] * (1.f / D_) + 1e-6f);
    for (int d = threadIdx.x; d < D_; d += 256) {
        float v = x[d] * scale * W[d];
        if (O)  O[(size_t)t * D_ + d] = v;
        OT[(size_t)t * D_ + d] = __float2half_rn(v);
    }
}

// read float scores, write half probs (causal row softmax, scale 0.125)
__global__ void softmax_kernel(const float* __restrict__ SC, __half* __restrict__ P) {
    int row = blockIdx.x;
    int bh = row >> 10, q = row & 1023;
    const float* s = SC + (size_t)bh * S_ * S_ + (size_t)q * S_;
    __half* p = P + (size_t)bh * S_ * S_ + (size_t)q * S_;
    int len = q + 1;
    int tid = threadIdx.x;
    __shared__ float red[128];
    float mx = -1e30f;
    for (int j = tid; j < len; j += 128) mx = fmaxf(mx, s[j]);
    red[tid] = mx; __syncthreads();
    for (int st = 64; st > 0; st >>= 1) {
        if (tid < st) red[tid] = fmaxf(red[tid], red[tid + st]);
        __syncthreads();
    }
    mx = red[0] * 0.125f; __syncthreads();
    float sum = 0.f;
    for (int j = tid; j < len; j += 128) sum += expf(s[j] * 0.125f - mx);
    red[tid] = sum; __syncthreads();
    for (int st = 64; st > 0; st >>= 1) {
        if (tid < st) red[tid] += red[tid + st];
        __syncthreads();
    }
    float inv = 1.f / red[0];
    for (int j = tid; j < len; j += 128)
        p[j] = __float2half_rn(expf(s[j] * 0.125f - mx) * inv);
    for (int j = len + tid; j < S_; j += 128) p[j] = __float2half_rn(0.f);
}

__global__ void router_kernel(const float* __restrict__ H, const float* __restrict__ RW) {
    int t = blockIdx.x;
    int tid = threadIdx.x;
    int e = tid >> 5, lane = tid & 31;
    const float* h = H + (size_t)t * D_;
    float p = 0.f;
    for (int d = lane; d < D_; d += 32) p += h[d] * RW[d * E_ + e];
    for (int o = 16; o > 0; o >>= 1) p += __shfl_down_sync(0xffffffff, p, o);
    __shared__ float lg[E_];
    if (lane == 0) lg[e] = p;
    __syncthreads();
    if (tid == 0) {
        float mx = lg[0];
        for (int i = 1; i < E_; i++) mx = fmaxf(mx, lg[i]);
        float pr[E_]; float s = 0.f;
        for (int i = 0; i < E_; i++) { pr[i] = expf(lg[i] - mx); s += pr[i]; }
        float inv = 1.f / s;
        float b1v = -1.f, b2v = -1.f; int b1i = 0, b2i = 0;
        for (int i = 0; i < E_; i++) {
            float v = pr[i] * inv;
            atomicAdd(&g_probsum[i], v);
            if (v > b1v) { b2v = b1v; b2i = b1i; b1v = v; b1i = i; }
            else if (v > b2v) { b2v = v; b2i = i; }
        }
        g_topidx[t * 2] = b1i; g_topidx[t * 2 + 1] = b2i;
        g_topval[t * 2] = b1v; g_topval[t * 2 + 1] = b2v;
        atomicAdd(&g_counts[b1i], 1);
        atomicAdd(&g_counts[b2i], 1);
    }
}

__global__ void scan_kernel() {
    if (threadIdx.x == 0) {
        g_offs[0] = 0;
        for (int e = 0; e < E_; e++) {
            g_offs[e + 1] = g_offs[e] + g_counts[e];
            g_cursor[e] = g_offs[e];
        }
    }
}

__global__ void place_kernel() {
    int t = blockIdx.x * blockDim.x + threadIdx.x;
    if (t >= NTOK) return;
    for (int kk = 0; kk < KSEL; kk++) {
        int e = g_topidx[t * 2 + kk];
        int slot = atomicAdd(&g_cursor[e], 1);
        g_perm[slot] = t;
        g_slotof[t * 2 + kk] = slot;
    }
}

__global__ void combine_kernel(float* __restrict__ out) {
    int idx = blockIdx.x * blockDim.x + threadIdx.x;
    if (idx >= NTOK * D_) return;
    int t = idx >> 10, d = idx & 1023;
    float v = g_x2[idx];
    v += g_topval[t * 2]     * g_y[(size_t)g_slotof[t * 2]     * D_ + d];
    v += g_topval[t * 2 + 1] * g_y[(size_t)g_slotof[t * 2 + 1] * D_ + d];
    out[idx] = v;
}

__global__ void finalize_kernel(float* __restrict__ out) {
    if (threadIdx.x == 0) {
        float loss = 0.f;
        for (int e = 0; e < E_; e++)
            loss += ((float)g_counts[e] / (float)NSLOT) * (g_probsum[e] / (float)NTOK);
        loss *= (float)E_;
        out[(size_t)NTOK * D_] = loss;
        for (int e = 0; e < E_; e++)
            out[(size_t)NTOK * D_ + 1 + e] = (float)g_counts[e];
    }
}

// ---------------- fp16 HMMA GEMM: 128xNT x64-stage, 4 warps, ldmatrix ----
// A [M,K] K-major half. B: TB ? [N,K] K-major : [K,N] N-major, half.
// EPI: 0 half store; 1 float store + float residual; 2 float store.
// mode: 0 none, 1 causal tile-skip, 2 k-clip.
template <bool TB, int NT, int EPI>
__global__ void __launch_bounds__(128, 2)
hgemm(const __half* __restrict__ A, int lda,
      const __half* __restrict__ B, int ldb,
      void* __restrict__ Cv, int ldc,
      int M, int N, int K,
      long long aO, long long aI, long long bO, long long bI,
      long long cO, long long cI, int zdiv,
      const float* __restrict__ addp, int mode) {
    constexpr int BSTH = NT + 8;                      // n-major B row stride (halfs)
    constexpr int BSZB = TB ? ASZB : (64 * BSTH * 2); // B stage bytes
    constexpr int STG  = ASZB + BSZB;
    constexpr int NTW  = NT / 16;                     // nt per warp
    extern __shared__ __align__(16) unsigned char smraw[];

    int z = blockIdx.z, zo = z / zdiv, zi = z % zdiv;
    A += zo * aO + zi * aI;
    B += zo * bO + zi * bI;

    int m0 = blockIdx.y * 128, n0 = blockIdx.x * NT;
    if (mode == 1 && n0 > m0 + 127) return;
    int Keff = (mode == 2) ? min(K, m0 + 128) : K;
    int KT = Keff / BKH;

    int tid = threadIdx.x, wid = tid >> 5, lane = tid & 31;
    int warpM = wid & 1, warpN = wid >> 1;
    int g = lane >> 2, t = lane & 3;
    unsigned smb = (unsigned)__cvta_generic_to_shared(smraw);

    bool av = (m0 + tid) < M;
    const __half* aptr = A + (size_t)(av ? (m0 + tid) : 0) * lda;
    const __half* bptr = nullptr;
    bool bv = true;
    if (TB) {
        bv = (n0 + tid) < N;
        bptr = B + (size_t)(bv ? (n0 + tid) : 0) * ldb;
    }

    float acc[4][NTW][4];
#pragma unroll
    for (int mt = 0; mt < 4; mt++)
#pragma unroll
        for (int nt = 0; nt < NTW; nt++)
#pragma unroll
            for (int r = 0; r < 4; r++) acc[mt][nt][r] = 0.f;

    auto issue = [&](int lt) {
        int s = lt & 1;
        unsigned ab = smb + (unsigned)s * STG;
        const __half* as = aptr + lt * BKH;
        unsigned arow = ab + (unsigned)tid * (ASTH * 2);
#pragma unroll
        for (int c = 0; c < 8; c++)
            cpa16(arow + c * 16, as + c * 8, av);
        unsigned bb = ab + ASZB;
        if (TB) {
            const __half* bs = bptr + lt * BKH;
            unsigned br = bb + (unsigned)tid * (ASTH * 2);
#pragma unroll
            for (int c = 0; c < 8; c++)
                cpa16(br + c * 16, bs + c * 8, bv);
        } else {
            int row = tid >> 1;                        // 0..63 (k)
            int cb = (tid & 1) * (NT / 16);
            const __half* bs = B + (size_t)(lt * BKH + row) * ldb + n0;
            unsigned br = bb + (unsigned)row * (BSTH * 2);
#pragma unroll
            for (int j = 0; j < NT / 16; j++)
                cpa16(br + (cb + j) * 16, bs + (cb + j) * 8, true);
        }
        cp_commit();
    };

    issue(0);
    for (int kt = 0; kt < KT; kt++) {
        int b = kt & 1;
        if (kt + 1 < KT) {
            issue(kt + 1);
            asm volatile("cp.async.wait_group 1;\n");
        } else {
            asm volatile("cp.async.wait_group 0;\n");
        }
        __syncthreads();

        unsigned aBase = smb + (unsigned)b * STG;
        unsigned bBase = aBase + ASZB;
#pragma unroll
        for (int ks = 0; ks < 4; ks++) {
            unsigned afr[4][4];
#pragma unroll
            for (int mt = 0; mt < 4; mt++) {
                int row = warpM * 64 + mt * 16 + (lane & 15);
                int kh = ks * 16 + ((lane >> 4) << 3);
                ldsm4(afr[mt][0], afr[mt][1], afr[mt][2], afr[mt][3],
                      aBase + (unsigned)(row * ASTH + kh) * 2);
            }
            unsigned bfr[NTW][2];
#pragma unroll
            for (int ntp = 0; ntp < NTW / 2; ntp++) {
                unsigned r0, r1, r2, r3;
                if (TB) {
                    int row = warpN * 64 + ntp * 16 + (lane & 15);
                    int kh = ks * 16 + ((lane >> 4) << 3);
                    ldsm4(r0, r1, r2, r3, bBase + (unsigned)(row * ASTH + kh) * 2);
                    bfr[2 * ntp][0] = r0; bfr[2 * ntp + 1][0] = r1;
                    bfr[2 * ntp][1] = r2; bfr[2 * ntp + 1][1] = r3;
                } else {
                    int krow = ks * 16 + (lane & 15);
                    int col = warpN * (NT / 2) + ntp * 16 + ((lane >> 4) << 3);
                    ldsm4t(r0, r1, r2, r3, bBase + (unsigned)(krow * BSTH + col) * 2);
                    bfr[2 * ntp][0] = r0; bfr[2 * ntp][1] = r1;
                    bfr[2 * ntp + 1][0] = r2; bfr[2 * ntp + 1][1] = r3;
                }
            }
#pragma unroll
            for (int mt = 0; mt < 4; mt++)
#pragma unroll
                for (int nt = 0; nt < NTW; nt++)
                    mma16816(acc[mt][nt], afr[mt], bfr[nt]);
        }
        __syncthreads();
    }

    // epilogue
#pragma unroll
    for (int mt = 0; mt < 4; mt++) {
#pragma unroll
        for (int nt = 0; nt < NTW; nt++) {
            int row = m0 + warpM * 64 + mt * 16 + g;
            int col = n0 + warpN * (NT / 2) + nt * 8 + 2 * t;
#pragma unroll
            for (int half_ = 0; half_ < 2; half_++) {
                int r = row + half_ * 8;
                if (r < M && col < N) {
                    float v0 = acc[mt][nt][half_ * 2 + 0];
                    float v1 = acc[mt][nt][half_ * 2 + 1];
                    size_t cidx = (size_t)(zo * cO + zi * cI) + (size_t)r * ldc + col;
                    if (EPI == 0) {
                        *(__half2*)((__half*)Cv + cidx) = __floats2half2_rn(v0, v1);
                    } else if (EPI == 1) {
                        float2 ad = *(const float2*)(addp + (size_t)r * ldc + col);
                        float2 o; o.x = v0 + ad.x; o.y = v1 + ad.y;
                        *(float2*)((float*)Cv + cidx) = o;
                    } else {
                        float2 o; o.x = v0; o.y = v1;
                        *(float2*)((float*)Cv + cidx) = o;
                    }
                }
            }
        }
    }
}

// ---------------- grouped MoE fp16 GEMMs ----------------
// EP 1: half(gelu(acc+bias)) -> g_act  (A = g_htf gathered, B = g_w1h[e] [K,N])
// EP 2: acc+bias (float) -> g_y        (A = g_act,          B = g_w2h[e] [K,N])
template <int EP>
__global__ void __launch_bounds__(128, 2)
moe_hgemm(const __half* __restrict__ H, const __half* __restrict__ W,
          const float* __restrict__ Bias, int Kdim, int Ndim) {
    constexpr int BSTH = 136;
    constexpr int BSZB = 64 * BSTH * 2;
    constexpr int STG  = ASZB + BSZB;
    extern __shared__ __align__(16) unsigned char smraw[];

    int e = blockIdx.z;
    int base = g_offs[e], cnt = g_offs[e + 1] - base;
    int m0 = blockIdx.y * 128;
    if (m0 >= cnt) return;
    int n0 = blockIdx.x * 128;
    const __half* Bmat = W + (size_t)e * (size_t)Kdim * Ndim;

    int tid = threadIdx.x, wid = tid >> 5, lane = tid & 31;
    int warpM = wid & 1, warpN = wid >> 1;
    int g = lane >> 2, t = lane & 3;
    unsigned smb = (unsigned)__cvta_generic_to_shared(smraw);
    float* sBias = (float*)smraw;          // 512 B
    unsigned tb0 = smb + 512;

    sBias[tid] = Bias[(size_t)e * Ndim + n0 + tid];

    bool av = (m0 + tid) < cnt;
    const __half* aptr;
    if (EP == 1) aptr = H + (size_t)(av ? g_perm[base + m0 + tid] : 0) * Kdim;
    else         aptr = g_act + (size_t)(av ? (base + m0 + tid) : 0) * Kdim;

    float acc[4][8][4];
#pragma unroll
    for (int mt = 0; mt < 4; mt++)
#pragma unroll
        for (int nt = 0; nt < 8; nt++)
#pragma unroll
            for (int r = 0; r < 4; r++) acc[mt][nt][r] = 0.f;

    int KT = Kdim / BKH;

    auto issue = [&](int lt) {
        int s = lt & 1;
        unsigned ab = tb0 + (unsigned)s * STG;
        const __half* as = aptr + lt * BKH;
        unsigned arow = ab + (unsigned)tid * (ASTH * 2);
#pragma unroll
        for (int c = 0; c < 8; c++)
            cpa16(arow + c * 16, as + c * 8, av);
        unsigned bb = ab + ASZB;
        int row = tid >> 1;
        int cb = (tid & 1) * 8;
        const __half* bs = Bmat + (size_t)(lt * BKH + row) * Ndim + n0;
        unsigned br = bb + (unsigned)row * (BSTH * 2);
#pragma unroll
        for (int j = 0; j < 8; j++)
            cpa16(br + (cb + j) * 16, bs + (cb + j) * 8, true);
        cp_commit();
    };

    issue(0);
    for (int kt = 0; kt < KT; kt++) {
        int b = kt & 1;
        if (kt + 1 < KT) {
            issue(kt + 1);
            asm volatile("cp.async.wait_group 1;\n");
        } else {
            asm volatile("cp.async.wait_group 0;\n");
        }
        __syncthreads();

        unsigned aBase = tb0 + (unsigned)b * STG;
        unsigned bBase = aBase + ASZB;
#pragma unroll
        for (int ks = 0; ks < 4; ks++) {
            unsigned afr[4][4];
#pragma unroll
            for (int mt = 0; mt < 4; mt++) {
                int row = warpM * 64 + mt * 16 + (lane & 15);
                int kh = ks * 16 + ((lane >> 4) << 3);
                ldsm4(afr[mt][0], afr[mt][1], afr[mt][2], afr[mt][3],
                      aBase + (unsigned)(row * ASTH + kh) * 2);
            }
            unsigned bfr[8][2];
#pragma unroll
            for (int ntp = 0; ntp < 4; ntp++) {
                unsigned r0, r1, r2, r3;
                int krow = ks * 16 + (lane & 15);
                int col = warpN * 64 + ntp * 16 + ((lane >> 4) << 3);
                ldsm4t(r0, r1, r2, r3, bBase + (unsigned)(krow * BSTH + col) * 2);
                bfr[2 * ntp][0] = r0; bfr[2 * ntp][1] = r1;
                bfr[2 * ntp + 1][0] = r2; bfr[2 * ntp + 1][1] = r3;
            }
#pragma unroll
            for (int mt = 0; mt < 4; mt++)
#pragma unroll
                for (int nt = 0; nt < 8; nt++)
                    mma16816(acc[mt][nt], afr[mt], bfr[nt]);
        }
        __syncthreads();
    }

#pragma unroll
    for (int mt = 0; mt < 4; mt++) {
#pragma unroll
        for (int nt = 0; nt < 8; nt++) {
            int rr = m0 + warpM * 64 + mt * 16 + g;
            int colL = warpN * 64 + nt * 8 + 2 * t;
            int col = n0 + colL;
#pragma unroll
            for (int half_ = 0; half_ < 2; half_++) {
                int r = rr + half_ * 8;
                if (r < cnt) {
                    float v0 = acc[mt][nt][half_ * 2 + 0] + sBias[colL];
                    float v1 = acc[mt][nt][half_ * 2 + 1] + sBias[colL + 1];
                    if (EP == 1) {
                        *(__half2*)(g_act + (size_t)(base + r) * FF_ + col) =
                            __floats2half2_rn(gelu_tanh(v0), gelu_tanh(v1));
                    } else {
                        float2 o; o.x = v0; o.y = v1;
                        *(float2*)(g_y + (size_t)(base + r) * D_ + col) = o;
                    }
                }
            }
        }
    }
}

// ---------------- launch ----------------
#define SMEM_NF128 (2 * (ASZB + 64 * 136 * 2))        // 71680  (TB=false, NT=128)
#define SMEM_T128  (2 * (ASZB + ASZB))                // 73728  (TB=true,  NT=128)
#define SMEM_NF64  (2 * (ASZB + 64 * 72 * 2))         // 55296  (TB=false, NT=64)
#define SMEM_MOE   (512 + 2 * (ASZB + 64 * 136 * 2))  // 72192

extern "C" void kernel_launch(void* const* d_in, const int* in_sizes, int n_in,
                              void* d_out, int out_size) {
    const float* x   = (const float*)d_in[0];
    const float* anw = (const float*)d_in[1];
    const float* wq  = (const float*)d_in[2];
    const float* wk  = (const float*)d_in[3];
    const float* wv  = (const float*)d_in[4];
    const float* wo  = (const float*)d_in[5];
    const float* mnw = (const float*)d_in[6];
    const float* rw  = (const float*)d_in[7];
    const float* w1  = (const float*)d_in[8];
    const float* b1  = (const float*)d_in[9];
    const float* w2  = (const float*)d_in[10];
    const float* b2  = (const float*)d_in[11];
    float* out = (float*)d_out;

    cudaFuncSetAttribute(hgemm<false, 128, 0>, cudaFuncAttributeMaxDynamicSharedMemorySize, SMEM_NF128);
    cudaFuncSetAttribute(hgemm<false, 128, 1>, cudaFuncAttributeMaxDynamicSharedMemorySize, SMEM_NF128);
    cudaFuncSetAttribute(hgemm<true, 128, 2>,  cudaFuncAttributeMaxDynamicSharedMemorySize, SMEM_T128);
    cudaFuncSetAttribute(hgemm<false, 64, 0>,  cudaFuncAttributeMaxDynamicSharedMemorySize, SMEM_NF64);
    cudaFuncSetAttribute(moe_hgemm<1>,         cudaFuncAttributeMaxDynamicSharedMemorySize, SMEM_MOE);
    cudaFuncSetAttribute(moe_hgemm<2>,         cudaFuncAttributeMaxDynamicSharedMemorySize, SMEM_MOE);

    __half *xn, *wqkvh, *woh, *w1h, *w2h, *qkv, *probsH, *ao, *htf;
    float *scF, *x2, *h;
    cudaGetSymbolAddress((void**)&xn,     g_xn);
    cudaGetSymbolAddress((void**)&wqkvh,  g_wqkvh);
    cudaGetSymbolAddress((void**)&woh,    g_woh);
    cudaGetSymbolAddress((void**)&w1h,    g_w1h);
    cudaGetSymbolAddress((void**)&w2h,    g_w2h);
    cudaGetSymbolAddress((void**)&qkv,    g_qkv);
    cudaGetSymbolAddress((void**)&scF,    g_scoresF);
    cudaGetSymbolAddress((void**)&probsH, g_probsH);
    cudaGetSymbolAddress((void**)&ao,     g_attnout);
    cudaGetSymbolAddress((void**)&x2,     g_x2);
    cudaGetSymbolAddress((void**)&h,      g_h);
    cudaGetSymbolAddress((void**)&htf,    g_htf);

    const __half* q = qkv;
    const __half* k = qkv + (size_t)NTOK * D_;
    const __half* v = qkv + 2 * (size_t)NTOK * D_;

    init_kernel<<<1, 32>>>();
    // fp32 -> fp16 weight conversion (layout preserved; [K,N] n-major)
    f2h_kernel<<<2048, 256>>>(wq, wqkvh, (long long)D_ * D_ / 2);
    f2h_kernel<<<2048, 256>>>(wk, wqkvh + (size_t)D_ * D_, (long long)D_ * D_ / 2);
    f2h_kernel<<<2048, 256>>>(wv, wqkvh + 2 * (size_t)D_ * D_, (long long)D_ * D_ / 2);
    f2h_kernel<<<2048, 256>>>(wo, woh, (long long)D_ * D_ / 2);
    f2h_kernel<<<4096, 256>>>(w1, w1h, (long long)E_ * D_ * FF_ / 2);
    f2h_kernel<<<4096, 256>>>(w2, w2h, (long long)E_ * FF_ * D_ / 2);

    rmsnorm_kernel<<<NTOK, 256>>>(x, anw, nullptr, xn);

    // fused QKV (z=3): half out
    hgemm<false, 128, 0><<<dim3(8, 16, 3), 128, SMEM_NF128>>>(
        xn, D_, wqkvh, D_, qkv, D_, NTOK, D_, D_,
        0, 0, (long long)D_ * D_, 0, (long long)NTOK * D_, 0, 1, nullptr, 0);

    // scores = Q @ K^T per (b,h): float out (exact logits), causal tile skip
    {
        long long sSD = (long long)S_ * D_, sSS = (long long)S_ * S_;
        hgemm<true, 128, 2><<<dim3(8, 8, BB_ * NH_), 128, SMEM_T128>>>(
            q, D_, k, D_, scF, S_, S_, S_, DH_,
            sSD, DH_, sSD, DH_, NH_ * sSS, sSS, NH_, nullptr, 1);
    }

    softmax_kernel<<<BB_ * NH_ * S_, 128>>>(scF, probsH);

    // attnout = P @ V per (b,h): B = v [K=S, N=64 slice] n-major, k-clip, half out
    {
        long long sSD = (long long)S_ * D_, sSS = (long long)S_ * S_;
        hgemm<false, 64, 0><<<dim3(1, 8, BB_ * NH_), 128, SMEM_NF64>>>(
            probsH, S_, v, D_, ao, D_, S_, DH_, S_,
            NH_ * sSS, sSS, sSD, DH_, sSD, DH_, NH_, nullptr, 2);
    }

    // x2 = x + attnout @ wo (float out + residual)
    hgemm<false, 128, 1><<<dim3(8, 16, 1), 128, SMEM_NF128>>>(
        ao, D_, woh, D_, x2, D_, NTOK, D_, D_,
        0, 0, 0, 0, 0, 0, 1, x, 0);

    rmsnorm_kernel<<<NTOK, 256>>>(x2, mnw, h, htf);
    router_kernel<<<NTOK, 256>>>(h, rw);
    scan_kernel<<<1, 1>>>();
    place_kernel<<<(NTOK + 255) / 256, 256>>>();

    moe_hgemm<1><<<dim3(FF_ / 128, NSLOT / 128, E_), 128, SMEM_MOE>>>(htf, w1h, b1, D_, FF_);
    moe_hgemm<2><<<dim3(D_ / 128, NSLOT / 128, E_), 128, SMEM_MOE>>>(nullptr, w2h, b2, FF_, D_);

    combine_kernel<<<(NTOK * D_ + 255) / 256, 256>>>(out);
    finalize_kernel<<<1, 32>>>(out);
}

// round 8
// speedup vs baseline: 1.3727x; 1.0157x over previous
#include <cuda_runtime.h>
#include <cuda_fp16.h>
#include <math.h>
#include <stdint.h>

#define D_    1024
#define S_    1024
#define BB_   2
#define NTOK  2048
#define NH_   16
#define DH_   64
#define E_    8
#define KSEL  2
#define FF_   4096
#define NSLOT 4096

#define BKH   64          // K halfs per stage (128B)
#define ASTH  72          // A smem row stride (halfs): 16B-unit step 9 -> conflict-free
#define ASZB  (128*ASTH*2)  // 18432 B

// ---------------- static scratch ----------------
__device__ __half g_xn[NTOK * D_];
__device__ __half g_wqkvh[3 * D_ * D_];
__device__ __half g_woh[D_ * D_];
__device__ __half g_w1h[(size_t)E_ * D_ * FF_];
__device__ __half g_w2h[(size_t)E_ * FF_ * D_];
__device__ __half g_qkv[3 * NTOK * D_];
__device__ float  g_scoresF[(size_t)BB_ * NH_ * S_ * S_];
__device__ __half g_probsH[(size_t)BB_ * NH_ * S_ * S_];
__device__ __half g_attnout[NTOK * D_];
__device__ float  g_x2[NTOK * D_];
__device__ float  g_h[NTOK * D_];
__device__ __half g_htf[NTOK * D_];
__device__ __half g_act[(size_t)NSLOT * FF_];
__device__ float  g_y[(size_t)NSLOT * D_];
__device__ float g_topval[NTOK * KSEL];
__device__ int   g_topidx[NTOK * KSEL];
__device__ int   g_slotof[NTOK * KSEL];
__device__ int   g_perm[NSLOT];
__device__ int   g_counts[E_];
__device__ int   g_offs[E_ + 1];
__device__ int   g_cursor[E_];
__device__ float g_probsum[E_];

// ---------------- helpers ----------------
__device__ __forceinline__ float gelu_tanh(float v) {
    float v3 = v * v * v;
    return 0.5f * v * (1.f + tanhf(0.7978845608028654f * (v + 0.044715f * v3)));
}
__device__ __forceinline__ void cpa16(unsigned dst, const void* src, bool p) {
    int sz = p ? 16 : 0;
    asm volatile("cp.async.cg.shared.global [%0], [%1], 16, %2;\n"
                 :: "r"(dst), "l"(src), "r"(sz));
}
__device__ __forceinline__ void cp_commit() { asm volatile("cp.async.commit_group;\n"); }
__device__ __forceinline__ void ldsm4(unsigned& r0, unsigned& r1, unsigned& r2, unsigned& r3,
                                      unsigned addr) {
    asm volatile("ldmatrix.sync.aligned.m8n8.x4.shared.b16 {%0,%1,%2,%3}, [%4];"
                 : "=r"(r0), "=r"(r1), "=r"(r2), "=r"(r3) : "r"(addr));
}
__device__ __forceinline__ void ldsm4t(unsigned& r0, unsigned& r1, unsigned& r2, unsigned& r3,
                                       unsigned addr) {
    asm volatile("ldmatrix.sync.aligned.m8n8.x4.trans.shared.b16 {%0,%1,%2,%3}, [%4];"
                 : "=r"(r0), "=r"(r1), "=r"(r2), "=r"(r3) : "r"(addr));
}
__device__ __forceinline__ void mma16816(float* d, const unsigned* a, const unsigned* b) {
    asm volatile(
        "mma.sync.aligned.m16n8k16.row.col.f32.f16.f16.f32 "
        "{%0,%1,%2,%3}, {%4,%5,%6,%7}, {%8,%9}, {%0,%1,%2,%3};"
        : "+f"(d[0]), "+f"(d[1]), "+f"(d[2]), "+f"(d[3])
        : "r"(a[0]), "r"(a[1]), "r"(a[2]), "r"(a[3]), "r"(b[0]), "r"(b[1]));
}

// ---------------- utility kernels ----------------
__global__ void init_kernel() {
    int i = threadIdx.x;
    if (i < E_) { g_counts[i] = 0; g_cursor[i] = 0; g_probsum[i] = 0.f; }
}

__global__ void f2h_kernel(const float* __restrict__ in, __half* __restrict__ out,
                           long long n2) {
    for (long long i = blockIdx.x * 256LL + threadIdx.x; i < n2; i += (long long)gridDim.x * 256) {
        float2 v = ((const float2*)in)[i];
        ((__half2*)out)[i] = __floats2half2_rn(v.x, v.y);
    }
}

__global__ void rmsnorm_kernel(const float* __restrict__ X, const float* __restrict__ W,
                               float* __restrict__ O, __half* __restrict__ OT) {
    int t = blockIdx.x;
    const float* x = X + (size_t)t * D_;
    float ss = 0.f;
    for (int d = threadIdx.x; d < D_; d += 256) { float v = x[d]; ss += v * v; }
    __shared__ float red[256];
    red[threadIdx.x] = ss; __syncthreads();
    for (int s = 128; s > 0; s >>= 1) {
        if (threadIdx.x < s) red[threadIdx.x] += red[threadIdx.x + s];
        __syncthreads();
    }
    float scale = rsqrtf(red[0] * (1.f / D_) + 1e-6f);
    for (int d = threadIdx.x; d < D_; d += 256) {
        float v = x[d] * scale * W[d];
        if (O)  O[(size_t)t * D_ + d] = v;
        OT[(size_t)t * D_ + d] = __float2half_rn(v);
    }
}

// causal row softmax: single exp pass (no max-subtract; logits are O(1) bounded),
// probabilities kept in registers, scaled once, stored as half.
__global__ void softmax_kernel(const float* __restrict__ SC, __half* __restrict__ P) {
    int row = blockIdx.x;
    int bh = row >> 10, q = row & 1023;
    const float* s = SC + (size_t)bh * S_ * S_ + (size_t)q * S_;
    __half* p = P + (size_t)bh * S_ * S_ + (size_t)q * S_;
    int len = q + 1;
    int tid = threadIdx.x;
    __shared__ float red[128];
    float pv[8];
    int cnt = 0;
    float sum = 0.f;
    for (int j = tid; j < len; j += 128) {
        float e = __expf(s[j] * 0.125f);
        pv[cnt++] = e;
        sum += e;
    }
    red[tid] = sum; __syncthreads();
    for (int st = 64; st > 0; st >>= 1) {
        if (tid < st) red[tid] += red[tid + st];
        __syncthreads();
    }
    float inv = 1.f / red[0];
    cnt = 0;
    for (int j = tid; j < len; j += 128)
        p[j] = __float2half_rn(pv[cnt++] * inv);
    for (int j = len + tid; j < S_; j += 128) p[j] = __float2half_rn(0.f);
}

__global__ void router_kernel(const float* __restrict__ H, const float* __restrict__ RW) {
    int t = blockIdx.x;
    int tid = threadIdx.x;
    int e = tid >> 5, lane = tid & 31;
    const float* h = H + (size_t)t * D_;
    float p = 0.f;
    for (int d = lane; d < D_; d += 32) p += h[d] * RW[d * E_ + e];
    for (int o = 16; o > 0; o >>= 1) p += __shfl_down_sync(0xffffffff, p, o);
    __shared__ float lg[E_];
    if (lane == 0) lg[e] = p;
    __syncthreads();
    if (tid == 0) {
        float mx = lg[0];
        for (int i = 1; i < E_; i++) mx = fmaxf(mx, lg[i]);
        float pr[E_]; float s = 0.f;
        for (int i = 0; i < E_; i++) { pr[i] = expf(lg[i] - mx); s += pr[i]; }
        float inv = 1.f / s;
        float b1v = -1.f, b2v = -1.f; int b1i = 0, b2i = 0;
        for (int i = 0; i < E_; i++) {
            float v = pr[i] * inv;
            atomicAdd(&g_probsum[i], v);
            if (v > b1v) { b2v = b1v; b2i = b1i; b1v = v; b1i = i; }
            else if (v > b2v) { b2v = v; b2i = i; }
        }
        g_topidx[t * 2] = b1i; g_topidx[t * 2 + 1] = b2i;
        g_topval[t * 2] = b1v; g_topval[t * 2 + 1] = b2v;
        atomicAdd(&g_counts[b1i], 1);
        atomicAdd(&g_counts[b2i], 1);
    }
}

__global__ void scan_kernel() {
    if (threadIdx.x == 0) {
        g_offs[0] = 0;
        for (int e = 0; e < E_; e++) {
            g_offs[e + 1] = g_offs[e] + g_counts[e];
            g_cursor[e] = g_offs[e];
        }
    }
}

__global__ void place_kernel() {
    int t = blockIdx.x * blockDim.x + threadIdx.x;
    if (t >= NTOK) return;
    for (int kk = 0; kk < KSEL; kk++) {
        int e = g_topidx[t * 2 + kk];
        int slot = atomicAdd(&g_cursor[e], 1);
        g_perm[slot] = t;
        g_slotof[t * 2 + kk] = slot;
    }
}

__global__ void combine_kernel(float* __restrict__ out) {
    int idx = blockIdx.x * blockDim.x + threadIdx.x;
    if (idx >= NTOK * D_) return;
    int t = idx >> 10, d = idx & 1023;
    float v = g_x2[idx];
    v += g_topval[t * 2]     * g_y[(size_t)g_slotof[t * 2]     * D_ + d];
    v += g_topval[t * 2 + 1] * g_y[(size_t)g_slotof[t * 2 + 1] * D_ + d];
    out[idx] = v;
}

__global__ void finalize_kernel(float* __restrict__ out) {
    if (threadIdx.x == 0) {
        float loss = 0.f;
        for (int e = 0; e < E_; e++)
            loss += ((float)g_counts[e] / (float)NSLOT) * (g_probsum[e] / (float)NTOK);
        loss *= (float)E_;
        out[(size_t)NTOK * D_] = loss;
        for (int e = 0; e < E_; e++)
            out[(size_t)NTOK * D_ + 1 + e] = (float)g_counts[e];
    }
}

// ---------------- fp16 HMMA GEMM: 128xNT x64-stage, 4 warps, ldmatrix ----
// A [M,K] K-major half. B: TB ? [N,K] K-major : [K,N] N-major, half.
// EPI: 0 half store; 1 float store + float residual; 2 float store.
// mode: 0 none, 1 causal tile-skip, 2 k-clip.
template <bool TB, int NT, int EPI>
__global__ void __launch_bounds__(128, 2)
hgemm(const __half* __restrict__ A, int lda,
      const __half* __restrict__ B, int ldb,
      void* __restrict__ Cv, int ldc,
      int M, int N, int K,
      long long aO, long long aI, long long bO, long long bI,
      long long cO, long long cI, int zdiv,
      const float* __restrict__ addp, int mode) {
    constexpr int BSTH = NT + 8;                      // n-major B row stride (halfs)
    constexpr int BSZB = TB ? ASZB : (64 * BSTH * 2); // B stage bytes
    constexpr int STG  = ASZB + BSZB;
    constexpr int NTW  = NT / 16;                     // nt per warp
    extern __shared__ __align__(16) unsigned char smraw[];

    int z = blockIdx.z, zo = z / zdiv, zi = z % zdiv;
    A += zo * aO + zi * aI;
    B += zo * bO + zi * bI;

    int m0 = blockIdx.y * 128, n0 = blockIdx.x * NT;
    if (mode == 1 && n0 > m0 + 127) return;
    int Keff = (mode == 2) ? min(K, m0 + 128) : K;
    int KT = Keff / BKH;

    int tid = threadIdx.x, wid = tid >> 5, lane = tid & 31;
    int warpM = wid & 1, warpN = wid >> 1;
    int g = lane >> 2, t = lane & 3;
    unsigned smb = (unsigned)__cvta_generic_to_shared(smraw);

    bool av = (m0 + tid) < M;
    const __half* aptr = A + (size_t)(av ? (m0 + tid) : 0) * lda;
    const __half* bptr = nullptr;
    bool bv = true;
    if (TB) {
        bv = (n0 + tid) < N;
        bptr = B + (size_t)(bv ? (n0 + tid) : 0) * ldb;
    }

    float acc[4][NTW][4];
#pragma unroll
    for (int mt = 0; mt < 4; mt++)
#pragma unroll
        for (int nt = 0; nt < NTW; nt++)
#pragma unroll
            for (int r = 0; r < 4; r++) acc[mt][nt][r] = 0.f;

    auto issue = [&](int lt) {
        int s = lt & 1;
        unsigned ab = smb + (unsigned)s * STG;
        const __half* as = aptr + lt * BKH;
        unsigned arow = ab + (unsigned)tid * (ASTH * 2);
#pragma unroll
        for (int c = 0; c < 8; c++)
            cpa16(arow + c * 16, as + c * 8, av);
        unsigned bb = ab + ASZB;
        if (TB) {
            const __half* bs = bptr + lt * BKH;
            unsigned br = bb + (unsigned)tid * (ASTH * 2);
#pragma unroll
            for (int c = 0; c < 8; c++)
                cpa16(br + c * 16, bs + c * 8, bv);
        } else {
            int row = tid >> 1;                        // 0..63 (k)
            int cb = (tid & 1) * (NT / 16);
            const __half* bs = B + (size_t)(lt * BKH + row) * ldb + n0;
            unsigned br = bb + (unsigned)row * (BSTH * 2);
#pragma unroll
            for (int j = 0; j < NT / 16; j++)
                cpa16(br + (cb + j) * 16, bs + (cb + j) * 8, true);
        }
        cp_commit();
    };

    issue(0);
    for (int kt = 0; kt < KT; kt++) {
        int b = kt & 1;
        if (kt + 1 < KT) {
            issue(kt + 1);
            asm volatile("cp.async.wait_group 1;\n");
        } else {
            asm volatile("cp.async.wait_group 0;\n");
        }
        __syncthreads();

        unsigned aBase = smb + (unsigned)b * STG;
        unsigned bBase = aBase + ASZB;
#pragma unroll
        for (int ks = 0; ks < 4; ks++) {
            unsigned afr[4][4];
#pragma unroll
            for (int mt = 0; mt < 4; mt++) {
                int row = warpM * 64 + mt * 16 + (lane & 15);
                int kh = ks * 16 + ((lane >> 4) << 3);
                ldsm4(afr[mt][0], afr[mt][1], afr[mt][2], afr[mt][3],
                      aBase + (unsigned)(row * ASTH + kh) * 2);
            }
            unsigned bfr[NTW][2];
#pragma unroll
            for (int ntp = 0; ntp < NTW / 2; ntp++) {
                unsigned r0, r1, r2, r3;
                if (TB) {
                    int row = warpN * 64 + ntp * 16 + (lane & 15);
                    int kh = ks * 16 + ((lane >> 4) << 3);
                    ldsm4(r0, r1, r2, r3, bBase + (unsigned)(row * ASTH + kh) * 2);
                    bfr[2 * ntp][0] = r0; bfr[2 * ntp + 1][0] = r1;
                    bfr[2 * ntp][1] = r2; bfr[2 * ntp + 1][1] = r3;
                } else {
                    int krow = ks * 16 + (lane & 15);
                    int col = warpN * (NT / 2) + ntp * 16 + ((lane >> 4) << 3);
                    ldsm4t(r0, r1, r2, r3, bBase + (unsigned)(krow * BSTH + col) * 2);
                    bfr[2 * ntp][0] = r0; bfr[2 * ntp][1] = r1;
                    bfr[2 * ntp + 1][0] = r2; bfr[2 * ntp + 1][1] = r3;
                }
            }
#pragma unroll
            for (int mt = 0; mt < 4; mt++)
#pragma unroll
                for (int nt = 0; nt < NTW; nt++)
                    mma16816(acc[mt][nt], afr[mt], bfr[nt]);
        }
        __syncthreads();
    }

    // epilogue
#pragma unroll
    for (int mt = 0; mt < 4; mt++) {
#pragma unroll
        for (int nt = 0; nt < NTW; nt++) {
            int row = m0 + warpM * 64 + mt * 16 + g;
            int col = n0 + warpN * (NT / 2) + nt * 8 + 2 * t;
#pragma unroll
            for (int half_ = 0; half_ < 2; half_++) {
                int r = row + half_ * 8;
                if (r < M && col < N) {
                    float v0 = acc[mt][nt][half_ * 2 + 0];
                    float v1 = acc[mt][nt][half_ * 2 + 1];
                    size_t cidx = (size_t)(zo * cO + zi * cI) + (size_t)r * ldc + col;
                    if (EPI == 0) {
                        *(__half2*)((__half*)Cv + cidx) = __floats2half2_rn(v0, v1);
                    } else if (EPI == 1) {
                        float2 ad = *(const float2*)(addp + (size_t)r * ldc + col);
                        float2 o; o.x = v0 + ad.x; o.y = v1 + ad.y;
                        *(float2*)((float*)Cv + cidx) = o;
                    } else {
                        float2 o; o.x = v0; o.y = v1;
                        *(float2*)((float*)Cv + cidx) = o;
                    }
                }
            }
        }
    }
}

// ---------------- grouped MoE fp16 GEMMs ----------------
// EP 1: half(gelu(acc+bias)) -> g_act  (A = g_htf gathered, B = g_w1h[e] [K,N])
// EP 2: acc+bias (float) -> g_y        (A = g_act,          B = g_w2h[e] [K,N])
template <int EP>
__global__ void __launch_bounds__(128, 2)
moe_hgemm(const __half* __restrict__ H, const __half* __restrict__ W,
          const float* __restrict__ Bias, int Kdim, int Ndim) {
    constexpr int BSTH = 136;
    constexpr int BSZB = 64 * BSTH * 2;
    constexpr int STG  = ASZB + BSZB;
    extern __shared__ __align__(16) unsigned char smraw[];

    int e = blockIdx.z;
    int base = g_offs[e], cnt = g_offs[e + 1] - base;
    int m0 = blockIdx.y * 128;
    if (m0 >= cnt) return;
    int n0 = blockIdx.x * 128;
    const __half* Bmat = W + (size_t)e * (size_t)Kdim * Ndim;

    int tid = threadIdx.x, wid = tid >> 5, lane = tid & 31;
    int warpM = wid & 1, warpN = wid >> 1;
    int g = lane >> 2, t = lane & 3;
    unsigned smb = (unsigned)__cvta_generic_to_shared(smraw);
    float* sBias = (float*)smraw;          // 512 B
    unsigned tb0 = smb + 512;

    sBias[tid] = Bias[(size_t)e * Ndim + n0 + tid];

    bool av = (m0 + tid) < cnt;
    const __half* aptr;
    if (EP == 1) aptr = H + (size_t)(av ? g_perm[base + m0 + tid] : 0) * Kdim;
    else         aptr = g_act + (size_t)(av ? (base + m0 + tid) : 0) * Kdim;

    float acc[4][8][4];
#pragma unroll
    for (int mt = 0; mt < 4; mt++)
#pragma unroll
        for (int nt = 0; nt < 8; nt++)
#pragma unroll
            for (int r = 0; r < 4; r++) acc[mt][nt][r] = 0.f;

    int KT = Kdim / BKH;

    auto issue = [&](int lt) {
        int s = lt & 1;
        unsigned ab = tb0 + (unsigned)s * STG;
        const __half* as = aptr + lt * BKH;
        unsigned arow = ab + (unsigned)tid * (ASTH * 2);
#pragma unroll
        for (int c = 0; c < 8; c++)
            cpa16(arow + c * 16, as + c * 8, av);
        unsigned bb = ab + ASZB;
        int row = tid >> 1;
        int cb = (tid & 1) * 8;
        const __half* bs = Bmat + (size_t)(lt * BKH + row) * Ndim + n0;
        unsigned br = bb + (unsigned)row * (BSTH * 2);
#pragma unroll
        for (int j = 0; j < 8; j++)
            cpa16(br + (cb + j) * 16, bs + (cb + j) * 8, true);
        cp_commit();
    };

    issue(0);
    for (int kt = 0; kt < KT; kt++) {
        int b = kt & 1;
        if (kt + 1 < KT) {
            issue(kt + 1);
            asm volatile("cp.async.wait_group 1;\n");
        } else {
            asm volatile("cp.async.wait_group 0;\n");
        }
        __syncthreads();

        unsigned aBase = tb0 + (unsigned)b * STG;
        unsigned bBase = aBase + ASZB;
#pragma unroll
        for (int ks = 0; ks < 4; ks++) {
            unsigned afr[4][4];
#pragma unroll
            for (int mt = 0; mt < 4; mt++) {
                int row = warpM * 64 + mt * 16 + (lane & 15);
                int kh = ks * 16 + ((lane >> 4) << 3);
                ldsm4(afr[mt][0], afr[mt][1], afr[mt][2], afr[mt][3],
                      aBase + (unsigned)(row * ASTH + kh) * 2);
            }
            unsigned bfr[8][2];
#pragma unroll
            for (int ntp = 0; ntp < 4; ntp++) {
                unsigned r0, r1, r2, r3;
                int krow = ks * 16 + (lane & 15);
                int col = warpN * 64 + ntp * 16 + ((lane >> 4) << 3);
                ldsm4t(r0, r1, r2, r3, bBase + (unsigned)(krow * BSTH + col) * 2);
                bfr[2 * ntp][0] = r0; bfr[2 * ntp][1] = r1;
                bfr[2 * ntp + 1][0] = r2; bfr[2 * ntp + 1][1] = r3;
            }
#pragma unroll
            for (int mt = 0; mt < 4; mt++)
#pragma unroll
                for (int nt = 0; nt < 8; nt++)
                    mma16816(acc[mt][nt], afr[mt], bfr[nt]);
        }
        __syncthreads();
    }

#pragma unroll
    for (int mt = 0; mt < 4; mt++) {
#pragma unroll
        for (int nt = 0; nt < 8; nt++) {
            int rr = m0 + warpM * 64 + mt * 16 + g;
            int colL = warpN * 64 + nt * 8 + 2 * t;
            int col = n0 + colL;
#pragma unroll
            for (int half_ = 0; half_ < 2; half_++) {
                int r = rr + half_ * 8;
                if (r < cnt) {
                    float v0 = acc[mt][nt][half_ * 2 + 0] + sBias[colL];
                    float v1 = acc[mt][nt][half_ * 2 + 1] + sBias[colL + 1];
                    if (EP == 1) {
                        *(__half2*)(g_act + (size_t)(base + r) * FF_ + col) =
                            __floats2half2_rn(gelu_tanh(v0), gelu_tanh(v1));
                    } else {
                        float2 o; o.x = v0; o.y = v1;
                        *(float2*)(g_y + (size_t)(base + r) * D_ + col) = o;
                    }
                }
            }
        }
    }
}

// ---------------- launch ----------------
#define SMEM_NF128 (2 * (ASZB + 64 * 136 * 2))        // 71680  (TB=false, NT=128)
#define SMEM_T128  (2 * (ASZB + ASZB))                // 73728  (TB=true,  NT=128)
#define SMEM_NF64  (2 * (ASZB + 64 * 72 * 2))         // 55296  (TB=false, NT=64)
#define SMEM_MOE   (512 + 2 * (ASZB + 64 * 136 * 2))  // 72192

extern "C" void kernel_launch(void* const* d_in, const int* in_sizes, int n_in,
                              void* d_out, int out_size) {
    const float* x   = (const float*)d_in[0];
    const float* anw = (const float*)d_in[1];
    const float* wq  = (const float*)d_in[2];
    const float* wk  = (const float*)d_in[3];
    const float* wv  = (const float*)d_in[4];
    const float* wo  = (const float*)d_in[5];
    const float* mnw = (const float*)d_in[6];
    const float* rw  = (const float*)d_in[7];
    const float* w1  = (const float*)d_in[8];
    const float* b1  = (const float*)d_in[9];
    const float* w2  = (const float*)d_in[10];
    const float* b2  = (const float*)d_in[11];
    float* out = (float*)d_out;

    cudaFuncSetAttribute(hgemm<false, 128, 0>, cudaFuncAttributeMaxDynamicSharedMemorySize, SMEM_NF128);
    cudaFuncSetAttribute(hgemm<false, 128, 1>, cudaFuncAttributeMaxDynamicSharedMemorySize, SMEM_NF128);
    cudaFuncSetAttribute(hgemm<true, 128, 2>,  cudaFuncAttributeMaxDynamicSharedMemorySize, SMEM_T128);
    cudaFuncSetAttribute(hgemm<false, 64, 0>,  cudaFuncAttributeMaxDynamicSharedMemorySize, SMEM_NF64);
    cudaFuncSetAttribute(moe_hgemm<1>,         cudaFuncAttributeMaxDynamicSharedMemorySize, SMEM_MOE);
    cudaFuncSetAttribute(moe_hgemm<2>,         cudaFuncAttributeMaxDynamicSharedMemorySize, SMEM_MOE);

    __half *xn, *wqkvh, *woh, *w1h, *w2h, *qkv, *probsH, *ao, *htf;
    float *scF, *x2, *h;
    cudaGetSymbolAddress((void**)&xn,     g_xn);
    cudaGetSymbolAddress((void**)&wqkvh,  g_wqkvh);
    cudaGetSymbolAddress((void**)&woh,    g_woh);
    cudaGetSymbolAddress((void**)&w1h,    g_w1h);
    cudaGetSymbolAddress((void**)&w2h,    g_w2h);
    cudaGetSymbolAddress((void**)&qkv,    g_qkv);
    cudaGetSymbolAddress((void**)&scF,    g_scoresF);
    cudaGetSymbolAddress((void**)&probsH, g_probsH);
    cudaGetSymbolAddress((void**)&ao,     g_attnout);
    cudaGetSymbolAddress((void**)&x2,     g_x2);
    cudaGetSymbolAddress((void**)&h,      g_h);
    cudaGetSymbolAddress((void**)&htf,    g_htf);

    const __half* q = qkv;
    const __half* k = qkv + (size_t)NTOK * D_;
    const __half* v = qkv + 2 * (size_t)NTOK * D_;

    init_kernel<<<1, 32>>>();
    f2h_kernel<<<2048, 256>>>(wq, wqkvh, (long long)D_ * D_ / 2);
    f2h_kernel<<<2048, 256>>>(wk, wqkvh + (size_t)D_ * D_, (long long)D_ * D_ / 2);
    f2h_kernel<<<2048, 256>>>(wv, wqkvh + 2 * (size_t)D_ * D_, (long long)D_ * D_ / 2);
    f2h_kernel<<<2048, 256>>>(wo, woh, (long long)D_ * D_ / 2);
    f2h_kernel<<<4096, 256>>>(w1, w1h, (long long)E_ * D_ * FF_ / 2);
    f2h_kernel<<<4096, 256>>>(w2, w2h, (long long)E_ * FF_ * D_ / 2);

    rmsnorm_kernel<<<NTOK, 256>>>(x, anw, nullptr, xn);

    // fused QKV (z=3): half out
    hgemm<false, 128, 0><<<dim3(8, 16, 3), 128, SMEM_NF128>>>(
        xn, D_, wqkvh, D_, qkv, D_, NTOK, D_, D_,
        0, 0, (long long)D_ * D_, 0, (long long)NTOK * D_, 0, 1, nullptr, 0);

    // scores = Q @ K^T per (b,h): float out (exact logits), causal tile skip
    {
        long long sSD = (long long)S_ * D_, sSS = (long long)S_ * S_;
        hgemm<true, 128, 2><<<dim3(8, 8, BB_ * NH_), 128, SMEM_T128>>>(
            q, D_, k, D_, scF, S_, S_, S_, DH_,
            sSD, DH_, sSD, DH_, NH_ * sSS, sSS, NH_, nullptr, 1);
    }

    softmax_kernel<<<BB_ * NH_ * S_, 128>>>(scF, probsH);

    // attnout = P @ V per (b,h): B = v [K=S, N=64 slice] n-major, k-clip, half out
    {
        long long sSD = (long long)S_ * D_, sSS = (long long)S_ * S_;
        hgemm<false, 64, 0><<<dim3(1, 8, BB_ * NH_), 128, SMEM_NF64>>>(
            probsH, S_, v, D_, ao, D_, S_, DH_, S_,
            NH_ * sSS, sSS, sSD, DH_, sSD, DH_, NH_, nullptr, 2);
    }

    // x2 = x + attnout @ wo (float out + residual)
    hgemm<false, 128, 1><<<dim3(8, 16, 1), 128, SMEM_NF128>>>(
        ao, D_, woh, D_, x2, D_, NTOK, D_, D_,
        0, 0, 0, 0, 0, 0, 1, x, 0);

    rmsnorm_kernel<<<NTOK, 256>>>(x2, mnw, h, htf);
    router_kernel<<<NTOK, 256>>>(h, rw);
    scan_kernel<<<1, 1>>>();
    place_kernel<<<(NTOK + 255) / 256, 256>>>();

    moe_hgemm<1><<<dim3(FF_ / 128, NSLOT / 128, E_), 128, SMEM_MOE>>>(htf, w1h, b1, D_, FF_);
    moe_hgemm<2><<<dim3(D_ / 128, NSLOT / 128, E_), 128, SMEM_MOE>>>(nullptr, w2h, b2, FF_, D_);

    combine_kernel<<<(NTOK * D_ + 255) / 256, 256>>>(out);
    finalize_kernel<<<1, 32>>>(out);
}

// round 9
// speedup vs baseline: 1.4914x; 1.0865x over previous
#include <cuda_runtime.h>
#include <cuda_fp16.h>
#include <math.h>
#include <stdint.h>

#define D_    1024
#define S_    1024
#define BB_   2
#define NTOK  2048
#define NH_   16
#define DH_   64
#define E_    8
#define KSEL  2
#define FF_   4096
#define NSLOT 4096

#define BKH   64            // K halfs per stage (128B)
#define ASTH  72            // A smem row stride (halfs)
#define ASZB  (128*ASTH*2)  // 18432 B

// ---------------- static scratch ----------------
__device__ __half g_xn[NTOK * D_];
__device__ __half g_wqkvh[3 * D_ * D_];
__device__ __half g_woh[D_ * D_];
__device__ __half g_w1h[(size_t)E_ * D_ * FF_];
__device__ __half g_w2h[(size_t)E_ * FF_ * D_];
__device__ __half g_qkv[3 * NTOK * D_];
__device__ __half g_probsH[(size_t)BB_ * NH_ * S_ * S_];   // unnormalized exp
__device__ float  g_invsum[BB_ * NH_ * S_];
__device__ __half g_attnout[NTOK * D_];
__device__ float  g_x2[NTOK * D_];
__device__ float  g_h[NTOK * D_];
__device__ __half g_htf[NTOK * D_];
__device__ __half g_act[(size_t)NSLOT * FF_];
__device__ float  g_y[(size_t)NSLOT * D_];
__device__ float g_topval[NTOK * KSEL];
__device__ int   g_topidx[NTOK * KSEL];
__device__ int   g_slotof[NTOK * KSEL];
__device__ int   g_perm[NSLOT];
__device__ int   g_counts[E_];
__device__ int   g_offs[E_ + 1];
__device__ int   g_cursor[E_];
__device__ float g_probsum[E_];

// ---------------- helpers ----------------
__device__ __forceinline__ float gelu_tanh(float v) {
    float v3 = v * v * v;
    return 0.5f * v * (1.f + tanhf(0.7978845608028654f * (v + 0.044715f * v3)));
}
__device__ __forceinline__ void cpa16(unsigned dst, const void* src, bool p) {
    int sz = p ? 16 : 0;
    asm volatile("cp.async.cg.shared.global [%0], [%1], 16, %2;\n"
                 :: "r"(dst), "l"(src), "r"(sz));
}
__device__ __forceinline__ void cp_commit() { asm volatile("cp.async.commit_group;\n"); }
__device__ __forceinline__ void ldsm4(unsigned& r0, unsigned& r1, unsigned& r2, unsigned& r3,
                                      unsigned addr) {
    asm volatile("ldmatrix.sync.aligned.m8n8.x4.shared.b16 {%0,%1,%2,%3}, [%4];"
                 : "=r"(r0), "=r"(r1), "=r"(r2), "=r"(r3) : "r"(addr));
}
__device__ __forceinline__ void ldsm4t(unsigned& r0, unsigned& r1, unsigned& r2, unsigned& r3,
                                       unsigned addr) {
    asm volatile("ldmatrix.sync.aligned.m8n8.x4.trans.shared.b16 {%0,%1,%2,%3}, [%4];"
                 : "=r"(r0), "=r"(r1), "=r"(r2), "=r"(r3) : "r"(addr));
}
__device__ __forceinline__ void mma16816(float* d, const unsigned* a, const unsigned* b) {
    asm volatile(
        "mma.sync.aligned.m16n8k16.row.col.f32.f16.f16.f32 "
        "{%0,%1,%2,%3}, {%4,%5,%6,%7}, {%8,%9}, {%0,%1,%2,%3};"
        : "+f"(d[0]), "+f"(d[1]), "+f"(d[2]), "+f"(d[3])
        : "r"(a[0]), "r"(a[1]), "r"(a[2]), "r"(a[3]), "r"(b[0]), "r"(b[1]));
}

// ---------------- utility kernels ----------------
__global__ void init_kernel() {
    int i = threadIdx.x;
    if (i < E_) { g_counts[i] = 0; g_cursor[i] = 0; g_probsum[i] = 0.f; }
}

// vectorized f2h: 2x float4 in -> uint4 (8 halfs) out per iter
__global__ void f2h_kernel(const float4* __restrict__ in, uint4* __restrict__ out,
                           long long n8) {
    for (long long i = blockIdx.x * 256LL + threadIdx.x; i < n8;
         i += (long long)gridDim.x * 256) {
        float4 a = in[2 * i], b = in[2 * i + 1];
        __half2 h0 = __floats2half2_rn(a.x, a.y);
        __half2 h1 = __floats2half2_rn(a.z, a.w);
        __half2 h2 = __floats2half2_rn(b.x, b.y);
        __half2 h3 = __floats2half2_rn(b.z, b.w);
        uint4 o;
        o.x = *(unsigned*)&h0; o.y = *(unsigned*)&h1;
        o.z = *(unsigned*)&h2; o.w = *(unsigned*)&h3;
        out[i] = o;
    }
}

__global__ void rmsnorm_kernel(const float* __restrict__ X, const float* __restrict__ W,
                               float* __restrict__ O, __half* __restrict__ OT) {
    int t = blockIdx.x;
    const float* x = X + (size_t)t * D_;
    float ss = 0.f;
    for (int d = threadIdx.x; d < D_; d += 256) { float v = x[d]; ss += v * v; }
    __shared__ float red[256];
    red[threadIdx.x] = ss; __syncthreads();
    for (int s = 128; s > 0; s >>= 1) {
        if (threadIdx.x < s) red[threadIdx.x] += red[threadIdx.x + s];
        __syncthreads();
    }
    float scale = rsqrtf(red[0] * (1.f / D_) + 1e-6f);
    for (int d = threadIdx.x; d < D_; d += 256) {
        float v = x[d] * scale * W[d];
        if (O)  O[(size_t)t * D_ + d] = v;
        OT[(size_t)t * D_ + d] = __float2half_rn(v);
    }
}

// per-row sum of unnormalized exp -> inverse
__global__ void rowsum_kernel(const __half* __restrict__ P, float* __restrict__ INV) {
    int row = blockIdx.x;                 // bh*S + q
    int q = row & 1023;
    const __half* p = P + (size_t)row * S_;
    int len = q + 1;
    int tid = threadIdx.x;
    __shared__ float red[128];
    float sum = 0.f;
    for (int j = tid; j < len; j += 128) sum += __half2float(p[j]);
    red[tid] = sum; __syncthreads();
    for (int st = 64; st > 0; st >>= 1) {
        if (tid < st) red[tid] += red[tid + st];
        __syncthreads();
    }
    if (tid == 0) INV[row] = 1.f / red[0];
}

__global__ void router_kernel(const float* __restrict__ H, const float* __restrict__ RW) {
    int t = blockIdx.x;
    int tid = threadIdx.x;
    int e = tid >> 5, lane = tid & 31;
    const float* h = H + (size_t)t * D_;
    float p = 0.f;
    for (int d = lane; d < D_; d += 32) p += h[d] * RW[d * E_ + e];
    for (int o = 16; o > 0; o >>= 1) p += __shfl_down_sync(0xffffffff, p, o);
    __shared__ float lg[E_];
    if (lane == 0) lg[e] = p;
    __syncthreads();
    if (tid == 0) {
        float mx = lg[0];
        for (int i = 1; i < E_; i++) mx = fmaxf(mx, lg[i]);
        float pr[E_]; float s = 0.f;
        for (int i = 0; i < E_; i++) { pr[i] = expf(lg[i] - mx); s += pr[i]; }
        float inv = 1.f / s;
        float b1v = -1.f, b2v = -1.f; int b1i = 0, b2i = 0;
        for (int i = 0; i < E_; i++) {
            float v = pr[i] * inv;
            atomicAdd(&g_probsum[i], v);
            if (v > b1v) { b2v = b1v; b2i = b1i; b1v = v; b1i = i; }
            else if (v > b2v) { b2v = v; b2i = i; }
        }
        g_topidx[t * 2] = b1i; g_topidx[t * 2 + 1] = b2i;
        g_topval[t * 2] = b1v; g_topval[t * 2 + 1] = b2v;
        atomicAdd(&g_counts[b1i], 1);
        atomicAdd(&g_counts[b2i], 1);
    }
}

__global__ void scan_kernel() {
    if (threadIdx.x == 0) {
        g_offs[0] = 0;
        for (int e = 0; e < E_; e++) {
            g_offs[e + 1] = g_offs[e] + g_counts[e];
            g_cursor[e] = g_offs[e];
        }
    }
}

__global__ void place_kernel() {
    int t = blockIdx.x * blockDim.x + threadIdx.x;
    if (t >= NTOK) return;
    for (int kk = 0; kk < KSEL; kk++) {
        int e = g_topidx[t * 2 + kk];
        int slot = atomicAdd(&g_cursor[e], 1);
        g_perm[slot] = t;
        g_slotof[t * 2 + kk] = slot;
    }
}

__global__ void combine_kernel(float* __restrict__ out) {
    int idx = blockIdx.x * blockDim.x + threadIdx.x;
    if (idx >= NTOK * D_) return;
    int t = idx >> 10, d = idx & 1023;
    float v = g_x2[idx];
    v += g_topval[t * 2]     * g_y[(size_t)g_slotof[t * 2]     * D_ + d];
    v += g_topval[t * 2 + 1] * g_y[(size_t)g_slotof[t * 2 + 1] * D_ + d];
    out[idx] = v;
}

__global__ void finalize_kernel(float* __restrict__ out) {
    if (threadIdx.x == 0) {
        float loss = 0.f;
        for (int e = 0; e < E_; e++)
            loss += ((float)g_counts[e] / (float)NSLOT) * (g_probsum[e] / (float)NTOK);
        loss *= (float)E_;
        out[(size_t)NTOK * D_] = loss;
        for (int e = 0; e < E_; e++)
            out[(size_t)NTOK * D_ + 1 + e] = (float)g_counts[e];
    }
}

// ---------------- fp16 HMMA GEMM ----------------
// A [M,K] K-major half. B: TB ? [N,K] K-major : [K,N] N-major, half.
// EPI: 0 half store; 1 float store + residual; 2 float store;
//      3 half store of causal-masked exp(v*0.125);
//      4 half store of v * addp[z*S_ + r] (row scale).
// mode: 0 none, 1 causal tile-skip, 2 k-clip.
template <bool TB, int NT, int EPI>
__global__ void __launch_bounds__(128, 2)
hgemm(const __half* __restrict__ A, int lda,
      const __half* __restrict__ B, int ldb,
      void* __restrict__ Cv, int ldc,
      int M, int N, int K,
      long long aO, long long aI, long long bO, long long bI,
      long long cO, long long cI, int zdiv,
      const float* __restrict__ addp, int mode) {
    constexpr int BSTH = NT + 8;
    constexpr int BSZB = TB ? ASZB : (64 * BSTH * 2);
    constexpr int STG  = ASZB + BSZB;
    constexpr int NTW  = NT / 16;
    extern __shared__ __align__(16) unsigned char smraw[];

    int z = blockIdx.z, zo = z / zdiv, zi = z % zdiv;
    A += zo * aO + zi * aI;
    B += zo * bO + zi * bI;

    int m0 = blockIdx.y * 128, n0 = blockIdx.x * NT;
    if (mode == 1 && n0 > m0 + 127) return;
    int Keff = (mode == 2) ? min(K, m0 + 128) : K;
    int KT = Keff / BKH;

    int tid = threadIdx.x, wid = tid >> 5, lane = tid & 31;
    int warpM = wid & 1, warpN = wid >> 1;
    int g = lane >> 2, t = lane & 3;
    unsigned smb = (unsigned)__cvta_generic_to_shared(smraw);

    bool av = (m0 + tid) < M;
    const __half* aptr = A + (size_t)(av ? (m0 + tid) : 0) * lda;
    const __half* bptr = nullptr;
    bool bv = true;
    if (TB) {
        bv = (n0 + tid) < N;
        bptr = B + (size_t)(bv ? (n0 + tid) : 0) * ldb;
    }

    float acc[4][NTW][4];
#pragma unroll
    for (int mt = 0; mt < 4; mt++)
#pragma unroll
        for (int nt = 0; nt < NTW; nt++)
#pragma unroll
            for (int r = 0; r < 4; r++) acc[mt][nt][r] = 0.f;

    auto issue = [&](int lt) {
        int s = lt & 1;
        unsigned ab = smb + (unsigned)s * STG;
        const __half* as = aptr + lt * BKH;
        unsigned arow = ab + (unsigned)tid * (ASTH * 2);
#pragma unroll
        for (int c = 0; c < 8; c++)
            cpa16(arow + c * 16, as + c * 8, av);
        unsigned bb = ab + ASZB;
        if (TB) {
            const __half* bs = bptr + lt * BKH;
            unsigned br = bb + (unsigned)tid * (ASTH * 2);
#pragma unroll
            for (int c = 0; c < 8; c++)
                cpa16(br + c * 16, bs + c * 8, bv);
        } else {
            int row = tid >> 1;
            int cb = (tid & 1) * (NT / 16);
            const __half* bs = B + (size_t)(lt * BKH + row) * ldb + n0;
            unsigned br = bb + (unsigned)row * (BSTH * 2);
#pragma unroll
            for (int j = 0; j < NT / 16; j++)
                cpa16(br + (cb + j) * 16, bs + (cb + j) * 8, true);
        }
        cp_commit();
    };

    issue(0);
    for (int kt = 0; kt < KT; kt++) {
        int b = kt & 1;
        if (kt + 1 < KT) {
            issue(kt + 1);
            asm volatile("cp.async.wait_group 1;\n");
        } else {
            asm volatile("cp.async.wait_group 0;\n");
        }
        __syncthreads();

        unsigned aBase = smb + (unsigned)b * STG;
        unsigned bBase = aBase + ASZB;
#pragma unroll
        for (int ks = 0; ks < 4; ks++) {
            unsigned afr[4][4];
#pragma unroll
            for (int mt = 0; mt < 4; mt++) {
                int row = warpM * 64 + mt * 16 + (lane & 15);
                int kh = ks * 16 + ((lane >> 4) << 3);
                ldsm4(afr[mt][0], afr[mt][1], afr[mt][2], afr[mt][3],
                      aBase + (unsigned)(row * ASTH + kh) * 2);
            }
            unsigned bfr[NTW][2];
#pragma unroll
            for (int ntp = 0; ntp < NTW / 2; ntp++) {
                unsigned r0, r1, r2, r3;
                if (TB) {
                    int row = warpN * 64 + ntp * 16 + (lane & 15);
                    int kh = ks * 16 + ((lane >> 4) << 3);
                    ldsm4(r0, r1, r2, r3, bBase + (unsigned)(row * ASTH + kh) * 2);
                    bfr[2 * ntp][0] = r0; bfr[2 * ntp + 1][0] = r1;
                    bfr[2 * ntp][1] = r2; bfr[2 * ntp + 1][1] = r3;
                } else {
                    int krow = ks * 16 + (lane & 15);
                    int col = warpN * (NT / 2) + ntp * 16 + ((lane >> 4) << 3);
                    ldsm4t(r0, r1, r2, r3, bBase + (unsigned)(krow * BSTH + col) * 2);
                    bfr[2 * ntp][0] = r0; bfr[2 * ntp][1] = r1;
                    bfr[2 * ntp + 1][0] = r2; bfr[2 * ntp + 1][1] = r3;
                }
            }
#pragma unroll
            for (int mt = 0; mt < 4; mt++)
#pragma unroll
                for (int nt = 0; nt < NTW; nt++)
                    mma16816(acc[mt][nt], afr[mt], bfr[nt]);
        }
        __syncthreads();
    }

    // epilogue
#pragma unroll
    for (int mt = 0; mt < 4; mt++) {
#pragma unroll
        for (int nt = 0; nt < NTW; nt++) {
            int row = m0 + warpM * 64 + mt * 16 + g;
            int col = n0 + warpN * (NT / 2) + nt * 8 + 2 * t;
#pragma unroll
            for (int half_ = 0; half_ < 2; half_++) {
                int r = row + half_ * 8;
                if (r < M && col < N) {
                    float v0 = acc[mt][nt][half_ * 2 + 0];
                    float v1 = acc[mt][nt][half_ * 2 + 1];
                    size_t cidx = (size_t)(zo * cO + zi * cI) + (size_t)r * ldc + col;
                    if (EPI == 0) {
                        *(__half2*)((__half*)Cv + cidx) = __floats2half2_rn(v0, v1);
                    } else if (EPI == 1) {
                        float2 ad = *(const float2*)(addp + (size_t)r * ldc + col);
                        float2 o; o.x = v0 + ad.x; o.y = v1 + ad.y;
                        *(float2*)((float*)Cv + cidx) = o;
                    } else if (EPI == 2) {
                        float2 o; o.x = v0; o.y = v1;
                        *(float2*)((float*)Cv + cidx) = o;
                    } else if (EPI == 3) {
                        float e0 = (col     <= r) ? __expf(v0 * 0.125f) : 0.f;
                        float e1 = (col + 1 <= r) ? __expf(v1 * 0.125f) : 0.f;
                        *(__half2*)((__half*)Cv + cidx) = __floats2half2_rn(e0, e1);
                    } else {  // EPI == 4
                        float sc = addp[(size_t)z * S_ + r];
                        *(__half2*)((__half*)Cv + cidx) = __floats2half2_rn(v0 * sc, v1 * sc);
                    }
                }
            }
        }
    }
}

// ---------------- grouped MoE fp16 GEMMs: 256 thr, 128x256 tiles ----------
// EP 1: half(gelu(acc+bias)) -> g_act  (A = g_htf gathered, B = g_w1h[e] [K,N])
// EP 2: acc+bias (float) -> g_y        (A = g_act,          B = g_w2h[e] [K,N])
template <int EP>
__global__ void __launch_bounds__(256, 1)
moe_hgemm(const __half* __restrict__ H, const __half* __restrict__ W,
          const float* __restrict__ Bias, int Kdim, int Ndim) {
    constexpr int BSTH = 264;              // 256+8 halfs; 33 odd 16B units
    constexpr int BSZB = 64 * BSTH * 2;    // 33792
    constexpr int STG  = ASZB + BSZB;      // 52224
    extern __shared__ __align__(16) unsigned char smraw[];

    int e = blockIdx.z;
    int base = g_offs[e], cnt = g_offs[e + 1] - base;
    int m0 = blockIdx.y * 128;
    if (m0 >= cnt) return;
    int n0 = blockIdx.x * 256;
    const __half* Bmat = W + (size_t)e * (size_t)Kdim * Ndim;

    int tid = threadIdx.x, wid = tid >> 5, lane = tid & 31;
    int warpM = wid & 1, warpN = wid >> 1;       // 2 x 4 warp grid
    int g = lane >> 2, t = lane & 3;
    unsigned smb = (unsigned)__cvta_generic_to_shared(smraw);
    float* sBias = (float*)smraw;                // 1024 B
    unsigned tb0 = smb + 1024;

    sBias[tid] = Bias[(size_t)e * Ndim + n0 + tid];

    int arow_i = tid >> 1;
    bool av = (m0 + arow_i) < cnt;
    const __half* aptr;
    if (EP == 1) aptr = H + (size_t)(av ? g_perm[base + m0 + arow_i] : 0) * Kdim;
    else         aptr = g_act + (size_t)(av ? (base + m0 + arow_i) : 0) * Kdim;
    int ahalf = (tid & 1) * 32;                  // half-row (32 halfs) per thread

    int brow = tid >> 2, bq = tid & 3;           // 64 rows x 4 quarters

    float acc[4][8][4];
#pragma unroll
    for (int mt = 0; mt < 4; mt++)
#pragma unroll
        for (int nt = 0; nt < 8; nt++)
#pragma unroll
            for (int r = 0; r < 4; r++) acc[mt][nt][r] = 0.f;

    int KT = Kdim / BKH;

    auto issue = [&](int lt) {
        int s = lt & 1;
        unsigned ab = tb0 + (unsigned)s * STG;
        const __half* as = aptr + lt * BKH + ahalf;
        unsigned ar = ab + (unsigned)arow_i * (ASTH * 2) + (unsigned)(tid & 1) * 64;
#pragma unroll
        for (int c = 0; c < 4; c++)
            cpa16(ar + c * 16, as + c * 8, av);
        unsigned bb = ab + ASZB;
        const __half* bs = Bmat + (size_t)(lt * BKH + brow) * Ndim + n0 + bq * 64;
        unsigned br = bb + (unsigned)brow * (BSTH * 2) + (unsigned)bq * 128;
#pragma unroll
        for (int c = 0; c < 8; c++)
            cpa16(br + c * 16, bs + c * 8, true);
        cp_commit();
    };

    issue(0);
    for (int kt = 0; kt < KT; kt++) {
        int b = kt & 1;
        if (kt + 1 < KT) {
            issue(kt + 1);
            asm volatile("cp.async.wait_group 1;\n");
        } else {
            asm volatile("cp.async.wait_group 0;\n");
        }
        __syncthreads();

        unsigned aBase = tb0 + (unsigned)b * STG;
        unsigned bBase = aBase + ASZB;
#pragma unroll
        for (int ks = 0; ks < 4; ks++) {
            unsigned afr[4][4];
#pragma unroll
            for (int mt = 0; mt < 4; mt++) {
                int row = warpM * 64 + mt * 16 + (lane & 15);
                int kh = ks * 16 + ((lane >> 4) << 3);
                ldsm4(afr[mt][0], afr[mt][1], afr[mt][2], afr[mt][3],
                      aBase + (unsigned)(row * ASTH + kh) * 2);
            }
            unsigned bfr[8][2];
#pragma unroll
            for (int ntp = 0; ntp < 4; ntp++) {
                unsigned r0, r1, r2, r3;
                int krow = ks * 16 + (lane & 15);
                int col = warpN * 64 + ntp * 16 + ((lane >> 4) << 3);
                ldsm4t(r0, r1, r2, r3, bBase + (unsigned)(krow * BSTH + col) * 2);
                bfr[2 * ntp][0] = r0; bfr[2 * ntp][1] = r1;
                bfr[2 * ntp + 1][0] = r2; bfr[2 * ntp + 1][1] = r3;
            }
#pragma unroll
            for (int mt = 0; mt < 4; mt++)
#pragma unroll
                for (int nt = 0; nt < 8; nt++)
                    mma16816(acc[mt][nt], afr[mt], bfr[nt]);
        }
        __syncthreads();
    }

#pragma unroll
    for (int mt = 0; mt < 4; mt++) {
#pragma unroll
        for (int nt = 0; nt < 8; nt++) {
            int rr = m0 + warpM * 64 + mt * 16 + g;
            int colL = warpN * 64 + nt * 8 + 2 * t;
            int col = n0 + colL;
#pragma unroll
            for (int half_ = 0; half_ < 2; half_++) {
                int r = rr + half_ * 8;
                if (r < cnt) {
                    float v0 = acc[mt][nt][half_ * 2 + 0] + sBias[colL];
                    float v1 = acc[mt][nt][half_ * 2 + 1] + sBias[colL + 1];
                    if (EP == 1) {
                        *(__half2*)(g_act + (size_t)(base + r) * FF_ + col) =
                            __floats2half2_rn(gelu_tanh(v0), gelu_tanh(v1));
                    } else {
                        float2 o; o.x = v0; o.y = v1;
                        *(float2*)(g_y + (size_t)(base + r) * D_ + col) = o;
                    }
                }
            }
        }
    }
}

// ---------------- launch ----------------
#define SMEM_NF128 (2 * (ASZB + 64 * 136 * 2))
#define SMEM_T128  (2 * (ASZB + ASZB))
#define SMEM_NF64  (2 * (ASZB + 64 * 72 * 2))
#define SMEM_MOE   (1024 + 2 * (ASZB + 64 * 264 * 2))   // 105472

extern "C" void kernel_launch(void* const* d_in, const int* in_sizes, int n_in,
                              void* d_out, int out_size) {
    const float* x   = (const float*)d_in[0];
    const float* anw = (const float*)d_in[1];
    const float* wq  = (const float*)d_in[2];
    const float* wk  = (const float*)d_in[3];
    const float* wv  = (const float*)d_in[4];
    const float* wo  = (const float*)d_in[5];
    const float* mnw = (const float*)d_in[6];
    const float* rw  = (const float*)d_in[7];
    const float* w1  = (const float*)d_in[8];
    const float* b1  = (const float*)d_in[9];
    const float* w2  = (const float*)d_in[10];
    const float* b2  = (const float*)d_in[11];
    float* out = (float*)d_out;

    cudaFuncSetAttribute(hgemm<false, 128, 0>, cudaFuncAttributeMaxDynamicSharedMemorySize, SMEM_NF128);
    cudaFuncSetAttribute(hgemm<false, 128, 1>, cudaFuncAttributeMaxDynamicSharedMemorySize, SMEM_NF128);
    cudaFuncSetAttribute(hgemm<true, 128, 3>,  cudaFuncAttributeMaxDynamicSharedMemorySize, SMEM_T128);
    cudaFuncSetAttribute(hgemm<false, 64, 4>,  cudaFuncAttributeMaxDynamicSharedMemorySize, SMEM_NF64);
    cudaFuncSetAttribute(moe_hgemm<1>,         cudaFuncAttributeMaxDynamicSharedMemorySize, SMEM_MOE);
    cudaFuncSetAttribute(moe_hgemm<2>,         cudaFuncAttributeMaxDynamicSharedMemorySize, SMEM_MOE);

    __half *xn, *wqkvh, *woh, *w1h, *w2h, *qkv, *probsH, *ao, *htf;
    float *x2, *h, *invs;
    cudaGetSymbolAddress((void**)&xn,     g_xn);
    cudaGetSymbolAddress((void**)&wqkvh,  g_wqkvh);
    cudaGetSymbolAddress((void**)&woh,    g_woh);
    cudaGetSymbolAddress((void**)&w1h,    g_w1h);
    cudaGetSymbolAddress((void**)&w2h,    g_w2h);
    cudaGetSymbolAddress((void**)&qkv,    g_qkv);
    cudaGetSymbolAddress((void**)&probsH, g_probsH);
    cudaGetSymbolAddress((void**)&invs,   g_invsum);
    cudaGetSymbolAddress((void**)&ao,     g_attnout);
    cudaGetSymbolAddress((void**)&x2,     g_x2);
    cudaGetSymbolAddress((void**)&h,      g_h);
    cudaGetSymbolAddress((void**)&htf,    g_htf);

    const __half* q = qkv;
    const __half* k = qkv + (size_t)NTOK * D_;
    const __half* v = qkv + 2 * (size_t)NTOK * D_;

    init_kernel<<<1, 32>>>();
    f2h_kernel<<<1024, 256>>>((const float4*)wq, (uint4*)wqkvh, (long long)D_ * D_ / 8);
    f2h_kernel<<<1024, 256>>>((const float4*)wk, (uint4*)(wqkvh + (size_t)D_ * D_), (long long)D_ * D_ / 8);
    f2h_kernel<<<1024, 256>>>((const float4*)wv, (uint4*)(wqkvh + 2 * (size_t)D_ * D_), (long long)D_ * D_ / 8);
    f2h_kernel<<<1024, 256>>>((const float4*)wo, (uint4*)woh, (long long)D_ * D_ / 8);
    f2h_kernel<<<4096, 256>>>((const float4*)w1, (uint4*)w1h, (long long)E_ * D_ * FF_ / 8);
    f2h_kernel<<<4096, 256>>>((const float4*)w2, (uint4*)w2h, (long long)E_ * FF_ * D_ / 8);

    rmsnorm_kernel<<<NTOK, 256>>>(x, anw, nullptr, xn);

    // fused QKV (z=3): half out
    hgemm<false, 128, 0><<<dim3(8, 16, 3), 128, SMEM_NF128>>>(
        xn, D_, wqkvh, D_, qkv, D_, NTOK, D_, D_,
        0, 0, (long long)D_ * D_, 0, (long long)NTOK * D_, 0, 1, nullptr, 0);

    // E = exp(Q@K^T / 8), causal-masked, half, unnormalized
    {
        long long sSD = (long long)S_ * D_, sSS = (long long)S_ * S_;
        hgemm<true, 128, 3><<<dim3(8, 8, BB_ * NH_), 128, SMEM_T128>>>(
            q, D_, k, D_, probsH, S_, S_, S_, DH_,
            sSD, DH_, sSD, DH_, NH_ * sSS, sSS, NH_, nullptr, 1);
    }

    rowsum_kernel<<<BB_ * NH_ * S_, 128>>>(probsH, invs);

    // attnout = (E @ V) * invsum[row], k-clipped, half out
    {
        long long sSD = (long long)S_ * D_, sSS = (long long)S_ * S_;
        hgemm<false, 64, 4><<<dim3(1, 8, BB_ * NH_), 128, SMEM_NF64>>>(
            probsH, S_, v, D_, ao, D_, S_, DH_, S_,
            NH_ * sSS, sSS, sSD, DH_, sSD, DH_, NH_, invs, 2);
    }

    // x2 = x + attnout @ wo (float out + residual)
    hgemm<false, 128, 1><<<dim3(8, 16, 1), 128, SMEM_NF128>>>(
        ao, D_, woh, D_, x2, D_, NTOK, D_, D_,
        0, 0, 0, 0, 0, 0, 1, x, 0);

    rmsnorm_kernel<<<NTOK, 256>>>(x2, mnw, h, htf);
    router_kernel<<<NTOK, 256>>>(h, rw);
    scan_kernel<<<1, 1>>>();
    place_kernel<<<(NTOK + 255) / 256, 256>>>();

    moe_hgemm<1><<<dim3(FF_ / 256, NSLOT / 128, E_), 256, SMEM_MOE>>>(htf, w1h, b1, D_, FF_);
    moe_hgemm<2><<<dim3(D_ / 256, NSLOT / 128, E_), 256, SMEM_MOE>>>(nullptr, w2h, b2, FF_, D_);

    combine_kernel<<<(NTOK * D_ + 255) / 256, 256>>>(out);
    finalize_kernel<<<1, 32>>>(out);
}

// round 10
// speedup vs baseline: 1.5088x; 1.0117x over previous
#include <cuda_runtime.h>
#include <cuda_fp16.h>
#include <math.h>
#include <stdint.h>

#define D_    1024
#define S_    1024
#define BB_   2
#define NTOK  2048
#define NH_   16
#define DH_   64
#define E_    8
#define KSEL  2
#define FF_   4096
#define NSLOT 4096

#define BKH   64            // K halfs per stage (128B)
#define ASTH  72            // A smem row stride (halfs)
#define ASZB  (128*ASTH*2)  // 18432 B

// ---------------- static scratch ----------------
__device__ __half g_xn[NTOK * D_];
__device__ __half g_wqkvh[3 * D_ * D_];
__device__ __half g_woh[D_ * D_];
__device__ __half g_w1h[(size_t)E_ * D_ * FF_];
__device__ __half g_w2h[(size_t)E_ * FF_ * D_];
__device__ __half g_qkv[3 * NTOK * D_];
__device__ __half g_probsH[(size_t)BB_ * NH_ * S_ * S_];   // unnormalized exp
__device__ float  g_invsum[BB_ * NH_ * S_];
__device__ __half g_attnout[NTOK * D_];
__device__ float  g_x2[NTOK * D_];
__device__ float  g_h[NTOK * D_];
__device__ __half g_htf[NTOK * D_];
__device__ __half g_act[(size_t)NSLOT * FF_];
__device__ float  g_y[(size_t)NSLOT * D_];
__device__ float g_topval[NTOK * KSEL];
__device__ int   g_topidx[NTOK * KSEL];
__device__ int   g_slotof[NTOK * KSEL];
__device__ int   g_perm[NSLOT];
__device__ int   g_counts[E_];
__device__ int   g_offs[E_ + 1];
__device__ int   g_cursor[E_];
__device__ float g_probsum[E_];

// ---------------- helpers ----------------
__device__ __forceinline__ float gelu_tanh(float v) {
    float v3 = v * v * v;
    return 0.5f * v * (1.f + tanhf(0.7978845608028654f * (v + 0.044715f * v3)));
}
__device__ __forceinline__ void cpa16(unsigned dst, const void* src, bool p) {
    int sz = p ? 16 : 0;
    asm volatile("cp.async.cg.shared.global [%0], [%1], 16, %2;\n"
                 :: "r"(dst), "l"(src), "r"(sz));
}
__device__ __forceinline__ void cp_commit() { asm volatile("cp.async.commit_group;\n"); }
__device__ __forceinline__ void ldsm4(unsigned& r0, unsigned& r1, unsigned& r2, unsigned& r3,
                                      unsigned addr) {
    asm volatile("ldmatrix.sync.aligned.m8n8.x4.shared.b16 {%0,%1,%2,%3}, [%4];"
                 : "=r"(r0), "=r"(r1), "=r"(r2), "=r"(r3) : "r"(addr));
}
__device__ __forceinline__ void ldsm4t(unsigned& r0, unsigned& r1, unsigned& r2, unsigned& r3,
                                       unsigned addr) {
    asm volatile("ldmatrix.sync.aligned.m8n8.x4.trans.shared.b16 {%0,%1,%2,%3}, [%4];"
                 : "=r"(r0), "=r"(r1), "=r"(r2), "=r"(r3) : "r"(addr));
}
__device__ __forceinline__ void mma16816(float* d, const unsigned* a, const unsigned* b) {
    asm volatile(
        "mma.sync.aligned.m16n8k16.row.col.f32.f16.f16.f32 "
        "{%0,%1,%2,%3}, {%4,%5,%6,%7}, {%8,%9}, {%0,%1,%2,%3};"
        : "+f"(d[0]), "+f"(d[1]), "+f"(d[2]), "+f"(d[3])
        : "r"(a[0]), "r"(a[1]), "r"(a[2]), "r"(a[3]), "r"(b[0]), "r"(b[1]));
}

// ---------------- utility kernels ----------------
__global__ void init_kernel() {
    int i = threadIdx.x;
    if (i < E_) { g_counts[i] = 0; g_cursor[i] = 0; g_probsum[i] = 0.f; }
}

// vectorized f2h: 2x float4 in -> uint4 (8 halfs) out per iter
__global__ void f2h_kernel(const float4* __restrict__ in, uint4* __restrict__ out,
                           long long n8) {
    for (long long i = blockIdx.x * 256LL + threadIdx.x; i < n8;
         i += (long long)gridDim.x * 256) {
        float4 a = in[2 * i], b = in[2 * i + 1];
        __half2 h0 = __floats2half2_rn(a.x, a.y);
        __half2 h1 = __floats2half2_rn(a.z, a.w);
        __half2 h2 = __floats2half2_rn(b.x, b.y);
        __half2 h3 = __floats2half2_rn(b.z, b.w);
        uint4 o;
        o.x = *(unsigned*)&h0; o.y = *(unsigned*)&h1;
        o.z = *(unsigned*)&h2; o.w = *(unsigned*)&h3;
        out[i] = o;
    }
}

// 4 small weight matrices in one launch (blockIdx.y selects tensor)
__global__ void f2h4_kernel(const float4* __restrict__ a, const float4* __restrict__ b,
                            const float4* __restrict__ c, const float4* __restrict__ d,
                            uint4* __restrict__ oqkv, uint4* __restrict__ oo) {
    const float4* src[4] = { a, b, c, d };
    long long n8 = (long long)D_ * D_ / 8;
    uint4* dst;
    int z = blockIdx.y;
    if (z < 3) dst = oqkv + (size_t)z * n8;
    else       dst = oo;
    const float4* in = src[z];
    for (long long i = blockIdx.x * 256LL + threadIdx.x; i < n8;
         i += (long long)gridDim.x * 256) {
        float4 va = in[2 * i], vb = in[2 * i + 1];
        __half2 h0 = __floats2half2_rn(va.x, va.y);
        __half2 h1 = __floats2half2_rn(va.z, va.w);
        __half2 h2 = __floats2half2_rn(vb.x, vb.y);
        __half2 h3 = __floats2half2_rn(vb.z, vb.w);
        uint4 o;
        o.x = *(unsigned*)&h0; o.y = *(unsigned*)&h1;
        o.z = *(unsigned*)&h2; o.w = *(unsigned*)&h3;
        dst[i] = o;
    }
}

__global__ void rmsnorm_kernel(const float* __restrict__ X, const float* __restrict__ W,
                               float* __restrict__ O, __half* __restrict__ OT) {
    int t = blockIdx.x;
    const float* x = X + (size_t)t * D_;
    float ss = 0.f;
    for (int d = threadIdx.x; d < D_; d += 256) { float v = x[d]; ss += v * v; }
    __shared__ float red[256];
    red[threadIdx.x] = ss; __syncthreads();
    for (int s = 128; s > 0; s >>= 1) {
        if (threadIdx.x < s) red[threadIdx.x] += red[threadIdx.x + s];
        __syncthreads();
    }
    float scale = rsqrtf(red[0] * (1.f / D_) + 1e-6f);
    for (int d = threadIdx.x; d < D_; d += 256) {
        float v = x[d] * scale * W[d];
        if (O)  O[(size_t)t * D_ + d] = v;
        OT[(size_t)t * D_ + d] = __float2half_rn(v);
    }
}

// per-row sum of unnormalized exp -> inverse
__global__ void rowsum_kernel(const __half* __restrict__ P, float* __restrict__ INV) {
    int row = blockIdx.x;                 // bh*S + q
    int q = row & 1023;
    const __half* p = P + (size_t)row * S_;
    int len = q + 1;
    int tid = threadIdx.x;
    __shared__ float red[128];
    float sum = 0.f;
    for (int j = tid; j < len; j += 128) sum += __half2float(p[j]);
    red[tid] = sum; __syncthreads();
    for (int st = 64; st > 0; st >>= 1) {
        if (tid < st) red[tid] += red[tid + st];
        __syncthreads();
    }
    if (tid == 0) INV[row] = 1.f / red[0];
}

__global__ void router_kernel(const float* __restrict__ H, const float* __restrict__ RW) {
    int t = blockIdx.x;
    int tid = threadIdx.x;
    int e = tid >> 5, lane = tid & 31;
    const float* h = H + (size_t)t * D_;
    float p = 0.f;
    for (int d = lane; d < D_; d += 32) p += h[d] * RW[d * E_ + e];
    for (int o = 16; o > 0; o >>= 1) p += __shfl_down_sync(0xffffffff, p, o);
    __shared__ float lg[E_];
    if (lane == 0) lg[e] = p;
    __syncthreads();
    if (tid == 0) {
        float mx = lg[0];
        for (int i = 1; i < E_; i++) mx = fmaxf(mx, lg[i]);
        float pr[E_]; float s = 0.f;
        for (int i = 0; i < E_; i++) { pr[i] = expf(lg[i] - mx); s += pr[i]; }
        float inv = 1.f / s;
        float b1v = -1.f, b2v = -1.f; int b1i = 0, b2i = 0;
        for (int i = 0; i < E_; i++) {
            float v = pr[i] * inv;
            atomicAdd(&g_probsum[i], v);
            if (v > b1v) { b2v = b1v; b2i = b1i; b1v = v; b1i = i; }
            else if (v > b2v) { b2v = v; b2i = i; }
        }
        g_topidx[t * 2] = b1i; g_topidx[t * 2 + 1] = b2i;
        g_topval[t * 2] = b1v; g_topval[t * 2 + 1] = b2v;
        atomicAdd(&g_counts[b1i], 1);
        atomicAdd(&g_counts[b2i], 1);
    }
}

__global__ void scan_kernel() {
    if (threadIdx.x == 0) {
        g_offs[0] = 0;
        for (int e = 0; e < E_; e++) {
            g_offs[e + 1] = g_offs[e] + g_counts[e];
            g_cursor[e] = g_offs[e];
        }
    }
}

__global__ void place_kernel() {
    int t = blockIdx.x * blockDim.x + threadIdx.x;
    if (t >= NTOK) return;
    for (int kk = 0; kk < KSEL; kk++) {
        int e = g_topidx[t * 2 + kk];
        int slot = atomicAdd(&g_cursor[e], 1);
        g_perm[slot] = t;
        g_slotof[t * 2 + kk] = slot;
    }
}

__global__ void combine_kernel(float* __restrict__ out) {
    int idx = blockIdx.x * blockDim.x + threadIdx.x;
    if (idx >= NTOK * D_) return;
    int t = idx >> 10, d = idx & 1023;
    float v = g_x2[idx];
    v += g_topval[t * 2]     * g_y[(size_t)g_slotof[t * 2]     * D_ + d];
    v += g_topval[t * 2 + 1] * g_y[(size_t)g_slotof[t * 2 + 1] * D_ + d];
    out[idx] = v;
}

__global__ void finalize_kernel(float* __restrict__ out) {
    if (threadIdx.x == 0) {
        float loss = 0.f;
        for (int e = 0; e < E_; e++)
            loss += ((float)g_counts[e] / (float)NSLOT) * (g_probsum[e] / (float)NTOK);
        loss *= (float)E_;
        out[(size_t)NTOK * D_] = loss;
        for (int e = 0; e < E_; e++)
            out[(size_t)NTOK * D_ + 1 + e] = (float)g_counts[e];
    }
}

// ---------------- fp16 HMMA GEMM ----------------
// A [M,K] K-major half. B: TB ? [N,K] K-major : [K,N] N-major, half.
// EPI: 0 half store; 1 float store + residual; 2 float store;
//      3 half store of causal-masked exp(v*0.125);
//      4 half store of v * addp[z*S_ + r] (row scale).
// mode: 0 none, 1 causal tile-skip, 2 k-clip.
template <bool TB, int NT, int EPI>
__global__ void __launch_bounds__(128, 2)
hgemm(const __half* __restrict__ A, int lda,
      const __half* __restrict__ B, int ldb,
      void* __restrict__ Cv, int ldc,
      int M, int N, int K,
      long long aO, long long aI, long long bO, long long bI,
      long long cO, long long cI, int zdiv,
      const float* __restrict__ addp, int mode) {
    constexpr int BSTH = NT + 8;
    constexpr int BSZB = TB ? ASZB : (64 * BSTH * 2);
    constexpr int STG  = ASZB + BSZB;
    constexpr int NTW  = NT / 16;
    extern __shared__ __align__(16) unsigned char smraw[];

    int z = blockIdx.z, zo = z / zdiv, zi = z % zdiv;
    A += zo * aO + zi * aI;
    B += zo * bO + zi * bI;

    int m0 = blockIdx.y * 128, n0 = blockIdx.x * NT;
    if (mode == 1 && n0 > m0 + 127) return;
    int Keff = (mode == 2) ? min(K, m0 + 128) : K;
    int KT = Keff / BKH;

    int tid = threadIdx.x, wid = tid >> 5, lane = tid & 31;
    int warpM = wid & 1, warpN = wid >> 1;
    int g = lane >> 2, t = lane & 3;
    unsigned smb = (unsigned)__cvta_generic_to_shared(smraw);

    bool av = (m0 + tid) < M;
    const __half* aptr = A + (size_t)(av ? (m0 + tid) : 0) * lda;
    const __half* bptr = nullptr;
    bool bv = true;
    if (TB) {
        bv = (n0 + tid) < N;
        bptr = B + (size_t)(bv ? (n0 + tid) : 0) * ldb;
    }

    float acc[4][NTW][4];
#pragma unroll
    for (int mt = 0; mt < 4; mt++)
#pragma unroll
        for (int nt = 0; nt < NTW; nt++)
#pragma unroll
            for (int r = 0; r < 4; r++) acc[mt][nt][r] = 0.f;

    auto issue = [&](int lt) {
        int s = lt & 1;
        unsigned ab = smb + (unsigned)s * STG;
        const __half* as = aptr + lt * BKH;
        unsigned arow = ab + (unsigned)tid * (ASTH * 2);
#pragma unroll
        for (int c = 0; c < 8; c++)
            cpa16(arow + c * 16, as + c * 8, av);
        unsigned bb = ab + ASZB;
        if (TB) {
            const __half* bs = bptr + lt * BKH;
            unsigned br = bb + (unsigned)tid * (ASTH * 2);
#pragma unroll
            for (int c = 0; c < 8; c++)
                cpa16(br + c * 16, bs + c * 8, bv);
        } else {
            int row = tid >> 1;
            int cb = (tid & 1) * (NT / 16);
            const __half* bs = B + (size_t)(lt * BKH + row) * ldb + n0;
            unsigned br = bb + (unsigned)row * (BSTH * 2);
#pragma unroll
            for (int j = 0; j < NT / 16; j++)
                cpa16(br + (cb + j) * 16, bs + (cb + j) * 8, true);
        }
        cp_commit();
    };

    issue(0);
    for (int kt = 0; kt < KT; kt++) {
        int b = kt & 1;
        if (kt + 1 < KT) {
            issue(kt + 1);
            asm volatile("cp.async.wait_group 1;\n");
        } else {
            asm volatile("cp.async.wait_group 0;\n");
        }
        __syncthreads();

        unsigned aBase = smb + (unsigned)b * STG;
        unsigned bBase = aBase + ASZB;
#pragma unroll
        for (int ks = 0; ks < 4; ks++) {
            unsigned afr[4][4];
#pragma unroll
            for (int mt = 0; mt < 4; mt++) {
                int row = warpM * 64 + mt * 16 + (lane & 15);
                int kh = ks * 16 + ((lane >> 4) << 3);
                ldsm4(afr[mt][0], afr[mt][1], afr[mt][2], afr[mt][3],
                      aBase + (unsigned)(row * ASTH + kh) * 2);
            }
            unsigned bfr[NTW][2];
#pragma unroll
            for (int ntp = 0; ntp < NTW / 2; ntp++) {
                unsigned r0, r1, r2, r3;
                if (TB) {
                    int row = warpN * 64 + ntp * 16 + (lane & 15);
                    int kh = ks * 16 + ((lane >> 4) << 3);
                    ldsm4(r0, r1, r2, r3, bBase + (unsigned)(row * ASTH + kh) * 2);
                    bfr[2 * ntp][0] = r0; bfr[2 * ntp + 1][0] = r1;
                    bfr[2 * ntp][1] = r2; bfr[2 * ntp + 1][1] = r3;
                } else {
                    int krow = ks * 16 + (lane & 15);
                    int col = warpN * (NT / 2) + ntp * 16 + ((lane >> 4) << 3);
                    ldsm4t(r0, r1, r2, r3, bBase + (unsigned)(krow * BSTH + col) * 2);
                    bfr[2 * ntp][0] = r0; bfr[2 * ntp][1] = r1;
                    bfr[2 * ntp + 1][0] = r2; bfr[2 * ntp + 1][1] = r3;
                }
            }
#pragma unroll
            for (int mt = 0; mt < 4; mt++)
#pragma unroll
                for (int nt = 0; nt < NTW; nt++)
                    mma16816(acc[mt][nt], afr[mt], bfr[nt]);
        }
        __syncthreads();
    }

    // epilogue
#pragma unroll
    for (int mt = 0; mt < 4; mt++) {
#pragma unroll
        for (int nt = 0; nt < NTW; nt++) {
            int row = m0 + warpM * 64 + mt * 16 + g;
            int col = n0 + warpN * (NT / 2) + nt * 8 + 2 * t;
#pragma unroll
            for (int half_ = 0; half_ < 2; half_++) {
                int r = row + half_ * 8;
                if (r < M && col < N) {
                    float v0 = acc[mt][nt][half_ * 2 + 0];
                    float v1 = acc[mt][nt][half_ * 2 + 1];
                    size_t cidx = (size_t)(zo * cO + zi * cI) + (size_t)r * ldc + col;
                    if (EPI == 0) {
                        *(__half2*)((__half*)Cv + cidx) = __floats2half2_rn(v0, v1);
                    } else if (EPI == 1) {
                        float2 ad = *(const float2*)(addp + (size_t)r * ldc + col);
                        float2 o; o.x = v0 + ad.x; o.y = v1 + ad.y;
                        *(float2*)((float*)Cv + cidx) = o;
                    } else if (EPI == 2) {
                        float2 o; o.x = v0; o.y = v1;
                        *(float2*)((float*)Cv + cidx) = o;
                    } else if (EPI == 3) {
                        float e0 = (col     <= r) ? __expf(v0 * 0.125f) : 0.f;
                        float e1 = (col + 1 <= r) ? __expf(v1 * 0.125f) : 0.f;
                        *(__half2*)((__half*)Cv + cidx) = __floats2half2_rn(e0, e1);
                    } else {  // EPI == 4
                        float sc = addp[(size_t)z * S_ + r];
                        *(__half2*)((__half*)Cv + cidx) = __floats2half2_rn(v0 * sc, v1 * sc);
                    }
                }
            }
        }
    }
}

// ---------------- grouped MoE fp16 GEMMs: 256 thr, 128x256 tiles ----------
template <int EP>
__global__ void __launch_bounds__(256, 1)
moe_hgemm(const __half* __restrict__ H, const __half* __restrict__ W,
          const float* __restrict__ Bias, int Kdim, int Ndim) {
    constexpr int BSTH = 264;
    constexpr int BSZB = 64 * BSTH * 2;
    constexpr int STG  = ASZB + BSZB;
    extern __shared__ __align__(16) unsigned char smraw[];

    int e = blockIdx.z;
    int base = g_offs[e], cnt = g_offs[e + 1] - base;
    int m0 = blockIdx.y * 128;
    if (m0 >= cnt) return;
    int n0 = blockIdx.x * 256;
    const __half* Bmat = W + (size_t)e * (size_t)Kdim * Ndim;

    int tid = threadIdx.x, wid = tid >> 5, lane = tid & 31;
    int warpM = wid & 1, warpN = wid >> 1;
    int g = lane >> 2, t = lane & 3;
    unsigned smb = (unsigned)__cvta_generic_to_shared(smraw);
    float* sBias = (float*)smraw;
    unsigned tb0 = smb + 1024;

    sBias[tid] = Bias[(size_t)e * Ndim + n0 + tid];

    int arow_i = tid >> 1;
    bool av = (m0 + arow_i) < cnt;
    const __half* aptr;
    if (EP == 1) aptr = H + (size_t)(av ? g_perm[base + m0 + arow_i] : 0) * Kdim;
    else         aptr = g_act + (size_t)(av ? (base + m0 + arow_i) : 0) * Kdim;
    int ahalf = (tid & 1) * 32;

    int brow = tid >> 2, bq = tid & 3;

    float acc[4][8][4];
#pragma unroll
    for (int mt = 0; mt < 4; mt++)
#pragma unroll
        for (int nt = 0; nt < 8; nt++)
#pragma unroll
            for (int r = 0; r < 4; r++) acc[mt][nt][r] = 0.f;

    int KT = Kdim / BKH;

    auto issue = [&](int lt) {
        int s = lt & 1;
        unsigned ab = tb0 + (unsigned)s * STG;
        const __half* as = aptr + lt * BKH + ahalf;
        unsigned ar = ab + (unsigned)arow_i * (ASTH * 2) + (unsigned)(tid & 1) * 64;
#pragma unroll
        for (int c = 0; c < 4; c++)
            cpa16(ar + c * 16, as + c * 8, av);
        unsigned bb = ab + ASZB;
        const __half* bs = Bmat + (size_t)(lt * BKH + brow) * Ndim + n0 + bq * 64;
        unsigned br = bb + (unsigned)brow * (BSTH * 2) + (unsigned)bq * 128;
#pragma unroll
        for (int c = 0; c < 8; c++)
            cpa16(br + c * 16, bs + c * 8, true);
        cp_commit();
    };

    issue(0);
    for (int kt = 0; kt < KT; kt++) {
        int b = kt & 1;
        if (kt + 1 < KT) {
            issue(kt + 1);
            asm volatile("cp.async.wait_group 1;\n");
        } else {
            asm volatile("cp.async.wait_group 0;\n");
        }
        __syncthreads();

        unsigned aBase = tb0 + (unsigned)b * STG;
        unsigned bBase = aBase + ASZB;
#pragma unroll
        for (int ks = 0; ks < 4; ks++) {
            unsigned afr[4][4];
#pragma unroll
            for (int mt = 0; mt < 4; mt++) {
                int row = warpM * 64 + mt * 16 + (lane & 15);
                int kh = ks * 16 + ((lane >> 4) << 3);
                ldsm4(afr[mt][0], afr[mt][1], afr[mt][2], afr[mt][3],
                      aBase + (unsigned)(row * ASTH + kh) * 2);
            }
            unsigned bfr[8][2];
#pragma unroll
            for (int ntp = 0; ntp < 4; ntp++) {
                unsigned r0, r1, r2, r3;
                int krow = ks * 16 + (lane & 15);
                int col = warpN * 64 + ntp * 16 + ((lane >> 4) << 3);
                ldsm4t(r0, r1, r2, r3, bBase + (unsigned)(krow * BSTH + col) * 2);
                bfr[2 * ntp][0] = r0; bfr[2 * ntp][1] = r1;
                bfr[2 * ntp + 1][0] = r2; bfr[2 * ntp + 1][1] = r3;
            }
#pragma unroll
            for (int mt = 0; mt < 4; mt++)
#pragma unroll
                for (int nt = 0; nt < 8; nt++)
                    mma16816(acc[mt][nt], afr[mt], bfr[nt]);
        }
        __syncthreads();
    }

#pragma unroll
    for (int mt = 0; mt < 4; mt++) {
#pragma unroll
        for (int nt = 0; nt < 8; nt++) {
            int rr = m0 + warpM * 64 + mt * 16 + g;
            int colL = warpN * 64 + nt * 8 + 2 * t;
            int col = n0 + colL;
#pragma unroll
            for (int half_ = 0; half_ < 2; half_++) {
                int r = rr + half_ * 8;
                if (r < cnt) {
                    float v0 = acc[mt][nt][half_ * 2 + 0] + sBias[colL];
                    float v1 = acc[mt][nt][half_ * 2 + 1] + sBias[colL + 1];
                    if (EP == 1) {
                        *(__half2*)(g_act + (size_t)(base + r) * FF_ + col) =
                            __floats2half2_rn(gelu_tanh(v0), gelu_tanh(v1));
                    } else {
                        float2 o; o.x = v0; o.y = v1;
                        *(float2*)(g_y + (size_t)(base + r) * D_ + col) = o;
                    }
                }
            }
        }
    }
}

// ---------------- launch ----------------
#define SMEM_NF128 (2 * (ASZB + 64 * 136 * 2))
#define SMEM_T128  (2 * (ASZB + ASZB))
#define SMEM_NF64  (2 * (ASZB + 64 * 72 * 2))
#define SMEM_MOE   (1024 + 2 * (ASZB + 64 * 264 * 2))

extern "C" void kernel_launch(void* const* d_in, const int* in_sizes, int n_in,
                              void* d_out, int out_size) {
    const float* x   = (const float*)d_in[0];
    const float* anw = (const float*)d_in[1];
    const float* wq  = (const float*)d_in[2];
    const float* wk  = (const float*)d_in[3];
    const float* wv  = (const float*)d_in[4];
    const float* wo  = (const float*)d_in[5];
    const float* mnw = (const float*)d_in[6];
    const float* rw  = (const float*)d_in[7];
    const float* w1  = (const float*)d_in[8];
    const float* b1  = (const float*)d_in[9];
    const float* w2  = (const float*)d_in[10];
    const float* b2  = (const float*)d_in[11];
    float* out = (float*)d_out;

    cudaFuncSetAttribute(hgemm<false, 128, 0>, cudaFuncAttributeMaxDynamicSharedMemorySize, SMEM_NF128);
    cudaFuncSetAttribute(hgemm<false, 128, 1>, cudaFuncAttributeMaxDynamicSharedMemorySize, SMEM_NF128);
    cudaFuncSetAttribute(hgemm<true, 128, 3>,  cudaFuncAttributeMaxDynamicSharedMemorySize, SMEM_T128);
    cudaFuncSetAttribute(hgemm<false, 64, 4>,  cudaFuncAttributeMaxDynamicSharedMemorySize, SMEM_NF64);
    cudaFuncSetAttribute(moe_hgemm<1>,         cudaFuncAttributeMaxDynamicSharedMemorySize, SMEM_MOE);
    cudaFuncSetAttribute(moe_hgemm<2>,         cudaFuncAttributeMaxDynamicSharedMemorySize, SMEM_MOE);

    __half *xn, *wqkvh, *woh, *w1h, *w2h, *qkv, *probsH, *ao, *htf;
    float *x2, *h, *invs;
    cudaGetSymbolAddress((void**)&xn,     g_xn);
    cudaGetSymbolAddress((void**)&wqkvh,  g_wqkvh);
    cudaGetSymbolAddress((void**)&woh,    g_woh);
    cudaGetSymbolAddress((void**)&w1h,    g_w1h);
    cudaGetSymbolAddress((void**)&w2h,    g_w2h);
    cudaGetSymbolAddress((void**)&qkv,    g_qkv);
    cudaGetSymbolAddress((void**)&probsH, g_probsH);
    cudaGetSymbolAddress((void**)&invs,   g_invsum);
    cudaGetSymbolAddress((void**)&ao,     g_attnout);
    cudaGetSymbolAddress((void**)&x2,     g_x2);
    cudaGetSymbolAddress((void**)&h,      g_h);
    cudaGetSymbolAddress((void**)&htf,    g_htf);

    const __half* q = qkv;
    const __half* k = qkv + (size_t)NTOK * D_;
    const __half* v = qkv + 2 * (size_t)NTOK * D_;

    // side stream for big weight conversion, forked off the capture stream.
    // streams/events are host objects (no device memory); intentionally not
    // destroyed here because capture is still active when we'd destroy them.
    cudaStream_t s2;
    cudaEvent_t evFork, evJoin;
    cudaStreamCreateWithFlags(&s2, cudaStreamNonBlocking);
    cudaEventCreateWithFlags(&evFork, cudaEventDisableTiming);
    cudaEventCreateWithFlags(&evJoin, cudaEventDisableTiming);

    init_kernel<<<1, 32>>>();
    cudaEventRecord(evFork, 0);
    cudaStreamWaitEvent(s2, evFork, 0);

    // side stream: big MoE weight conversions (~400 MB) overlapped with attention
    f2h_kernel<<<4096, 256, 0, s2>>>((const float4*)w1, (uint4*)w1h, (long long)E_ * D_ * FF_ / 8);
    f2h_kernel<<<4096, 256, 0, s2>>>((const float4*)w2, (uint4*)w2h, (long long)E_ * FF_ * D_ / 8);
    cudaEventRecord(evJoin, s2);

    // main stream: small weight conversions + attention chain
    f2h4_kernel<<<dim3(256, 4), 256>>>((const float4*)wq, (const float4*)wk,
                                       (const float4*)wv, (const float4*)wo,
                                       (uint4*)wqkvh, (uint4*)woh);
    rmsnorm_kernel<<<NTOK, 256>>>(x, anw, nullptr, xn);

    hgemm<false, 128, 0><<<dim3(8, 16, 3), 128, SMEM_NF128>>>(
        xn, D_, wqkvh, D_, qkv, D_, NTOK, D_, D_,
        0, 0, (long long)D_ * D_, 0, (long long)NTOK * D_, 0, 1, nullptr, 0);

    {
        long long sSD = (long long)S_ * D_, sSS = (long long)S_ * S_;
        hgemm<true, 128, 3><<<dim3(8, 8, BB_ * NH_), 128, SMEM_T128>>>(
            q, D_, k, D_, probsH, S_, S_, S_, DH_,
            sSD, DH_, sSD, DH_, NH_ * sSS, sSS, NH_, nullptr, 1);
    }

    rowsum_kernel<<<BB_ * NH_ * S_, 128>>>(probsH, invs);

    {
        long long sSD = (long long)S_ * D_, sSS = (long long)S_ * S_;
        hgemm<false, 64, 4><<<dim3(1, 8, BB_ * NH_), 128, SMEM_NF64>>>(
            probsH, S_, v, D_, ao, D_, S_, DH_, S_,
            NH_ * sSS, sSS, sSD, DH_, sSD, DH_, NH_, invs, 2);
    }

    hgemm<false, 128, 1><<<dim3(8, 16, 1), 128, SMEM_NF128>>>(
        ao, D_, woh, D_, x2, D_, NTOK, D_, D_,
        0, 0, 0, 0, 0, 0, 1, x, 0);

    rmsnorm_kernel<<<NTOK, 256>>>(x2, mnw, h, htf);
    router_kernel<<<NTOK, 256>>>(h, rw);
    scan_kernel<<<1, 1>>>();
    place_kernel<<<(NTOK + 255) / 256, 256>>>();

    // join: MoE needs converted w1/w2
    cudaStreamWaitEvent(0, evJoin, 0);

    moe_hgemm<1><<<dim3(FF_ / 256, NSLOT / 128, E_), 256, SMEM_MOE>>>(htf, w1h, b1, D_, FF_);
    moe_hgemm<2><<<dim3(D_ / 256, NSLOT / 128, E_), 256, SMEM_MOE>>>(nullptr, w2h, b2, FF_, D_);

    combine_kernel<<<(NTOK * D_ + 255) / 256, 256>>>(out);
    finalize_kernel<<<1, 32>>>(out);
}

// round 11
// speedup vs baseline: 1.5168x; 1.0053x over previous
#include <cuda_runtime.h>
#include <cuda_fp16.h>
#include <math.h>
#include <stdint.h>

#define D_    1024
#define S_    1024
#define BB_   2
#define NTOK  2048
#define NH_   16
#define DH_   64
#define E_    8
#define KSEL  2
#define FF_   4096
#define NSLOT 4096

#define BKH   64            // K halfs per stage (128B)
#define ASTH  72            // A smem row stride (halfs)
#define ASZB  (128*ASTH*2)  // 18432 B
#define NSTG  3             // pipeline stages

// ---------------- static scratch ----------------
__device__ __half g_xn[NTOK * D_];
__device__ __half g_wqkvh[3 * D_ * D_];
__device__ __half g_woh[D_ * D_];
__device__ __half g_w1h[(size_t)E_ * D_ * FF_];
__device__ __half g_w2h[(size_t)E_ * FF_ * D_];
__device__ __half g_qkv[3 * NTOK * D_];
__device__ __half g_probsH[(size_t)BB_ * NH_ * S_ * S_];   // unnormalized exp
__device__ float  g_invsum[BB_ * NH_ * S_];
__device__ __half g_attnout[NTOK * D_];
__device__ float  g_x2[NTOK * D_];
__device__ float  g_h[NTOK * D_];
__device__ __half g_htf[NTOK * D_];
__device__ __half g_act[(size_t)NSLOT * FF_];
__device__ float  g_y[(size_t)NSLOT * D_];
__device__ float g_topval[NTOK * KSEL];
__device__ int   g_topidx[NTOK * KSEL];
__device__ int   g_slotof[NTOK * KSEL];
__device__ int   g_perm[NSLOT];
__device__ int   g_counts[E_];
__device__ int   g_offs[E_ + 1];
__device__ int   g_cursor[E_];
__device__ float g_probsum[E_];

// ---------------- helpers ----------------
__device__ __forceinline__ float gelu_tanh(float v) {
    float v3 = v * v * v;
    return 0.5f * v * (1.f + tanhf(0.7978845608028654f * (v + 0.044715f * v3)));
}
__device__ __forceinline__ void cpa16(unsigned dst, const void* src, bool p) {
    int sz = p ? 16 : 0;
    asm volatile("cp.async.cg.shared.global [%0], [%1], 16, %2;\n"
                 :: "r"(dst), "l"(src), "r"(sz));
}
__device__ __forceinline__ void cp_commit() { asm volatile("cp.async.commit_group;\n"); }
__device__ __forceinline__ void ldsm4(unsigned& r0, unsigned& r1, unsigned& r2, unsigned& r3,
                                      unsigned addr) {
    asm volatile("ldmatrix.sync.aligned.m8n8.x4.shared.b16 {%0,%1,%2,%3}, [%4];"
                 : "=r"(r0), "=r"(r1), "=r"(r2), "=r"(r3) : "r"(addr));
}
__device__ __forceinline__ void ldsm4t(unsigned& r0, unsigned& r1, unsigned& r2, unsigned& r3,
                                       unsigned addr) {
    asm volatile("ldmatrix.sync.aligned.m8n8.x4.trans.shared.b16 {%0,%1,%2,%3}, [%4];"
                 : "=r"(r0), "=r"(r1), "=r"(r2), "=r"(r3) : "r"(addr));
}
__device__ __forceinline__ void mma16816(float* d, const unsigned* a, const unsigned* b) {
    asm volatile(
        "mma.sync.aligned.m16n8k16.row.col.f32.f16.f16.f32 "
        "{%0,%1,%2,%3}, {%4,%5,%6,%7}, {%8,%9}, {%0,%1,%2,%3};"
        : "+f"(d[0]), "+f"(d[1]), "+f"(d[2]), "+f"(d[3])
        : "r"(a[0]), "r"(a[1]), "r"(a[2]), "r"(a[3]), "r"(b[0]), "r"(b[1]));
}

// ---------------- utility kernels ----------------
__global__ void init_kernel() {
    int i = threadIdx.x;
    if (i < E_) { g_counts[i] = 0; g_cursor[i] = 0; g_probsum[i] = 0.f; }
}

__global__ void f2h_kernel(const float4* __restrict__ in, uint4* __restrict__ out,
                           long long n8) {
    for (long long i = blockIdx.x * 256LL + threadIdx.x; i < n8;
         i += (long long)gridDim.x * 256) {
        float4 a = in[2 * i], b = in[2 * i + 1];
        __half2 h0 = __floats2half2_rn(a.x, a.y);
        __half2 h1 = __floats2half2_rn(a.z, a.w);
        __half2 h2 = __floats2half2_rn(b.x, b.y);
        __half2 h3 = __floats2half2_rn(b.z, b.w);
        uint4 o;
        o.x = *(unsigned*)&h0; o.y = *(unsigned*)&h1;
        o.z = *(unsigned*)&h2; o.w = *(unsigned*)&h3;
        out[i] = o;
    }
}

__global__ void f2h4_kernel(const float4* __restrict__ a, const float4* __restrict__ b,
                            const float4* __restrict__ c, const float4* __restrict__ d,
                            uint4* __restrict__ oqkv, uint4* __restrict__ oo) {
    const float4* src[4] = { a, b, c, d };
    long long n8 = (long long)D_ * D_ / 8;
    uint4* dst;
    int z = blockIdx.y;
    if (z < 3) dst = oqkv + (size_t)z * n8;
    else       dst = oo;
    const float4* in = src[z];
    for (long long i = blockIdx.x * 256LL + threadIdx.x; i < n8;
         i += (long long)gridDim.x * 256) {
        float4 va = in[2 * i], vb = in[2 * i + 1];
        __half2 h0 = __floats2half2_rn(va.x, va.y);
        __half2 h1 = __floats2half2_rn(va.z, va.w);
        __half2 h2 = __floats2half2_rn(vb.x, vb.y);
        __half2 h3 = __floats2half2_rn(vb.z, vb.w);
        uint4 o;
        o.x = *(unsigned*)&h0; o.y = *(unsigned*)&h1;
        o.z = *(unsigned*)&h2; o.w = *(unsigned*)&h3;
        dst[i] = o;
    }
}

__global__ void rmsnorm_kernel(const float* __restrict__ X, const float* __restrict__ W,
                               float* __restrict__ O, __half* __restrict__ OT) {
    int t = blockIdx.x;
    const float* x = X + (size_t)t * D_;
    float ss = 0.f;
    for (int d = threadIdx.x; d < D_; d += 256) { float v = x[d]; ss += v * v; }
    __shared__ float red[256];
    red[threadIdx.x] = ss; __syncthreads();
    for (int s = 128; s > 0; s >>= 1) {
        if (threadIdx.x < s) red[threadIdx.x] += red[threadIdx.x + s];
        __syncthreads();
    }
    float scale = rsqrtf(red[0] * (1.f / D_) + 1e-6f);
    for (int d = threadIdx.x; d < D_; d += 256) {
        float v = x[d] * scale * W[d];
        if (O)  O[(size_t)t * D_ + d] = v;
        OT[(size_t)t * D_ + d] = __float2half_rn(v);
    }
}

__global__ void rowsum_kernel(const __half* __restrict__ P, float* __restrict__ INV) {
    int row = blockIdx.x;
    int q = row & 1023;
    const __half* p = P + (size_t)row * S_;
    int len = q + 1;
    int tid = threadIdx.x;
    __shared__ float red[128];
    float sum = 0.f;
    for (int j = tid; j < len; j += 128) sum += __half2float(p[j]);
    red[tid] = sum; __syncthreads();
    for (int st = 64; st > 0; st >>= 1) {
        if (tid < st) red[tid] += red[tid + st];
        __syncthreads();
    }
    if (tid == 0) INV[row] = 1.f / red[0];
}

__global__ void router_kernel(const float* __restrict__ H, const float* __restrict__ RW) {
    int t = blockIdx.x;
    int tid = threadIdx.x;
    int e = tid >> 5, lane = tid & 31;
    const float* h = H + (size_t)t * D_;
    float p = 0.f;
    for (int d = lane; d < D_; d += 32) p += h[d] * RW[d * E_ + e];
    for (int o = 16; o > 0; o >>= 1) p += __shfl_down_sync(0xffffffff, p, o);
    __shared__ float lg[E_];
    if (lane == 0) lg[e] = p;
    __syncthreads();
    if (tid == 0) {
        float mx = lg[0];
        for (int i = 1; i < E_; i++) mx = fmaxf(mx, lg[i]);
        float pr[E_]; float s = 0.f;
        for (int i = 0; i < E_; i++) { pr[i] = expf(lg[i] - mx); s += pr[i]; }
        float inv = 1.f / s;
        float b1v = -1.f, b2v = -1.f; int b1i = 0, b2i = 0;
        for (int i = 0; i < E_; i++) {
            float v = pr[i] * inv;
            atomicAdd(&g_probsum[i], v);
            if (v > b1v) { b2v = b1v; b2i = b1i; b1v = v; b1i = i; }
            else if (v > b2v) { b2v = v; b2i = i; }
        }
        g_topidx[t * 2] = b1i; g_topidx[t * 2 + 1] = b2i;
        g_topval[t * 2] = b1v; g_topval[t * 2 + 1] = b2v;
        atomicAdd(&g_counts[b1i], 1);
        atomicAdd(&g_counts[b2i], 1);
    }
}

__global__ void scan_kernel() {
    if (threadIdx.x == 0) {
        g_offs[0] = 0;
        for (int e = 0; e < E_; e++) {
            g_offs[e + 1] = g_offs[e] + g_counts[e];
            g_cursor[e] = g_offs[e];
        }
    }
}

__global__ void place_kernel() {
    int t = blockIdx.x * blockDim.x + threadIdx.x;
    if (t >= NTOK) return;
    for (int kk = 0; kk < KSEL; kk++) {
        int e = g_topidx[t * 2 + kk];
        int slot = atomicAdd(&g_cursor[e], 1);
        g_perm[slot] = t;
        g_slotof[t * 2 + kk] = slot;
    }
}

__global__ void combine_kernel(float* __restrict__ out) {
    int idx = blockIdx.x * blockDim.x + threadIdx.x;
    if (idx >= NTOK * D_) return;
    int t = idx >> 10, d = idx & 1023;
    float v = g_x2[idx];
    v += g_topval[t * 2]     * g_y[(size_t)g_slotof[t * 2]     * D_ + d];
    v += g_topval[t * 2 + 1] * g_y[(size_t)g_slotof[t * 2 + 1] * D_ + d];
    out[idx] = v;
}

__global__ void finalize_kernel(float* __restrict__ out) {
    if (threadIdx.x == 0) {
        float loss = 0.f;
        for (int e = 0; e < E_; e++)
            loss += ((float)g_counts[e] / (float)NSLOT) * (g_probsum[e] / (float)NTOK);
        loss *= (float)E_;
        out[(size_t)NTOK * D_] = loss;
        for (int e = 0; e < E_; e++)
            out[(size_t)NTOK * D_ + 1 + e] = (float)g_counts[e];
    }
}

// ---------------- fp16 HMMA GEMM (3-stage cp.async pipeline) ----------------
// A [M,K] K-major half. B: TB ? [N,K] K-major : [K,N] N-major, half.
// EPI: 0 half store; 1 float store + residual; 2 float store;
//      3 half store of causal-masked exp(v*0.125);
//      4 half store of v * addp[z*S_ + r] (row scale).
// mode: 0 none, 1 causal tile-skip, 2 k-clip.
template <bool TB, int NT, int EPI>
__global__ void __launch_bounds__(128, 2)
hgemm(const __half* __restrict__ A, int lda,
      const __half* __restrict__ B, int ldb,
      void* __restrict__ Cv, int ldc,
      int M, int N, int K,
      long long aO, long long aI, long long bO, long long bI,
      long long cO, long long cI, int zdiv,
      const float* __restrict__ addp, int mode) {
    constexpr int BSTH = NT + 8;
    constexpr int BSZB = TB ? ASZB : (64 * BSTH * 2);
    constexpr int STG  = ASZB + BSZB;
    constexpr int NTW  = NT / 16;
    extern __shared__ __align__(16) unsigned char smraw[];

    int z = blockIdx.z, zo = z / zdiv, zi = z % zdiv;
    A += zo * aO + zi * aI;
    B += zo * bO + zi * bI;

    int m0 = blockIdx.y * 128, n0 = blockIdx.x * NT;
    if (mode == 1 && n0 > m0 + 127) return;
    int Keff = (mode == 2) ? min(K, m0 + 128) : K;
    int KT = Keff / BKH;

    int tid = threadIdx.x, wid = tid >> 5, lane = tid & 31;
    int warpM = wid & 1, warpN = wid >> 1;
    int g = lane >> 2, t = lane & 3;
    unsigned smb = (unsigned)__cvta_generic_to_shared(smraw);

    bool av = (m0 + tid) < M;
    const __half* aptr = A + (size_t)(av ? (m0 + tid) : 0) * lda;
    const __half* bptr = nullptr;
    bool bv = true;
    if (TB) {
        bv = (n0 + tid) < N;
        bptr = B + (size_t)(bv ? (n0 + tid) : 0) * ldb;
    }

    float acc[4][NTW][4];
#pragma unroll
    for (int mt = 0; mt < 4; mt++)
#pragma unroll
        for (int nt = 0; nt < NTW; nt++)
#pragma unroll
            for (int r = 0; r < 4; r++) acc[mt][nt][r] = 0.f;

    auto issue = [&](int lt) {
        int s = lt % NSTG;
        unsigned ab = smb + (unsigned)s * STG;
        const __half* as = aptr + lt * BKH;
        unsigned arow = ab + (unsigned)tid * (ASTH * 2);
#pragma unroll
        for (int c = 0; c < 8; c++)
            cpa16(arow + c * 16, as + c * 8, av);
        unsigned bb = ab + ASZB;
        if (TB) {
            const __half* bs = bptr + lt * BKH;
            unsigned br = bb + (unsigned)tid * (ASTH * 2);
#pragma unroll
            for (int c = 0; c < 8; c++)
                cpa16(br + c * 16, bs + c * 8, bv);
        } else {
            int row = tid >> 1;
            int cb = (tid & 1) * (NT / 16);
            const __half* bs = B + (size_t)(lt * BKH + row) * ldb + n0;
            unsigned br = bb + (unsigned)row * (BSTH * 2);
#pragma unroll
            for (int j = 0; j < NT / 16; j++)
                cpa16(br + (cb + j) * 16, bs + (cb + j) * 8, true);
        }
        cp_commit();
    };

    // prefill NSTG stages (empty commits keep group accounting exact)
#pragma unroll
    for (int i = 0; i < NSTG; i++) {
        if (i < KT) issue(i); else cp_commit();
    }

    for (int kt = 0; kt < KT; kt++) {
        int b = kt % NSTG;
        asm volatile("cp.async.wait_group %0;\n" :: "n"(NSTG - 1));
        __syncthreads();

        unsigned aBase = smb + (unsigned)b * STG;
        unsigned bBase = aBase + ASZB;
#pragma unroll
        for (int ks = 0; ks < 4; ks++) {
            unsigned afr[4][4];
#pragma unroll
            for (int mt = 0; mt < 4; mt++) {
                int row = warpM * 64 + mt * 16 + (lane & 15);
                int kh = ks * 16 + ((lane >> 4) << 3);
                ldsm4(afr[mt][0], afr[mt][1], afr[mt][2], afr[mt][3],
                      aBase + (unsigned)(row * ASTH + kh) * 2);
            }
            unsigned bfr[NTW][2];
#pragma unroll
            for (int ntp = 0; ntp < NTW / 2; ntp++) {
                unsigned r0, r1, r2, r3;
                if (TB) {
                    int row = warpN * 64 + ntp * 16 + (lane & 15);
                    int kh = ks * 16 + ((lane >> 4) << 3);
                    ldsm4(r0, r1, r2, r3, bBase + (unsigned)(row * ASTH + kh) * 2);
                    bfr[2 * ntp][0] = r0; bfr[2 * ntp + 1][0] = r1;
                    bfr[2 * ntp][1] = r2; bfr[2 * ntp + 1][1] = r3;
                } else {
                    int krow = ks * 16 + (lane & 15);
                    int col = warpN * (NT / 2) + ntp * 16 + ((lane >> 4) << 3);
                    ldsm4t(r0, r1, r2, r3, bBase + (unsigned)(krow * BSTH + col) * 2);
                    bfr[2 * ntp][0] = r0; bfr[2 * ntp][1] = r1;
                    bfr[2 * ntp + 1][0] = r2; bfr[2 * ntp + 1][1] = r3;
                }
            }
#pragma unroll
            for (int mt = 0; mt < 4; mt++)
#pragma unroll
                for (int nt = 0; nt < NTW; nt++)
                    mma16816(acc[mt][nt], afr[mt], bfr[nt]);
        }
        __syncthreads();
        if (kt + NSTG < KT) issue(kt + NSTG); else cp_commit();
    }

    // epilogue
#pragma unroll
    for (int mt = 0; mt < 4; mt++) {
#pragma unroll
        for (int nt = 0; nt < NTW; nt++) {
            int row = m0 + warpM * 64 + mt * 16 + g;
            int col = n0 + warpN * (NT / 2) + nt * 8 + 2 * t;
#pragma unroll
            for (int half_ = 0; half_ < 2; half_++) {
                int r = row + half_ * 8;
                if (r < M && col < N) {
                    float v0 = acc[mt][nt][half_ * 2 + 0];
                    float v1 = acc[mt][nt][half_ * 2 + 1];
                    size_t cidx = (size_t)(zo * cO + zi * cI) + (size_t)r * ldc + col;
                    if (EPI == 0) {
                        *(__half2*)((__half*)Cv + cidx) = __floats2half2_rn(v0, v1);
                    } else if (EPI == 1) {
                        float2 ad = *(const float2*)(addp + (size_t)r * ldc + col);
                        float2 o; o.x = v0 + ad.x; o.y = v1 + ad.y;
                        *(float2*)((float*)Cv + cidx) = o;
                    } else if (EPI == 2) {
                        float2 o; o.x = v0; o.y = v1;
                        *(float2*)((float*)Cv + cidx) = o;
                    } else if (EPI == 3) {
                        float e0 = (col     <= r) ? __expf(v0 * 0.125f) : 0.f;
                        float e1 = (col + 1 <= r) ? __expf(v1 * 0.125f) : 0.f;
                        *(__half2*)((__half*)Cv + cidx) = __floats2half2_rn(e0, e1);
                    } else {  // EPI == 4
                        float sc = addp[(size_t)z * S_ + r];
                        *(__half2*)((__half*)Cv + cidx) = __floats2half2_rn(v0 * sc, v1 * sc);
                    }
                }
            }
        }
    }
}

// ---------------- grouped MoE fp16 GEMMs: 256 thr, 128x256, 3-stage -------
template <int EP>
__global__ void __launch_bounds__(256, 1)
moe_hgemm(const __half* __restrict__ H, const __half* __restrict__ W,
          const float* __restrict__ Bias, int Kdim, int Ndim) {
    constexpr int BSTH = 264;
    constexpr int BSZB = 64 * BSTH * 2;
    constexpr int STG  = ASZB + BSZB;
    extern __shared__ __align__(16) unsigned char smraw[];

    int e = blockIdx.z;
    int base = g_offs[e], cnt = g_offs[e + 1] - base;
    int m0 = blockIdx.y * 128;
    if (m0 >= cnt) return;
    int n0 = blockIdx.x * 256;
    const __half* Bmat = W + (size_t)e * (size_t)Kdim * Ndim;

    int tid = threadIdx.x, wid = tid >> 5, lane = tid & 31;
    int warpM = wid & 1, warpN = wid >> 1;
    int g = lane >> 2, t = lane & 3;
    unsigned smb = (unsigned)__cvta_generic_to_shared(smraw);
    float* sBias = (float*)smraw;
    unsigned tb0 = smb + 1024;

    sBias[tid] = Bias[(size_t)e * Ndim + n0 + tid];

    int arow_i = tid >> 1;
    bool av = (m0 + arow_i) < cnt;
    const __half* aptr;
    if (EP == 1) aptr = H + (size_t)(av ? g_perm[base + m0 + arow_i] : 0) * Kdim;
    else         aptr = g_act + (size_t)(av ? (base + m0 + arow_i) : 0) * Kdim;
    int ahalf = (tid & 1) * 32;

    int brow = tid >> 2, bq = tid & 3;

    float acc[4][8][4];
#pragma unroll
    for (int mt = 0; mt < 4; mt++)
#pragma unroll
        for (int nt = 0; nt < 8; nt++)
#pragma unroll
            for (int r = 0; r < 4; r++) acc[mt][nt][r] = 0.f;

    int KT = Kdim / BKH;

    auto issue = [&](int lt) {
        int s = lt % NSTG;
        unsigned ab = tb0 + (unsigned)s * STG;
        const __half* as = aptr + lt * BKH + ahalf;
        unsigned ar = ab + (unsigned)arow_i * (ASTH * 2) + (unsigned)(tid & 1) * 64;
#pragma unroll
        for (int c = 0; c < 4; c++)
            cpa16(ar + c * 16, as + c * 8, av);
        unsigned bb = ab + ASZB;
        const __half* bs = Bmat + (size_t)(lt * BKH + brow) * Ndim + n0 + bq * 64;
        unsigned br = bb + (unsigned)brow * (BSTH * 2) + (unsigned)bq * 128;
#pragma unroll
        for (int c = 0; c < 8; c++)
            cpa16(br + c * 16, bs + c * 8, true);
        cp_commit();
    };

#pragma unroll
    for (int i = 0; i < NSTG; i++) {
        if (i < KT) issue(i); else cp_commit();
    }

    for (int kt = 0; kt < KT; kt++) {
        int b = kt % NSTG;
        asm volatile("cp.async.wait_group %0;\n" :: "n"(NSTG - 1));
        __syncthreads();

        unsigned aBase = tb0 + (unsigned)b * STG;
        unsigned bBase = aBase + ASZB;
#pragma unroll
        for (int ks = 0; ks < 4; ks++) {
            unsigned afr[4][4];
#pragma unroll
            for (int mt = 0; mt < 4; mt++) {
                int row = warpM * 64 + mt * 16 + (lane & 15);
                int kh = ks * 16 + ((lane >> 4) << 3);
                ldsm4(afr[mt][0], afr[mt][1], afr[mt][2], afr[mt][3],
                      aBase + (unsigned)(row * ASTH + kh) * 2);
            }
            unsigned bfr[8][2];
#pragma unroll
            for (int ntp = 0; ntp < 4; ntp++) {
                unsigned r0, r1, r2, r3;
                int krow = ks * 16 + (lane & 15);
                int col = warpN * 64 + ntp * 16 + ((lane >> 4) << 3);
                ldsm4t(r0, r1, r2, r3, bBase + (unsigned)(krow * BSTH + col) * 2);
                bfr[2 * ntp][0] = r0; bfr[2 * ntp][1] = r1;
                bfr[2 * ntp + 1][0] = r2; bfr[2 * ntp + 1][1] = r3;
            }
#pragma unroll
            for (int mt = 0; mt < 4; mt++)
#pragma unroll
                for (int nt = 0; nt < 8; nt++)
                    mma16816(acc[mt][nt], afr[mt], bfr[nt]);
        }
        __syncthreads();
        if (kt + NSTG < KT) issue(kt + NSTG); else cp_commit();
    }

#pragma unroll
    for (int mt = 0; mt < 4; mt++) {
#pragma unroll
        for (int nt = 0; nt < 8; nt++) {
            int rr = m0 + warpM * 64 + mt * 16 + g;
            int colL = warpN * 64 + nt * 8 + 2 * t;
            int col = n0 + colL;
#pragma unroll
            for (int half_ = 0; half_ < 2; half_++) {
                int r = rr + half_ * 8;
                if (r < cnt) {
                    float v0 = acc[mt][nt][half_ * 2 + 0] + sBias[colL];
                    float v1 = acc[mt][nt][half_ * 2 + 1] + sBias[colL + 1];
                    if (EP == 1) {
                        *(__half2*)(g_act + (size_t)(base + r) * FF_ + col) =
                            __floats2half2_rn(gelu_tanh(v0), gelu_tanh(v1));
                    } else {
                        float2 o; o.x = v0; o.y = v1;
                        *(float2*)(g_y + (size_t)(base + r) * D_ + col) = o;
                    }
                }
            }
        }
    }
}

// ---------------- launch ----------------
#define SMEM_NF128 (NSTG * (ASZB + 64 * 136 * 2))       // 107520
#define SMEM_T128  (NSTG * (ASZB + ASZB))               // 110592
#define SMEM_NF64  (NSTG * (ASZB + 64 * 72 * 2))        // 82944
#define SMEM_MOE   (1024 + NSTG * (ASZB + 64 * 264 * 2)) // 157696

extern "C" void kernel_launch(void* const* d_in, const int* in_sizes, int n_in,
                              void* d_out, int out_size) {
    const float* x   = (const float*)d_in[0];
    const float* anw = (const float*)d_in[1];
    const float* wq  = (const float*)d_in[2];
    const float* wk  = (const float*)d_in[3];
    const float* wv  = (const float*)d_in[4];
    const float* wo  = (const float*)d_in[5];
    const float* mnw = (const float*)d_in[6];
    const float* rw  = (const float*)d_in[7];
    const float* w1  = (const float*)d_in[8];
    const float* b1  = (const float*)d_in[9];
    const float* w2  = (const float*)d_in[10];
    const float* b2  = (const float*)d_in[11];
    float* out = (float*)d_out;

    cudaFuncSetAttribute(hgemm<false, 128, 0>, cudaFuncAttributeMaxDynamicSharedMemorySize, SMEM_NF128);
    cudaFuncSetAttribute(hgemm<false, 128, 1>, cudaFuncAttributeMaxDynamicSharedMemorySize, SMEM_NF128);
    cudaFuncSetAttribute(hgemm<true, 128, 3>,  cudaFuncAttributeMaxDynamicSharedMemorySize, SMEM_T128);
    cudaFuncSetAttribute(hgemm<false, 64, 4>,  cudaFuncAttributeMaxDynamicSharedMemorySize, SMEM_NF64);
    cudaFuncSetAttribute(moe_hgemm<1>,         cudaFuncAttributeMaxDynamicSharedMemorySize, SMEM_MOE);
    cudaFuncSetAttribute(moe_hgemm<2>,         cudaFuncAttributeMaxDynamicSharedMemorySize, SMEM_MOE);

    __half *xn, *wqkvh, *woh, *w1h, *w2h, *qkv, *probsH, *ao, *htf;
    float *x2, *h, *invs;
    cudaGetSymbolAddress((void**)&xn,     g_xn);
    cudaGetSymbolAddress((void**)&wqkvh,  g_wqkvh);
    cudaGetSymbolAddress((void**)&woh,    g_woh);
    cudaGetSymbolAddress((void**)&w1h,    g_w1h);
    cudaGetSymbolAddress((void**)&w2h,    g_w2h);
    cudaGetSymbolAddress((void**)&qkv,    g_qkv);
    cudaGetSymbolAddress((void**)&probsH, g_probsH);
    cudaGetSymbolAddress((void**)&invs,   g_invsum);
    cudaGetSymbolAddress((void**)&ao,     g_attnout);
    cudaGetSymbolAddress((void**)&x2,     g_x2);
    cudaGetSymbolAddress((void**)&h,      g_h);
    cudaGetSymbolAddress((void**)&htf,    g_htf);

    const __half* q = qkv;
    const __half* k = qkv + (size_t)NTOK * D_;
    const __half* v = qkv + 2 * (size_t)NTOK * D_;

    cudaStream_t s2;
    cudaEvent_t evFork, evJoin;
    cudaStreamCreateWithFlags(&s2, cudaStreamNonBlocking);
    cudaEventCreateWithFlags(&evFork, cudaEventDisableTiming);
    cudaEventCreateWithFlags(&evJoin, cudaEventDisableTiming);

    init_kernel<<<1, 32>>>();
    cudaEventRecord(evFork, 0);
    cudaStreamWaitEvent(s2, evFork, 0);

    f2h_kernel<<<4096, 256, 0, s2>>>((const float4*)w1, (uint4*)w1h, (long long)E_ * D_ * FF_ / 8);
    f2h_kernel<<<4096, 256, 0, s2>>>((const float4*)w2, (uint4*)w2h, (long long)E_ * FF_ * D_ / 8);
    cudaEventRecord(evJoin, s2);

    f2h4_kernel<<<dim3(256, 4), 256>>>((const float4*)wq, (const float4*)wk,
                                       (const float4*)wv, (const float4*)wo,
                                       (uint4*)wqkvh, (uint4*)woh);
    rmsnorm_kernel<<<NTOK, 256>>>(x, anw, nullptr, xn);

    hgemm<false, 128, 0><<<dim3(8, 16, 3), 128, SMEM_NF128>>>(
        xn, D_, wqkvh, D_, qkv, D_, NTOK, D_, D_,
        0, 0, (long long)D_ * D_, 0, (long long)NTOK * D_, 0, 1, nullptr, 0);

    {
        long long sSD = (long long)S_ * D_, sSS = (long long)S_ * S_;
        hgemm<true, 128, 3><<<dim3(8, 8, BB_ * NH_), 128, SMEM_T128>>>(
            q, D_, k, D_, probsH, S_, S_, S_, DH_,
            sSD, DH_, sSD, DH_, NH_ * sSS, sSS, NH_, nullptr, 1);
    }

    rowsum_kernel<<<BB_ * NH_ * S_, 128>>>(probsH, invs);

    {
        long long sSD = (long long)S_ * D_, sSS = (long long)S_ * S_;
        hgemm<false, 64, 4><<<dim3(1, 8, BB_ * NH_), 128, SMEM_NF64>>>(
            probsH, S_, v, D_, ao, D_, S_, DH_, S_,
            NH_ * sSS, sSS, sSD, DH_, sSD, DH_, NH_, invs, 2);
    }

    hgemm<false, 128, 1><<<dim3(8, 16, 1), 128, SMEM_NF128>>>(
        ao, D_, woh, D_, x2, D_, NTOK, D_, D_,
        0, 0, 0, 0, 0, 0, 1, x, 0);

    rmsnorm_kernel<<<NTOK, 256>>>(x2, mnw, h, htf);
    router_kernel<<<NTOK, 256>>>(h, rw);
    scan_kernel<<<1, 1>>>();
    place_kernel<<<(NTOK + 255) / 256, 256>>>();

    cudaStreamWaitEvent(0, evJoin, 0);

    moe_hgemm<1><<<dim3(FF_ / 256, NSLOT / 128, E_), 256, SMEM_MOE>>>(htf, w1h, b1, D_, FF_);
    moe_hgemm<2><<<dim3(D_ / 256, NSLOT / 128, E_), 256, SMEM_MOE>>>(nullptr, w2h, b2, FF_, D_);

    combine_kernel<<<(NTOK * D_ + 255) / 256, 256>>>(out);
    finalize_kernel<<<1, 32>>>(out);
}

// round 12
// speedup vs baseline: 1.5707x; 1.0355x over previous
#include <cuda_runtime.h>
#include <cuda_fp16.h>
#include <math.h>
#include <stdint.h>

#define D_    1024
#define S_    1024
#define BB_   2
#define NTOK  2048
#define NH_   16
#define DH_   64
#define E_    8
#define KSEL  2
#define FF_   4096
#define NSLOT 4096

#define BKH   64
#define ASTH  72
#define ASZB  (128*ASTH*2)
#define NSTG  3

__device__ __half g_xn[NTOK * D_];
__device__ __half g_wqkvh[3 * D_ * D_];
__device__ __half g_woh[D_ * D_];
__device__ __half g_w1h[(size_t)E_ * D_ * FF_];
__device__ __half g_w2h[(size_t)E_ * FF_ * D_];
__device__ __half g_qkv[3 * NTOK * D_];
__device__ __half g_probsH[(size_t)BB_ * NH_ * S_ * S_];
__device__ float  g_rowsum[BB_ * NH_ * S_];
__device__ __half g_attnout[NTOK * D_];
__device__ float  g_x2[NTOK * D_];
__device__ float  g_h[NTOK * D_];
__device__ __half g_htf[NTOK * D_];
__device__ __half g_act[(size_t)NSLOT * FF_];
__device__ float  g_y[(size_t)NSLOT * D_];
__device__ float g_topval[NTOK * KSEL];
__device__ int   g_topidx[NTOK * KSEL];
__device__ int   g_slotof[NTOK * KSEL];
__device__ int   g_perm[NSLOT];
__device__ int   g_counts[E_];
__device__ int   g_offs[E_ + 1];
__device__ int   g_cursor[E_];
__device__ float g_probsum[E_];

__device__ __forceinline__ float gelu_tanh(float v) {
    float v3 = v * v * v;
    return 0.5f * v * (1.f + tanhf(0.7978845608028654f * (v + 0.044715f * v3)));
}
__device__ __forceinline__ void cpa16(unsigned dst, const void* src, bool p) {
    int sz = p ? 16 : 0;
    asm volatile("cp.async.cg.shared.global [%0], [%1], 16, %2;\n"
                 :: "r"(dst), "l"(src), "r"(sz));
}
__device__ __forceinline__ void cp_commit() { asm volatile("cp.async.commit_group;\n"); }
__device__ __forceinline__ void ldsm4(unsigned& r0, unsigned& r1, unsigned& r2, unsigned& r3,
                                      unsigned addr) {
    asm volatile("ldmatrix.sync.aligned.m8n8.x4.shared.b16 {%0,%1,%2,%3}, [%4];"
                 : "=r"(r0), "=r"(r1), "=r"(r2), "=r"(r3) : "r"(addr));
}
__device__ __forceinline__ void ldsm4t(unsigned& r0, unsigned& r1, unsigned& r2, unsigned& r3,
                                       unsigned addr) {
    asm volatile("ldmatrix.sync.aligned.m8n8.x4.trans.shared.b16 {%0,%1,%2,%3}, [%4];"
                 : "=r"(r0), "=r"(r1), "=r"(r2), "=r"(r3) : "r"(addr));
}
__device__ __forceinline__ void mma16816(float* d, const unsigned* a, const unsigned* b) {
    asm volatile(
        "mma.sync.aligned.m16n8k16.row.col.f32.f16.f16.f32 "
        "{%0,%1,%2,%3}, {%4,%5,%6,%7}, {%8,%9}, {%0,%1,%2,%3};"
        : "+f"(d[0]), "+f"(d[1]), "+f"(d[2]), "+f"(d[3])
        : "r"(a[0]), "r"(a[1]), "r"(a[2]), "r"(a[3]), "r"(b[0]), "r"(b[1]));
}

__global__ void init_kernel() {
    int i = threadIdx.x;
    if (i < E_) { g_counts[i] = 0; g_cursor[i] = 0; g_probsum[i] = 0.f; }
}
__global__ void zrow_kernel() {
    int i = blockIdx.x * 512 + threadIdx.x;
    if (i < BB_ * NH_ * S_) g_rowsum[i] = 0.f;
}
__global__ void f2h_kernel(const float4* __restrict__ in, uint4* __restrict__ out,
                           long long n8) {
    for (long long i = blockIdx.x * 256LL + threadIdx.x; i < n8;
         i += (long long)gridDim.x * 256) {
        float4 a = in[2 * i], b = in[2 * i + 1];
        __half2 h0 = __floats2half2_rn(a.x, a.y);
        __half2 h1 = __floats2half2_rn(a.z, a.w);
        __half2 h2 = __floats2half2_rn(b.x, b.y);
        __half2 h3 = __floats2half2_rn(b.z, b.w);
        uint4 o;
        o.x = *(unsigned*)&h0; o.y = *(unsigned*)&h1;
        o.z = *(unsigned*)&h2; o.w = *(unsigned*)&h3;
        out[i] = o;
    }
}
__global__ void f2h4_kernel(const float4* __restrict__ a, const float4* __restrict__ b,
                            const float4* __restrict__ c, const float4* __restrict__ d,
                            uint4* __restrict__ oqkv, uint4* __restrict__ oo) {
    const float4* src[4] = { a, b, c, d };
    long long n8 = (long long)D_ * D_ / 8;
    uint4* dst;
    int z = blockIdx.y;
    if (z < 3) dst = oqkv + (size_t)z * n8;
    else       dst = oo;
    const float4* in = src[z];
    for (long long i = blockIdx.x * 256LL + threadIdx.x; i < n8;
         i += (long long)gridDim.x * 256) {
        float4 va = in[2 * i], vb = in[2 * i + 1];
        __half2 h0 = __floats2half2_rn(va.x, va.y);
        __half2 h1 = __floats2half2_rn(va.z, va.w);
        __half2 h2 = __floats2half2_rn(vb.x, vb.y);
        __half2 h3 = __floats2half2_rn(vb.z, vb.w);
        uint4 o;
        o.x = *(unsigned*)&h0; o.y = *(unsigned*)&h1;
        o.z = *(unsigned*)&h2; o.w = *(unsigned*)&h3;
        dst[i] = o;
    }
}
__global__ void rmsnorm_kernel(const float* __restrict__ X, const float* __restrict__ W,
                               float* __restrict__ O, __half* __restrict__ OT) {
    int t = blockIdx.x;
    const float* x = X + (size_t)t * D_;
    float ss = 0.f;
    for (int d = threadIdx.x; d < D_; d += 256) { float v = x[d]; ss += v * v; }
    __shared__ float red[256];
    red[threadIdx.x] = ss; __syncthreads();
    for (int s = 128; s > 0; s >>= 1) {
        if (threadIdx.x < s) red[threadIdx.x] += red[threadIdx.x + s];
        __syncthreads();
    }
    float scale = rsqrtf(red[0] * (1.f / D_) + 1e-6f);
    for (int d = threadIdx.x; d < D_; d += 256) {
        float v = x[d] * scale * W[d];
        if (O)  O[(size_t)t * D_ + d] = v;
        OT[(size_t)t * D_ + d] = __float2half_rn(v);
    }
}
__global__ void router_kernel(const float* __restrict__ H, const float* __restrict__ RW) {
    int t = blockIdx.x;
    int tid = threadIdx.x;
    int e = tid >> 5, lane = tid & 31;
    const float* h = H + (size_t)t * D_;
    float p = 0.f;
    for (int d = lane; d < D_; d += 32) p += h[d] * RW[d * E_ + e];
    for (int o = 16; o > 0; o >>= 1) p += __shfl_down_sync(0xffffffff, p, o);
    __shared__ float lg[E_];
    if (lane == 0) lg[e] = p;
    __syncthreads();
    if (tid == 0) {
        float mx = lg[0];
        for (int i = 1; i < E_; i++) mx = fmaxf(mx, lg[i]);
        float pr[E_]; float s = 0.f;
        for (int i = 0; i < E_; i++) { pr[i] = expf(lg[i] - mx); s += pr[i]; }
        float inv = 1.f / s;
        float b1v = -1.f, b2v = -1.f; int b1i = 0, b2i = 0;
        for (int i = 0; i < E_; i++) {
            float v = pr[i] * inv;
            atomicAdd(&g_probsum[i], v);
            if (v > b1v) { b2v = b1v; b2i = b1i; b1v = v; b1i = i; }
            else if (v > b2v) { b2v = v; b2i = i; }
        }
        g_topidx[t * 2] = b1i; g_topidx[t * 2 + 1] = b2i;
        g_topval[t * 2] = b1v; g_topval[t * 2 + 1] = b2v;
        atomicAdd(&g_counts[b1i], 1);
        atomicAdd(&g_counts[b2i], 1);
    }
}
__global__ void scan_kernel() {
    if (threadIdx.x == 0) {
        g_offs[0] = 0;
        for (int e = 0; e < E_; e++) {
            g_offs[e + 1] = g_offs[e] + g_counts[e];
            g_cursor[e] = g_offs[e];
        }
    }
}
__global__ void place_kernel() {
    int t = blockIdx.x * blockDim.x + threadIdx.x;
    if (t >= NTOK) return;
    for (int kk = 0; kk < KSEL; kk++) {
        int e = g_topidx[t * 2 + kk];
        int slot = atomicAdd(&g_cursor[e], 1);
        g_perm[slot] = t;
        g_slotof[t * 2 + kk] = slot;
    }
}
__global__ void combine_kernel(float* __restrict__ out) {
    int idx = blockIdx.x * blockDim.x + threadIdx.x;
    if (idx >= NTOK * D_) return;
    int t = idx >> 10, d = idx & 1023;
    float v = g_x2[idx];
    v += g_topval[t * 2]     * g_y[(size_t)g_slotof[t * 2]     * D_ + d];
    v += g_topval[t * 2 + 1] * g_y[(size_t)g_slotof[t * 2 + 1] * D_ + d];
    out[idx] = v;
}
__global__ void finalize_kernel(float* __restrict__ out) {
    if (threadIdx.x == 0) {
        float loss = 0.f;
        for (int e = 0; e < E_; e++)
            loss += ((float)g_counts[e] / (float)NSLOT) * (g_probsum[e] / (float)NTOK);
        loss *= (float)E_;
        out[(size_t)NTOK * D_] = loss;
        for (int e = 0; e < E_; e++)
            out[(size_t)NTOK * D_ + 1 + e] = (float)g_counts[e];
    }
}

// EPI: 0 half; 1 float + residual(addpF=[M,N] fp32); 2 float;
//      3 half exp(v/8) causal + atomic rowsum into addpF[z*S+r];
//      4 half v / addpF[z*S+r].
template <bool TB, int NT, int EPI>
__global__ void __launch_bounds__(128, 2)
hgemm(const __half* __restrict__ A, int lda,
      const __half* __restrict__ B, int ldb,
      void* __restrict__ Cv, int ldc,
      int M, int N, int K,
      long long aO, long long aI, long long bO, long long bI,
      long long cO, long long cI, int zdiv,
      float* __restrict__ addpF, int mode) {
    constexpr int BSTH = NT + 8;
    constexpr int BSZB = TB ? ASZB : (64 * BSTH * 2);
    constexpr int STG  = ASZB + BSZB;
    constexpr int NTW  = NT / 16;
    extern __shared__ __align__(16) unsigned char smraw[];

    int z = blockIdx.z, zo = z / zdiv, zi = z % zdiv;
    A += zo * aO + zi * aI;
    B += zo * bO + zi * bI;

    int m0 = blockIdx.y * 128, n0 = blockIdx.x * NT;
    if (mode == 1 && n0 > m0 + 127) return;
    int Keff = (mode == 2) ? min(K, m0 + 128) : K;
    int KT = Keff / BKH;

    int tid = threadIdx.x, wid = tid >> 5, lane = tid & 31;
    int warpM = wid & 1, warpN = wid >> 1;
    int g = lane >> 2, t = lane & 3;
    unsigned smb = (unsigned)__cvta_generic_to_shared(smraw);

    bool av = (m0 + tid) < M;
    const __half* aptr = A + (size_t)(av ? (m0 + tid) : 0) * lda;
    const __half* bptr = nullptr;
    bool bv = true;
    if (TB) {
        bv = (n0 + tid) < N;
        bptr = B + (size_t)(bv ? (n0 + tid) : 0) * ldb;
    }

    float acc[4][NTW][4];
#pragma unroll
    for (int mt = 0; mt < 4; mt++)
#pragma unroll
        for (int nt = 0; nt < NTW; nt++)
#pragma unroll
            for (int r = 0; r < 4; r++) acc[mt][nt][r] = 0.f;

    auto issue = [&](int lt) {
        int s = lt % NSTG;
        unsigned ab = smb + (unsigned)s * STG;
        const __half* as = aptr + lt * BKH;
        unsigned arow = ab + (unsigned)tid * (ASTH * 2);
#pragma unroll
        for (int c = 0; c < 8; c++)
            cpa16(arow + c * 16, as + c * 8, av);
        unsigned bb = ab + ASZB;
        if (TB) {
            const __half* bs = bptr + lt * BKH;
            unsigned br = bb + (unsigned)tid * (ASTH * 2);
#pragma unroll
            for (int c = 0; c < 8; c++)
                cpa16(br + c * 16, bs + c * 8, bv);
        } else {
            int row = tid >> 1;
            int cb = (tid & 1) * (NT / 16);
            const __half* bs = B + (size_t)(lt * BKH + row) * ldb + n0;
            unsigned br = bb + (unsigned)row * (BSTH * 2);
#pragma unroll
            for (int j = 0; j < NT / 16; j++)
                cpa16(br + (cb + j) * 16, bs + (cb + j) * 8, true);
        }
        cp_commit();
    };

#pragma unroll
    for (int i = 0; i < NSTG - 1; i++) {
        if (i < KT) issue(i); else cp_commit();
    }

    for (int kt = 0; kt < KT; kt++) {
        int b = kt % NSTG;
        asm volatile("cp.async.wait_group %0;\n" :: "n"(NSTG - 2));
        __syncthreads();
        if (kt + NSTG - 1 < KT) issue(kt + NSTG - 1); else cp_commit();

        unsigned aBase = smb + (unsigned)b * STG;
        unsigned bBase = aBase + ASZB;
#pragma unroll
        for (int ks = 0; ks < 4; ks++) {
            unsigned afr[4][4];
#pragma unroll
            for (int mt = 0; mt < 4; mt++) {
                int row = warpM * 64 + mt * 16 + (lane & 15);
                int kh = ks * 16 + ((lane >> 4) << 3);
                ldsm4(afr[mt][0], afr[mt][1], afr[mt][2], afr[mt][3],
                      aBase + (unsigned)(row * ASTH + kh) * 2);
            }
            unsigned bfr[NTW][2];
#pragma unroll
            for (int ntp = 0; ntp < NTW / 2; ntp++) {
                unsigned r0, r1, r2, r3;
                if (TB) {
                    int row = warpN * 64 + ntp * 16 + (lane & 15);
                    int kh = ks * 16 + ((lane >> 4) << 3);
                    ldsm4(r0, r1, r2, r3, bBase + (unsigned)(row * ASTH + kh) * 2);
                    bfr[2 * ntp][0] = r0; bfr[2 * ntp + 1][0] = r1;
                    bfr[2 * ntp][1] = r2; bfr[2 * ntp + 1][1] = r3;
                } else {
                    int krow = ks * 16 + (lane & 15);
                    int col = warpN * (NT / 2) + ntp * 16 + ((lane >> 4) << 3);
                    ldsm4t(r0, r1, r2, r3, bBase + (unsigned)(krow * BSTH + col) * 2);
                    bfr[2 * ntp][0] = r0; bfr[2 * ntp][1] = r1;
                    bfr[2 * ntp + 1][0] = r2; bfr[2 * ntp + 1][1] = r3;
                }
            }
#pragma unroll
            for (int mt = 0; mt < 4; mt++)
#pragma unroll
                for (int nt = 0; nt < NTW; nt++)
                    mma16816(acc[mt][nt], afr[mt], bfr[nt]);
        }
        __syncthreads();
    }

#pragma unroll
    for (int mt = 0; mt < 4; mt++) {
#pragma unroll
        for (int half_ = 0; half_ < 2; half_++) {
            int r = m0 + warpM * 64 + mt * 16 + g + half_ * 8;
            float rsum = 0.f;
#pragma unroll
            for (int nt = 0; nt < NTW; nt++) {
                int col = n0 + warpN * (NT / 2) + nt * 8 + 2 * t;
                if (r < M && col < N) {
                    float v0 = acc[mt][nt][half_ * 2 + 0];
                    float v1 = acc[mt][nt][half_ * 2 + 1];
                    size_t cidx = (size_t)(zo * cO + zi * cI) + (size_t)r * ldc + col;
                    if (EPI == 0) {
                        *(__half2*)((__half*)Cv + cidx) = __floats2half2_rn(v0, v1);
                    } else if (EPI == 1) {
                        float2 ad = *(const float2*)(addpF + (size_t)r * ldc + col);
                        float2 o; o.x = v0 + ad.x; o.y = v1 + ad.y;
                        *(float2*)((float*)Cv + cidx) = o;
                    } else if (EPI == 2) {
                        float2 o; o.x = v0; o.y = v1;
                        *(float2*)((float*)Cv + cidx) = o;
                    } else if (EPI == 3) {
                        float e0 = (col     <= r) ? __expf(v0 * 0.125f) : 0.f;
                        float e1 = (col + 1 <= r) ? __expf(v1 * 0.125f) : 0.f;
                        rsum += e0 + e1;
                        *(__half2*)((__half*)Cv + cidx) = __floats2half2_rn(e0, e1);
                    } else {
                        float sc = 1.f / addpF[(size_t)z * S_ + r];
                        *(__half2*)((__half*)Cv + cidx) = __floats2half2_rn(v0 * sc, v1 * sc);
                    }
                }
            }
            if (EPI == 3) {
                rsum += __shfl_down_sync(0xffffffffu, rsum, 2);
                rsum += __shfl_down_sync(0xffffffffu, rsum, 1);
                if (t == 0 && r < M)
                    atomicAdd(&addpF[(size_t)z * S_ + r], rsum);
            }
        }
    }
}

template <int EP>
__global__ void __launch_bounds__(256, 1)
moe_hgemm(const __half* __restrict__ H, const __half* __restrict__ W,
          const float* __restrict__ Bias, int Kdim, int Ndim) {
    constexpr int BSTH = 264;
    constexpr int BSZB = 64 * BSTH * 2;
    constexpr int STG  = ASZB + BSZB;
    extern __shared__ __align__(16) unsigned char smraw[];

    int e = blockIdx.z;
    int base = g_offs[e], cnt = g_offs[e + 1] - base;
    int m0 = blockIdx.y * 128;
    if (m0 >= cnt) return;
    int n0 = blockIdx.x * 256;
    const __half* Bmat = W + (size_t)e * (size_t)Kdim * Ndim;

    int tid = threadIdx.x, wid = tid >> 5, lane = tid & 31;
    int warpM = wid & 1, warpN = wid >> 1;
    int g = lane >> 2, t = lane & 3;
    unsigned smb = (unsigned)__cvta_generic_to_shared(smraw);
    float* sBias = (float*)smraw;
    unsigned tb0 = smb + 1024;

    sBias[tid] = Bias[(size_t)e * Ndim + n0 + tid];

    int arow_i = tid >> 1;
    bool av = (m0 + arow_i) < cnt;
    const __half* aptr;
    if (EP == 1) aptr = H + (size_t)(av ? g_perm[base + m0 + arow_i] : 0) * Kdim;
    else         aptr = g_act + (size_t)(av ? (base + m0 + arow_i) : 0) * Kdim;
    int ahalf = (tid & 1) * 32;

    int brow = tid >> 2, bq = tid & 3;

    float acc[4][8][4];
#pragma unroll
    for (int mt = 0; mt < 4; mt++)
#pragma unroll
        for (int nt = 0; nt < 8; nt++)
#pragma unroll
            for (int r = 0; r < 4; r++) acc[mt][nt][r] = 0.f;

    int KT = Kdim / BKH;

    auto issue = [&](int lt) {
        int s = lt % NSTG;
        unsigned ab = tb0 + (unsigned)s * STG;
        const __half* as = aptr + lt * BKH + ahalf;
        unsigned ar = ab + (unsigned)arow_i * (ASTH * 2) + (unsigned)(tid & 1) * 64;
#pragma unroll
        for (int c = 0; c < 4; c++)
            cpa16(ar + c * 16, as + c * 8, av);
        unsigned bb = ab + ASZB;
        const __half* bs = Bmat + (size_t)(lt * BKH + brow) * Ndim + n0 + bq * 64;
        unsigned br = bb + (unsigned)brow * (BSTH * 2) + (unsigned)bq * 128;
#pragma unroll
        for (int c = 0; c < 8; c++)
            cpa16(br + c * 16, bs + c * 8, true);
        cp_commit();
    };

#pragma unroll
    for (int i = 0; i < NSTG - 1; i++) {
        if (i < KT) issue(i); else cp_commit();
    }

    for (int kt = 0; kt < KT; kt++) {
        int b = kt % NSTG;
        asm volatile("cp.async.wait_group %0;\n" :: "n"(NSTG - 2));
        __syncthreads();
        if (kt + NSTG - 1 < KT) issue(kt + NSTG - 1); else cp_commit();

        unsigned aBase = tb0 + (unsigned)b * STG;
        unsigned bBase = aBase + ASZB;
#pragma unroll
        for (int ks = 0; ks < 4; ks++) {
            unsigned afr[4][4];
#pragma unroll
            for (int mt = 0; mt < 4; mt++) {
                int row = warpM * 64 + mt * 16 + (lane & 15);
                int kh = ks * 16 + ((lane >> 4) << 3);
                ldsm4(afr[mt][0], afr[mt][1], afr[mt][2], afr[mt][3],
                      aBase + (unsigned)(row * ASTH + kh) * 2);
            }
            unsigned bfr[8][2];
#pragma unroll
            for (int ntp = 0; ntp < 4; ntp++) {
                unsigned r0, r1, r2, r3;
                int krow = ks * 16 + (lane & 15);
                int col = warpN * 64 + ntp * 16 + ((lane >> 4) << 3);
                ldsm4t(r0, r1, r2, r3, bBase + (unsigned)(krow * BSTH + col) * 2);
                bfr[2 * ntp][0] = r0; bfr[2 * ntp][1] = r1;
                bfr[2 * ntp + 1][0] = r2; bfr[2 * ntp + 1][1] = r3;
            }
#pragma unroll
            for (int mt = 0; mt < 4; mt++)
#pragma unroll
                for (int nt = 0; nt < 8; nt++)
                    mma16816(acc[mt][nt], afr[mt], bfr[nt]);
        }
        __syncthreads();
    }

#pragma unroll
    for (int mt = 0; mt < 4; mt++) {
#pragma unroll
        for (int nt = 0; nt < 8; nt++) {
            int rr = m0 + warpM * 64 + mt * 16 + g;
            int colL = warpN * 64 + nt * 8 + 2 * t;
            int col = n0 + colL;
#pragma unroll
            for (int half_ = 0; half_ < 2; half_++) {
                int r = rr + half_ * 8;
                if (r < cnt) {
                    float v0 = acc[mt][nt][half_ * 2 + 0] + sBias[colL];
                    float v1 = acc[mt][nt][half_ * 2 + 1] + sBias[colL + 1];
                    if (EP == 1) {
                        *(__half2*)(g_act + (size_t)(base + r) * FF_ + col) =
                            __floats2half2_rn(gelu_tanh(v0), gelu_tanh(v1));
                    } else {
                        float2 o; o.x = v0; o.y = v1;
                        *(float2*)(g_y + (size_t)(base + r) * D_ + col) = o;
                    }
                }
            }
        }
    }
}

#define SMEM_NF128 (NSTG * (ASZB + 64 * 136 * 2))
#define SMEM_T128  (NSTG * (ASZB + ASZB))
#define SMEM_NF64  (NSTG * (ASZB + 64 * 72 * 2))
#define SMEM_MOE   (1024 + NSTG * (ASZB + 64 * 264 * 2))

extern "C" void kernel_launch(void* const* d_in, const int* in_sizes, int n_in,
                              void* d_out, int out_size) {
    const float* x   = (const float*)d_in[0];
    const float* anw = (const float*)d_in[1];
    const float* wq  = (const float*)d_in[2];
    const float* wk  = (const float*)d_in[3];
    const float* wv  = (const float*)d_in[4];
    const float* wo  = (const float*)d_in[5];
    const float* mnw = (const float*)d_in[6];
    const float* rw  = (const float*)d_in[7];
    const float* w1  = (const float*)d_in[8];
    const float* b1  = (const float*)d_in[9];
    const float* w2  = (const float*)d_in[10];
    const float* b2  = (const float*)d_in[11];
    float* out = (float*)d_out;

    cudaFuncSetAttribute(hgemm<false, 128, 0>, cudaFuncAttributeMaxDynamicSharedMemorySize, SMEM_NF128);
    cudaFuncSetAttribute(hgemm<false, 128, 1>, cudaFuncAttributeMaxDynamicSharedMemorySize, SMEM_NF128);
    cudaFuncSetAttribute(hgemm<true, 128, 3>,  cudaFuncAttributeMaxDynamicSharedMemorySize, SMEM_T128);
    cudaFuncSetAttribute(hgemm<false, 64, 4>,  cudaFuncAttributeMaxDynamicSharedMemorySize, SMEM_NF64);
    cudaFuncSetAttribute(moe_hgemm<1>,         cudaFuncAttributeMaxDynamicSharedMemorySize, SMEM_MOE);
    cudaFuncSetAttribute(moe_hgemm<2>,         cudaFuncAttributeMaxDynamicSharedMemorySize, SMEM_MOE);

    __half *xn, *wqkvh, *woh, *w1h, *w2h, *qkv, *probsH, *ao, *htf;
    float *x2, *h, *rsum;
    cudaGetSymbolAddress((void**)&xn,     g_xn);
    cudaGetSymbolAddress((void**)&wqkvh,  g_wqkvh);
    cudaGetSymbolAddress((void**)&woh,    g_woh);
    cudaGetSymbolAddress((void**)&w1h,    g_w1h);
    cudaGetSymbolAddress((void**)&w2h,    g_w2h);
    cudaGetSymbolAddress((void**)&qkv,    g_qkv);
    cudaGetSymbolAddress((void**)&probsH, g_probsH);
    cudaGetSymbolAddress((void**)&rsum,   g_rowsum);
    cudaGetSymbolAddress((void**)&ao,     g_attnout);
    cudaGetSymbolAddress((void**)&x2,     g_x2);
    cudaGetSymbolAddress((void**)&h,      g_h);
    cudaGetSymbolAddress((void**)&htf,    g_htf);

    const __half* q = qkv;
    const __half* k = qkv + (size_t)NTOK * D_;
    const __half* v = qkv + 2 * (size_t)NTOK * D_;

    cudaStream_t s2;
    cudaEvent_t evFork, evJoin;
    cudaStreamCreateWithFlags(&s2, cudaStreamNonBlocking);
    cudaEventCreateWithFlags(&evFork, cudaEventDisableTiming);
    cudaEventCreateWithFlags(&evJoin, cudaEventDisableTiming);

    init_kernel<<<1, 32>>>();
    zrow_kernel<<<(BB_ * NH_ * S_ + 511) / 512, 512>>>();
    cudaEventRecord(evFork, 0);
    cudaStreamWaitEvent(s2, evFork, 0);

    f2h_kernel<<<4096, 256, 0, s2>>>((const float4*)w1, (uint4*)w1h, (long long)E_ * D_ * FF_ / 8);
    f2h_kernel<<<4096, 256, 0, s2>>>((const float4*)w2, (uint4*)w2h, (long long)E_ * FF_ * D_ / 8);
    cudaEventRecord(evJoin, s2);

    f2h4_kernel<<<dim3(256, 4), 256>>>((const float4*)wq, (const float4*)wk,
                                       (const float4*)wv, (const float4*)wo,
                                       (uint4*)wqkvh, (uint4*)woh);
    rmsnorm_kernel<<<NTOK, 256>>>(x, anw, nullptr, xn);

    hgemm<false, 128, 0><<<dim3(8, 16, 3), 128, SMEM_NF128>>>(
        xn, D_, wqkvh, D_, qkv, D_, NTOK, D_, D_,
        0, 0, (long long)D_ * D_, 0, (long long)NTOK * D_, 0, 1, nullptr, 0);

    {
        long long sSD = (long long)S_ * D_, sSS = (long long)S_ * S_;
        hgemm<true, 128, 3><<<dim3(8, 8, BB_ * NH_), 128, SMEM_T128>>>(
            q, D_, k, D_, probsH, S_, S_, S_, DH_,
            sSD, DH_, sSD, DH_, NH_ * sSS, sSS, NH_, rsum, 1);
    }

    {
        long long sSD = (long long)S_ * D_, sSS = (long long)S_ * S_;
        hgemm<false, 64, 4><<<dim3(1, 8, BB_ * NH_), 128, SMEM_NF64>>>(
            probsH, S_, v, D_, ao, D_, S_, DH_, S_,
            NH_ * sSS, sSS, sSD, DH_, sSD, DH_, NH_, rsum, 2);
    }

    hgemm<false, 128, 1><<<dim3(8, 16, 1), 128, SMEM_NF128>>>(
        ao, D_, woh, D_, x2, D_, NTOK, D_, D_,
        0, 0, 0, 0, 0, 0, 1, (float*)x, 0);

    rmsnorm_kernel<<<NTOK, 256>>>(x2, mnw, h, htf);
    router_kernel<<<NTOK, 256>>>(h, rw);
    scan_kernel<<<1, 1>>>();
    place_kernel<<<(NTOK + 255) / 256, 256>>>();

    cudaStreamWaitEvent(0, evJoin, 0);

    moe_hgemm<1><<<dim3(FF_ / 256, NSLOT / 128, E_), 256, SMEM_MOE>>>(htf, w1h, b1, D_, FF_);
    moe_hgemm<2><<<dim3(D_ / 256, NSLOT / 128, E_), 256, SMEM_MOE>>>(nullptr, w2h, b2, FF_, D_);

    combine_kernel<<<(NTOK * D_ + 255) / 256, 256>>>(out);
    finalize_kernel<<<1, 32>>>(out);
}

// round 13
// speedup vs baseline: 1.5753x; 1.0029x over previous
#include <cuda_runtime.h>
#include <cuda_fp16.h>
#include <math.h>
#include <stdint.h>

#define D_    1024
#define S_    1024
#define BB_   2
#define NTOK  2048
#define NH_   16
#define DH_   64
#define E_    8
#define KSEL  2
#define FF_   4096
#define NSLOT 4096

#define BKH   64
#define ASTH  72
#define ASZB  (128*ASTH*2)
#define NSTG  3

__device__ __half g_xn[NTOK * D_];
__device__ __half g_wqkvh[3 * D_ * D_];
__device__ __half g_woh[D_ * D_];
__device__ __half g_w1h[(size_t)E_ * D_ * FF_];
__device__ __half g_w2h[(size_t)E_ * FF_ * D_];
__device__ __half g_qkv[3 * NTOK * D_];
__device__ __half g_probsH[(size_t)BB_ * NH_ * S_ * S_];
__device__ float  g_rowsum[BB_ * NH_ * S_];
__device__ __half g_attnout[NTOK * D_];
__device__ float  g_x2[NTOK * D_];
__device__ __half g_htf[NTOK * D_];
__device__ __half g_act[(size_t)NSLOT * FF_];
__device__ float  g_y[(size_t)NSLOT * D_];
__device__ float g_topval[NTOK * KSEL];
__device__ int   g_topidx[NTOK * KSEL];
__device__ int   g_slotof[NTOK * KSEL];
__device__ int   g_perm[NSLOT];
__device__ int   g_counts[E_];
__device__ int   g_offs[E_ + 1];
__device__ int   g_cursor[E_];
__device__ float g_probsum[E_];

__device__ __forceinline__ float gelu_tanh(float v) {
    float v3 = v * v * v;
    return 0.5f * v * (1.f + tanhf(0.7978845608028654f * (v + 0.044715f * v3)));
}
__device__ __forceinline__ void cpa16(unsigned dst, const void* src, bool p) {
    int sz = p ? 16 : 0;
    asm volatile("cp.async.cg.shared.global [%0], [%1], 16, %2;\n"
                 :: "r"(dst), "l"(src), "r"(sz));
}
__device__ __forceinline__ void cp_commit() { asm volatile("cp.async.commit_group;\n"); }
__device__ __forceinline__ void ldsm4(unsigned& r0, unsigned& r1, unsigned& r2, unsigned& r3,
                                      unsigned addr) {
    asm volatile("ldmatrix.sync.aligned.m8n8.x4.shared.b16 {%0,%1,%2,%3}, [%4];"
                 : "=r"(r0), "=r"(r1), "=r"(r2), "=r"(r3) : "r"(addr));
}
__device__ __forceinline__ void ldsm4t(unsigned& r0, unsigned& r1, unsigned& r2, unsigned& r3,
                                       unsigned addr) {
    asm volatile("ldmatrix.sync.aligned.m8n8.x4.trans.shared.b16 {%0,%1,%2,%3}, [%4];"
                 : "=r"(r0), "=r"(r1), "=r"(r2), "=r"(r3) : "r"(addr));
}
__device__ __forceinline__ void mma16816(float* d, const unsigned* a, const unsigned* b) {
    asm volatile(
        "mma.sync.aligned.m16n8k16.row.col.f32.f16.f16.f32 "
        "{%0,%1,%2,%3}, {%4,%5,%6,%7}, {%8,%9}, {%0,%1,%2,%3};"
        : "+f"(d[0]), "+f"(d[1]), "+f"(d[2]), "+f"(d[3])
        : "r"(a[0]), "r"(a[1]), "r"(a[2]), "r"(a[3]), "r"(b[0]), "r"(b[1]));
}

// init counts/cursors/probsum + zero rowsum, one launch
__global__ void init2_kernel() {
    int i = blockIdx.x * 512 + threadIdx.x;
    if (i < E_) { g_counts[i] = 0; g_cursor[i] = 0; g_probsum[i] = 0.f; }
    if (i < BB_ * NH_ * S_) g_rowsum[i] = 0.f;
}

__global__ void f2h_kernel(const float4* __restrict__ in, uint4* __restrict__ out,
                           long long n8) {
    for (long long i = blockIdx.x * 256LL + threadIdx.x; i < n8;
         i += (long long)gridDim.x * 256) {
        float4 a = in[2 * i], b = in[2 * i + 1];
        __half2 h0 = __floats2half2_rn(a.x, a.y);
        __half2 h1 = __floats2half2_rn(a.z, a.w);
        __half2 h2 = __floats2half2_rn(b.x, b.y);
        __half2 h3 = __floats2half2_rn(b.z, b.w);
        uint4 o;
        o.x = *(unsigned*)&h0; o.y = *(unsigned*)&h1;
        o.z = *(unsigned*)&h2; o.w = *(unsigned*)&h3;
        out[i] = o;
    }
}
__global__ void f2h4_kernel(const float4* __restrict__ a, const float4* __restrict__ b,
                            const float4* __restrict__ c, const float4* __restrict__ d,
                            uint4* __restrict__ oqkv, uint4* __restrict__ oo) {
    const float4* src[4] = { a, b, c, d };
    long long n8 = (long long)D_ * D_ / 8;
    uint4* dst;
    int z = blockIdx.y;
    if (z < 3) dst = oqkv + (size_t)z * n8;
    else       dst = oo;
    const float4* in = src[z];
    for (long long i = blockIdx.x * 256LL + threadIdx.x; i < n8;
         i += (long long)gridDim.x * 256) {
        float4 va = in[2 * i], vb = in[2 * i + 1];
        __half2 h0 = __floats2half2_rn(va.x, va.y);
        __half2 h1 = __floats2half2_rn(va.z, va.w);
        __half2 h2 = __floats2half2_rn(vb.x, vb.y);
        __half2 h3 = __floats2half2_rn(vb.z, vb.w);
        uint4 o;
        o.x = *(unsigned*)&h0; o.y = *(unsigned*)&h1;
        o.z = *(unsigned*)&h2; o.w = *(unsigned*)&h3;
        dst[i] = o;
    }
}
__global__ void rmsnorm_kernel(const float* __restrict__ X, const float* __restrict__ W,
                               __half* __restrict__ OT) {
    int t = blockIdx.x;
    const float* x = X + (size_t)t * D_;
    float ss = 0.f;
    for (int d = threadIdx.x; d < D_; d += 256) { float v = x[d]; ss += v * v; }
    __shared__ float red[256];
    red[threadIdx.x] = ss; __syncthreads();
    for (int s = 128; s > 0; s >>= 1) {
        if (threadIdx.x < s) red[threadIdx.x] += red[threadIdx.x + s];
        __syncthreads();
    }
    float scale = rsqrtf(red[0] * (1.f / D_) + 1e-6f);
    for (int d = threadIdx.x; d < D_; d += 256)
        OT[(size_t)t * D_ + d] = __float2half_rn(x[d] * scale * W[d]);
}

// fused rmsnorm(x2) -> htf + router (h stays in smem; bit-identical dot order)
__global__ void rmsrouter_kernel(const float* __restrict__ X, const float* __restrict__ W,
                                 __half* __restrict__ OT, const float* __restrict__ RW) {
    int t = blockIdx.x;
    int tid = threadIdx.x;
    const float* x = X + (size_t)t * D_;
    __shared__ float hv[D_];
    __shared__ float red[256];
    float ss = 0.f;
    for (int d = tid; d < D_; d += 256) { float v = x[d]; ss += v * v; }
    red[tid] = ss; __syncthreads();
    for (int s = 128; s > 0; s >>= 1) {
        if (tid < s) red[tid] += red[tid + s];
        __syncthreads();
    }
    float scale = rsqrtf(red[0] * (1.f / D_) + 1e-6f);
    for (int d = tid; d < D_; d += 256) {
        float v = x[d] * scale * W[d];
        hv[d] = v;
        OT[(size_t)t * D_ + d] = __float2half_rn(v);
    }
    __syncthreads();

    int e = tid >> 5, lane = tid & 31;
    float p = 0.f;
    for (int d = lane; d < D_; d += 32) p += hv[d] * RW[d * E_ + e];
    for (int o = 16; o > 0; o >>= 1) p += __shfl_down_sync(0xffffffff, p, o);
    __shared__ float lg[E_];
    if (lane == 0) lg[e] = p;
    __syncthreads();
    if (tid == 0) {
        float mx = lg[0];
        for (int i = 1; i < E_; i++) mx = fmaxf(mx, lg[i]);
        float pr[E_]; float s = 0.f;
        for (int i = 0; i < E_; i++) { pr[i] = expf(lg[i] - mx); s += pr[i]; }
        float inv = 1.f / s;
        float b1v = -1.f, b2v = -1.f; int b1i = 0, b2i = 0;
        for (int i = 0; i < E_; i++) {
            float v = pr[i] * inv;
            atomicAdd(&g_probsum[i], v);
            if (v > b1v) { b2v = b1v; b2i = b1i; b1v = v; b1i = i; }
            else if (v > b2v) { b2v = v; b2i = i; }
        }
        g_topidx[t * 2] = b1i; g_topidx[t * 2 + 1] = b2i;
        g_topval[t * 2] = b1v; g_topval[t * 2 + 1] = b2v;
        atomicAdd(&g_counts[b1i], 1);
        atomicAdd(&g_counts[b2i], 1);
    }
}

__global__ void scan_kernel() {
    if (threadIdx.x == 0) {
        g_offs[0] = 0;
        for (int e = 0; e < E_; e++) {
            g_offs[e + 1] = g_offs[e] + g_counts[e];
            g_cursor[e] = g_offs[e];
        }
    }
}
__global__ void place_kernel() {
    int t = blockIdx.x * blockDim.x + threadIdx.x;
    if (t >= NTOK) return;
    for (int kk = 0; kk < KSEL; kk++) {
        int e = g_topidx[t * 2 + kk];
        int slot = atomicAdd(&g_cursor[e], 1);
        g_perm[slot] = t;
        g_slotof[t * 2 + kk] = slot;
    }
}
__global__ void combine_kernel(float* __restrict__ out) {
    int idx = blockIdx.x * blockDim.x + threadIdx.x;
    if (idx >= NTOK * D_) return;
    int t = idx >> 10, d = idx & 1023;
    float v = g_x2[idx];
    v += g_topval[t * 2]     * g_y[(size_t)g_slotof[t * 2]     * D_ + d];
    v += g_topval[t * 2 + 1] * g_y[(size_t)g_slotof[t * 2 + 1] * D_ + d];
    out[idx] = v;
}
__global__ void finalize_kernel(float* __restrict__ out) {
    if (threadIdx.x == 0) {
        float loss = 0.f;
        for (int e = 0; e < E_; e++)
            loss += ((float)g_counts[e] / (float)NSLOT) * (g_probsum[e] / (float)NTOK);
        loss *= (float)E_;
        out[(size_t)NTOK * D_] = loss;
        for (int e = 0; e < E_; e++)
            out[(size_t)NTOK * D_ + 1 + e] = (float)g_counts[e];
    }
}

// EPI: 0 half; 1 float + residual(addpF=[M,N] fp32); 2 float;
//      3 half exp(v/8) causal + atomic rowsum into addpF[z*S+r];
//      4 half v / addpF[z*S+r].
// mode: 0 none, 1 causal tile-skip, 2 k-clip. modes 1/2 remap y heavy-first.
template <bool TB, int NT, int EPI>
__global__ void __launch_bounds__(128, 2)
hgemm(const __half* __restrict__ A, int lda,
      const __half* __restrict__ B, int ldb,
      void* __restrict__ Cv, int ldc,
      int M, int N, int K,
      long long aO, long long aI, long long bO, long long bI,
      long long cO, long long cI, int zdiv,
      float* __restrict__ addpF, int mode) {
    constexpr int BSTH = NT + 8;
    constexpr int BSZB = TB ? ASZB : (64 * BSTH * 2);
    constexpr int STG  = ASZB + BSZB;
    constexpr int NTW  = NT / 16;
    extern __shared__ __align__(16) unsigned char smraw[];

    int z = blockIdx.z, zo = z / zdiv, zi = z % zdiv;
    A += zo * aO + zi * aI;
    B += zo * bO + zi * bI;

    int by = mode ? ((int)gridDim.y - 1 - (int)blockIdx.y) : (int)blockIdx.y;
    int m0 = by * 128, n0 = blockIdx.x * NT;
    if (mode == 1 && n0 > m0 + 127) return;
    int Keff = (mode == 2) ? min(K, m0 + 128) : K;
    int KT = Keff / BKH;

    int tid = threadIdx.x, wid = tid >> 5, lane = tid & 31;
    int warpM = wid & 1, warpN = wid >> 1;
    int g = lane >> 2, t = lane & 3;
    unsigned smb = (unsigned)__cvta_generic_to_shared(smraw);

    bool av = (m0 + tid) < M;
    const __half* aptr = A + (size_t)(av ? (m0 + tid) : 0) * lda;
    const __half* bptr = nullptr;
    bool bv = true;
    if (TB) {
        bv = (n0 + tid) < N;
        bptr = B + (size_t)(bv ? (n0 + tid) : 0) * ldb;
    }

    float acc[4][NTW][4];
#pragma unroll
    for (int mt = 0; mt < 4; mt++)
#pragma unroll
        for (int nt = 0; nt < NTW; nt++)
#pragma unroll
            for (int r = 0; r < 4; r++) acc[mt][nt][r] = 0.f;

    auto issue = [&](int lt) {
        int s = lt % NSTG;
        unsigned ab = smb + (unsigned)s * STG;
        const __half* as = aptr + lt * BKH;
        unsigned arow = ab + (unsigned)tid * (ASTH * 2);
#pragma unroll
        for (int c = 0; c < 8; c++)
            cpa16(arow + c * 16, as + c * 8, av);
        unsigned bb = ab + ASZB;
        if (TB) {
            const __half* bs = bptr + lt * BKH;
            unsigned br = bb + (unsigned)tid * (ASTH * 2);
#pragma unroll
            for (int c = 0; c < 8; c++)
                cpa16(br + c * 16, bs + c * 8, bv);
        } else {
            int row = tid >> 1;
            int cb = (tid & 1) * (NT / 16);
            const __half* bs = B + (size_t)(lt * BKH + row) * ldb + n0;
            unsigned br = bb + (unsigned)row * (BSTH * 2);
#pragma unroll
            for (int j = 0; j < NT / 16; j++)
                cpa16(br + (cb + j) * 16, bs + (cb + j) * 8, true);
        }
        cp_commit();
    };

#pragma unroll
    for (int i = 0; i < NSTG - 1; i++) {
        if (i < KT) issue(i); else cp_commit();
    }

    for (int kt = 0; kt < KT; kt++) {
        int b = kt % NSTG;
        asm volatile("cp.async.wait_group %0;\n" :: "n"(NSTG - 2));
        __syncthreads();
        if (kt + NSTG - 1 < KT) issue(kt + NSTG - 1); else cp_commit();

        unsigned aBase = smb + (unsigned)b * STG;
        unsigned bBase = aBase + ASZB;
#pragma unroll
        for (int ks = 0; ks < 4; ks++) {
            unsigned afr[4][4];
#pragma unroll
            for (int mt = 0; mt < 4; mt++) {
                int row = warpM * 64 + mt * 16 + (lane & 15);
                int kh = ks * 16 + ((lane >> 4) << 3);
                ldsm4(afr[mt][0], afr[mt][1], afr[mt][2], afr[mt][3],
                      aBase + (unsigned)(row * ASTH + kh) * 2);
            }
            unsigned bfr[NTW][2];
#pragma unroll
            for (int ntp = 0; ntp < NTW / 2; ntp++) {
                unsigned r0, r1, r2, r3;
                if (TB) {
                    int row = warpN * 64 + ntp * 16 + (lane & 15);
                    int kh = ks * 16 + ((lane >> 4) << 3);
                    ldsm4(r0, r1, r2, r3, bBase + (unsigned)(row * ASTH + kh) * 2);
                    bfr[2 * ntp][0] = r0; bfr[2 * ntp + 1][0] = r1;
                    bfr[2 * ntp][1] = r2; bfr[2 * ntp + 1][1] = r3;
                } else {
                    int krow = ks * 16 + (lane & 15);
                    int col = warpN * (NT / 2) + ntp * 16 + ((lane >> 4) << 3);
                    ldsm4t(r0, r1, r2, r3, bBase + (unsigned)(krow * BSTH + col) * 2);
                    bfr[2 * ntp][0] = r0; bfr[2 * ntp][1] = r1;
                    bfr[2 * ntp + 1][0] = r2; bfr[2 * ntp + 1][1] = r3;
                }
            }
#pragma unroll
            for (int mt = 0; mt < 4; mt++)
#pragma unroll
                for (int nt = 0; nt < NTW; nt++)
                    mma16816(acc[mt][nt], afr[mt], bfr[nt]);
        }
        __syncthreads();
    }

#pragma unroll
    for (int mt = 0; mt < 4; mt++) {
#pragma unroll
        for (int half_ = 0; half_ < 2; half_++) {
            int r = m0 + warpM * 64 + mt * 16 + g + half_ * 8;
            float rsum = 0.f;
#pragma unroll
            for (int nt = 0; nt < NTW; nt++) {
                int col = n0 + warpN * (NT / 2) + nt * 8 + 2 * t;
                if (r < M && col < N) {
                    float v0 = acc[mt][nt][half_ * 2 + 0];
                    float v1 = acc[mt][nt][half_ * 2 + 1];
                    size_t cidx = (size_t)(zo * cO + zi * cI) + (size_t)r * ldc + col;
                    if (EPI == 0) {
                        *(__half2*)((__half*)Cv + cidx) = __floats2half2_rn(v0, v1);
                    } else if (EPI == 1) {
                        float2 ad = *(const float2*)(addpF + (size_t)r * ldc + col);
                        float2 o; o.x = v0 + ad.x; o.y = v1 + ad.y;
                        *(float2*)((float*)Cv + cidx) = o;
                    } else if (EPI == 2) {
                        float2 o; o.x = v0; o.y = v1;
                        *(float2*)((float*)Cv + cidx) = o;
                    } else if (EPI == 3) {
                        float e0 = (col     <= r) ? __expf(v0 * 0.125f) : 0.f;
                        float e1 = (col + 1 <= r) ? __expf(v1 * 0.125f) : 0.f;
                        rsum += e0 + e1;
                        *(__half2*)((__half*)Cv + cidx) = __floats2half2_rn(e0, e1);
                    } else {
                        float sc = 1.f / addpF[(size_t)z * S_ + r];
                        *(__half2*)((__half*)Cv + cidx) = __floats2half2_rn(v0 * sc, v1 * sc);
                    }
                }
            }
            if (EPI == 3) {
                rsum += __shfl_down_sync(0xffffffffu, rsum, 2);
                rsum += __shfl_down_sync(0xffffffffu, rsum, 1);
                if (t == 0 && r < M)
                    atomicAdd(&addpF[(size_t)z * S_ + r], rsum);
            }
        }
    }
}

template <int EP>
__global__ void __launch_bounds__(256, 1)
moe_hgemm(const __half* __restrict__ H, const __half* __restrict__ W,
          const float* __restrict__ Bias, int Kdim, int Ndim) {
    constexpr int BSTH = 264;
    constexpr int BSZB = 64 * BSTH * 2;
    constexpr int STG  = ASZB + BSZB;
    extern __shared__ __align__(16) unsigned char smraw[];

    int e = blockIdx.z;
    int base = g_offs[e], cnt = g_offs[e + 1] - base;
    int m0 = blockIdx.y * 128;
    if (m0 >= cnt) return;
    int n0 = blockIdx.x * 256;
    const __half* Bmat = W + (size_t)e * (size_t)Kdim * Ndim;

    int tid = threadIdx.x, wid = tid >> 5, lane = tid & 31;
    int warpM = wid & 1, warpN = wid >> 1;
    int g = lane >> 2, t = lane & 3;
    unsigned smb = (unsigned)__cvta_generic_to_shared(smraw);
    float* sBias = (float*)smraw;
    unsigned tb0 = smb + 1024;

    sBias[tid] = Bias[(size_t)e * Ndim + n0 + tid];

    int arow_i = tid >> 1;
    bool av = (m0 + arow_i) < cnt;
    const __half* aptr;
    if (EP == 1) aptr = H + (size_t)(av ? g_perm[base + m0 + arow_i] : 0) * Kdim;
    else         aptr = g_act + (size_t)(av ? (base + m0 + arow_i) : 0) * Kdim;
    int ahalf = (tid & 1) * 32;

    int brow = tid >> 2, bq = tid & 3;

    float acc[4][8][4];
#pragma unroll
    for (int mt = 0; mt < 4; mt++)
#pragma unroll
        for (int nt = 0; nt < 8; nt++)
#pragma unroll
            for (int r = 0; r < 4; r++) acc[mt][nt][r] = 0.f;

    int KT = Kdim / BKH;

    auto issue = [&](int lt) {
        int s = lt % NSTG;
        unsigned ab = tb0 + (unsigned)s * STG;
        const __half* as = aptr + lt * BKH + ahalf;
        unsigned ar = ab + (unsigned)arow_i * (ASTH * 2) + (unsigned)(tid & 1) * 64;
#pragma unroll
        for (int c = 0; c < 4; c++)
            cpa16(ar + c * 16, as + c * 8, av);
        unsigned bb = ab + ASZB;
        const __half* bs = Bmat + (size_t)(lt * BKH + brow) * Ndim + n0 + bq * 64;
        unsigned br = bb + (unsigned)brow * (BSTH * 2) + (unsigned)bq * 128;
#pragma unroll
        for (int c = 0; c < 8; c++)
            cpa16(br + c * 16, bs + c * 8, true);
        cp_commit();
    };

#pragma unroll
    for (int i = 0; i < NSTG - 1; i++) {
        if (i < KT) issue(i); else cp_commit();
    }

    for (int kt = 0; kt < KT; kt++) {
        int b = kt % NSTG;
        asm volatile("cp.async.wait_group %0;\n" :: "n"(NSTG - 2));
        __syncthreads();
        if (kt + NSTG - 1 < KT) issue(kt + NSTG - 1); else cp_commit();

        unsigned aBase = tb0 + (unsigned)b * STG;
        unsigned bBase = aBase + ASZB;
#pragma unroll
        for (int ks = 0; ks < 4; ks++) {
            unsigned afr[4][4];
#pragma unroll
            for (int mt = 0; mt < 4; mt++) {
                int row = warpM * 64 + mt * 16 + (lane & 15);
                int kh = ks * 16 + ((lane >> 4) << 3);
                ldsm4(afr[mt][0], afr[mt][1], afr[mt][2], afr[mt][3],
                      aBase + (unsigned)(row * ASTH + kh) * 2);
            }
            unsigned bfr[8][2];
#pragma unroll
            for (int ntp = 0; ntp < 4; ntp++) {
                unsigned r0, r1, r2, r3;
                int krow = ks * 16 + (lane & 15);
                int col = warpN * 64 + ntp * 16 + ((lane >> 4) << 3);
                ldsm4t(r0, r1, r2, r3, bBase + (unsigned)(krow * BSTH + col) * 2);
                bfr[2 * ntp][0] = r0; bfr[2 * ntp][1] = r1;
                bfr[2 * ntp + 1][0] = r2; bfr[2 * ntp + 1][1] = r3;
            }
#pragma unroll
            for (int mt = 0; mt < 4; mt++)
#pragma unroll
                for (int nt = 0; nt < 8; nt++)
                    mma16816(acc[mt][nt], afr[mt], bfr[nt]);
        }
        __syncthreads();
    }

#pragma unroll
    for (int mt = 0; mt < 4; mt++) {
#pragma unroll
        for (int nt = 0; nt < 8; nt++) {
            int rr = m0 + warpM * 64 + mt * 16 + g;
            int colL = warpN * 64 + nt * 8 + 2 * t;
            int col = n0 + colL;
#pragma unroll
            for (int half_ = 0; half_ < 2; half_++) {
                int r = rr + half_ * 8;
                if (r < cnt) {
                    float v0 = acc[mt][nt][half_ * 2 + 0] + sBias[colL];
                    float v1 = acc[mt][nt][half_ * 2 + 1] + sBias[colL + 1];
                    if (EP == 1) {
                        *(__half2*)(g_act + (size_t)(base + r) * FF_ + col) =
                            __floats2half2_rn(gelu_tanh(v0), gelu_tanh(v1));
                    } else {
                        float2 o; o.x = v0; o.y = v1;
                        *(float2*)(g_y + (size_t)(base + r) * D_ + col) = o;
                    }
                }
            }
        }
    }
}

#define SMEM_NF128 (NSTG * (ASZB + 64 * 136 * 2))
#define SMEM_T128  (NSTG * (ASZB + ASZB))
#define SMEM_NF64  (NSTG * (ASZB + 64 * 72 * 2))
#define SMEM_MOE   (1024 + NSTG * (ASZB + 64 * 264 * 2))

extern "C" void kernel_launch(void* const* d_in, const int* in_sizes, int n_in,
                              void* d_out, int out_size) {
    const float* x   = (const float*)d_in[0];
    const float* anw = (const float*)d_in[1];
    const float* wq  = (const float*)d_in[2];
    const float* wk  = (const float*)d_in[3];
    const float* wv  = (const float*)d_in[4];
    const float* wo  = (const float*)d_in[5];
    const float* mnw = (const float*)d_in[6];
    const float* rw  = (const float*)d_in[7];
    const float* w1  = (const float*)d_in[8];
    const float* b1  = (const float*)d_in[9];
    const float* w2  = (const float*)d_in[10];
    const float* b2  = (const float*)d_in[11];
    float* out = (float*)d_out;

    cudaFuncSetAttribute(hgemm<false, 128, 0>, cudaFuncAttributeMaxDynamicSharedMemorySize, SMEM_NF128);
    cudaFuncSetAttribute(hgemm<false, 128, 1>, cudaFuncAttributeMaxDynamicSharedMemorySize, SMEM_NF128);
    cudaFuncSetAttribute(hgemm<true, 128, 3>,  cudaFuncAttributeMaxDynamicSharedMemorySize, SMEM_T128);
    cudaFuncSetAttribute(hgemm<false, 64, 4>,  cudaFuncAttributeMaxDynamicSharedMemorySize, SMEM_NF64);
    cudaFuncSetAttribute(moe_hgemm<1>,         cudaFuncAttributeMaxDynamicSharedMemorySize, SMEM_MOE);
    cudaFuncSetAttribute(moe_hgemm<2>,         cudaFuncAttributeMaxDynamicSharedMemorySize, SMEM_MOE);

    __half *xn, *wqkvh, *woh, *w1h, *w2h, *qkv, *probsH, *ao, *htf;
    float *x2, *rsum;
    cudaGetSymbolAddress((void**)&xn,     g_xn);
    cudaGetSymbolAddress((void**)&wqkvh,  g_wqkvh);
    cudaGetSymbolAddress((void**)&woh,    g_woh);
    cudaGetSymbolAddress((void**)&w1h,    g_w1h);
    cudaGetSymbolAddress((void**)&w2h,    g_w2h);
    cudaGetSymbolAddress((void**)&qkv,    g_qkv);
    cudaGetSymbolAddress((void**)&probsH, g_probsH);
    cudaGetSymbolAddress((void**)&rsum,   g_rowsum);
    cudaGetSymbolAddress((void**)&ao,     g_attnout);
    cudaGetSymbolAddress((void**)&x2,     g_x2);
    cudaGetSymbolAddress((void**)&htf,    g_htf);

    const __half* q = qkv;
    const __half* k = qkv + (size_t)NTOK * D_;
    const __half* v = qkv + 2 * (size_t)NTOK * D_;

    cudaStream_t s2;
    cudaEvent_t evFork, evJoin;
    cudaStreamCreateWithFlags(&s2, cudaStreamNonBlocking);
    cudaEventCreateWithFlags(&evFork, cudaEventDisableTiming);
    cudaEventCreateWithFlags(&evJoin, cudaEventDisableTiming);

    init2_kernel<<<(BB_ * NH_ * S_ + 511) / 512, 512>>>();
    cudaEventRecord(evFork, 0);
    cudaStreamWaitEvent(s2, evFork, 0);

    f2h_kernel<<<4096, 256, 0, s2>>>((const float4*)w1, (uint4*)w1h, (long long)E_ * D_ * FF_ / 8);
    f2h_kernel<<<4096, 256, 0, s2>>>((const float4*)w2, (uint4*)w2h, (long long)E_ * FF_ * D_ / 8);
    cudaEventRecord(evJoin, s2);

    f2h4_kernel<<<dim3(256, 4), 256>>>((const float4*)wq, (const float4*)wk,
                                       (const float4*)wv, (const float4*)wo,
                                       (uint4*)wqkvh, (uint4*)woh);
    rmsnorm_kernel<<<NTOK, 256>>>(x, anw, xn);

    hgemm<false, 128, 0><<<dim3(8, 16, 3), 128, SMEM_NF128>>>(
        xn, D_, wqkvh, D_, qkv, D_, NTOK, D_, D_,
        0, 0, (long long)D_ * D_, 0, (long long)NTOK * D_, 0, 1, nullptr, 0);

    {
        long long sSD = (long long)S_ * D_, sSS = (long long)S_ * S_;
        hgemm<true, 128, 3><<<dim3(8, 8, BB_ * NH_), 128, SMEM_T128>>>(
            q, D_, k, D_, probsH, S_, S_, S_, DH_,
            sSD, DH_, sSD, DH_, NH_ * sSS, sSS, NH_, rsum, 1);
    }

    {
        long long sSD = (long long)S_ * D_, sSS = (long long)S_ * S_;
        hgemm<false, 64, 4><<<dim3(1, 8, BB_ * NH_), 128, SMEM_NF64>>>(
            probsH, S_, v, D_, ao, D_, S_, DH_, S_,
            NH_ * sSS, sSS, sSD, DH_, sSD, DH_, NH_, rsum, 2);
    }

    hgemm<false, 128, 1><<<dim3(8, 16, 1), 128, SMEM_NF128>>>(
        ao, D_, woh, D_, x2, D_, NTOK, D_, D_,
        0, 0, 0, 0, 0, 0, 1, (float*)x, 0);

    rmsrouter_kernel<<<NTOK, 256>>>(x2, mnw, htf, rw);
    scan_kernel<<<1, 1>>>();
    place_kernel<<<(NTOK + 255) / 256, 256>>>();

    cudaStreamWaitEvent(0, evJoin, 0);

    moe_hgemm<1><<<dim3(FF_ / 256, NSLOT / 128, E_), 256, SMEM_MOE>>>(htf, w1h, b1, D_, FF_);
    moe_hgemm<2><<<dim3(D_ / 256, NSLOT / 128, E_), 256, SMEM_MOE>>>(nullptr, w2h, b2, FF_, D_);

    combine_kernel<<<(NTOK * D_ + 255) / 256, 256>>>(out);
    finalize_kernel<<<1, 32>>>(out);
}

// round 14
// speedup vs baseline: 1.5884x; 1.0083x over previous
#include <cuda_runtime.h>
#include <cuda_fp16.h>
#include <math.h>
#include <stdint.h>

#define D_    1024
#define S_    1024
#define BB_   2
#define NTOK  2048
#define NH_   16
#define DH_   64
#define E_    8
#define KSEL  2
#define FF_   4096
#define NSLOT 4096

#define BKH   64
#define ASTH  72
#define ASZB  (128*ASTH*2)
#define NSTG  3

__device__ __half g_xn[NTOK * D_];
__device__ __half g_wqkvh[3 * D_ * D_];
__device__ __half g_woh[D_ * D_];
__device__ __half g_w1h[(size_t)E_ * D_ * FF_];
__device__ __half g_w2h[(size_t)E_ * FF_ * D_];
__device__ __half g_qkv[3 * NTOK * D_];
__device__ __half g_probsH[(size_t)BB_ * NH_ * S_ * S_];
__device__ float  g_rowsum[BB_ * NH_ * S_];
__device__ __half g_attnout[NTOK * D_];
__device__ float  g_x2[NTOK * D_];
__device__ __half g_htf[NTOK * D_];
__device__ __half g_act[(size_t)NSLOT * FF_];
__device__ __half g_y[(size_t)NSLOT * D_];
__device__ float g_topval[NTOK * KSEL];
__device__ int   g_topidx[NTOK * KSEL];
__device__ int   g_slotof[NTOK * KSEL];
__device__ int   g_perm[NSLOT];
__device__ int   g_counts[E_];
__device__ int   g_offs[E_ + 1];
__device__ int   g_cursor[E_];
__device__ float g_probsum[E_];

__device__ __forceinline__ float gelu_tanh(float v) {
    float v3 = v * v * v;
    return 0.5f * v * (1.f + tanhf(0.7978845608028654f * (v + 0.044715f * v3)));
}
__device__ __forceinline__ void cpa16(unsigned dst, const void* src, bool p) {
    int sz = p ? 16 : 0;
    asm volatile("cp.async.cg.shared.global [%0], [%1], 16, %2;\n"
                 :: "r"(dst), "l"(src), "r"(sz));
}
__device__ __forceinline__ void cp_commit() { asm volatile("cp.async.commit_group;\n"); }
__device__ __forceinline__ void ldsm4(unsigned& r0, unsigned& r1, unsigned& r2, unsigned& r3,
                                      unsigned addr) {
    asm volatile("ldmatrix.sync.aligned.m8n8.x4.shared.b16 {%0,%1,%2,%3}, [%4];"
                 : "=r"(r0), "=r"(r1), "=r"(r2), "=r"(r3) : "r"(addr));
}
__device__ __forceinline__ void ldsm4t(unsigned& r0, unsigned& r1, unsigned& r2, unsigned& r3,
                                       unsigned addr) {
    asm volatile("ldmatrix.sync.aligned.m8n8.x4.trans.shared.b16 {%0,%1,%2,%3}, [%4];"
                 : "=r"(r0), "=r"(r1), "=r"(r2), "=r"(r3) : "r"(addr));
}
__device__ __forceinline__ void mma16816(float* d, const unsigned* a, const unsigned* b) {
    asm volatile(
        "mma.sync.aligned.m16n8k16.row.col.f32.f16.f16.f32 "
        "{%0,%1,%2,%3}, {%4,%5,%6,%7}, {%8,%9}, {%0,%1,%2,%3};"
        : "+f"(d[0]), "+f"(d[1]), "+f"(d[2]), "+f"(d[3])
        : "r"(a[0]), "r"(a[1]), "r"(a[2]), "r"(a[3]), "r"(b[0]), "r"(b[1]));
}

__global__ void init2_kernel() {
    int i = blockIdx.x * 512 + threadIdx.x;
    if (i < E_) { g_counts[i] = 0; g_cursor[i] = 0; g_probsum[i] = 0.f; }
    if (i < BB_ * NH_ * S_) g_rowsum[i] = 0.f;
}

__global__ void f2h_kernel(const float4* __restrict__ in, uint4* __restrict__ out,
                           long long n8) {
    for (long long i = blockIdx.x * 256LL + threadIdx.x; i < n8;
         i += (long long)gridDim.x * 256) {
        float4 a = in[2 * i], b = in[2 * i + 1];
        __half2 h0 = __floats2half2_rn(a.x, a.y);
        __half2 h1 = __floats2half2_rn(a.z, a.w);
        __half2 h2 = __floats2half2_rn(b.x, b.y);
        __half2 h3 = __floats2half2_rn(b.z, b.w);
        uint4 o;
        o.x = *(unsigned*)&h0; o.y = *(unsigned*)&h1;
        o.z = *(unsigned*)&h2; o.w = *(unsigned*)&h3;
        out[i] = o;
    }
}
__global__ void f2h4_kernel(const float4* __restrict__ a, const float4* __restrict__ b,
                            const float4* __restrict__ c, const float4* __restrict__ d,
                            uint4* __restrict__ oqkv, uint4* __restrict__ oo) {
    const float4* src[4] = { a, b, c, d };
    long long n8 = (long long)D_ * D_ / 8;
    uint4* dst;
    int z = blockIdx.y;
    if (z < 3) dst = oqkv + (size_t)z * n8;
    else       dst = oo;
    const float4* in = src[z];
    for (long long i = blockIdx.x * 256LL + threadIdx.x; i < n8;
         i += (long long)gridDim.x * 256) {
        float4 va = in[2 * i], vb = in[2 * i + 1];
        __half2 h0 = __floats2half2_rn(va.x, va.y);
        __half2 h1 = __floats2half2_rn(va.z, va.w);
        __half2 h2 = __floats2half2_rn(vb.x, vb.y);
        __half2 h3 = __floats2half2_rn(vb.z, vb.w);
        uint4 o;
        o.x = *(unsigned*)&h0; o.y = *(unsigned*)&h1;
        o.z = *(unsigned*)&h2; o.w = *(unsigned*)&h3;
        dst[i] = o;
    }
}
__global__ void rmsnorm_kernel(const float* __restrict__ X, const float* __restrict__ W,
                               __half* __restrict__ OT) {
    int t = blockIdx.x;
    const float* x = X + (size_t)t * D_;
    float ss = 0.f;
    for (int d = threadIdx.x; d < D_; d += 256) { float v = x[d]; ss += v * v; }
    __shared__ float red[256];
    red[threadIdx.x] = ss; __syncthreads();
    for (int s = 128; s > 0; s >>= 1) {
        if (threadIdx.x < s) red[threadIdx.x] += red[threadIdx.x + s];
        __syncthreads();
    }
    float scale = rsqrtf(red[0] * (1.f / D_) + 1e-6f);
    for (int d = threadIdx.x; d < D_; d += 256)
        OT[(size_t)t * D_ + d] = __float2half_rn(x[d] * scale * W[d]);
}

// fused rmsnorm(x2) -> htf + router
__global__ void rmsrouter_kernel(const float* __restrict__ X, const float* __restrict__ W,
                                 __half* __restrict__ OT, const float* __restrict__ RW) {
    int t = blockIdx.x;
    int tid = threadIdx.x;
    const float* x = X + (size_t)t * D_;
    __shared__ float hv[D_];
    __shared__ float red[256];
    float ss = 0.f;
    for (int d = tid; d < D_; d += 256) { float v = x[d]; ss += v * v; }
    red[tid] = ss; __syncthreads();
    for (int s = 128; s > 0; s >>= 1) {
        if (tid < s) red[tid] += red[tid + s];
        __syncthreads();
    }
    float scale = rsqrtf(red[0] * (1.f / D_) + 1e-6f);
    for (int d = tid; d < D_; d += 256) {
        float v = x[d] * scale * W[d];
        hv[d] = v;
        OT[(size_t)t * D_ + d] = __float2half_rn(v);
    }
    __syncthreads();

    int e = tid >> 5, lane = tid & 31;
    float p = 0.f;
    for (int d = lane; d < D_; d += 32) p += hv[d] * RW[d * E_ + e];
    for (int o = 16; o > 0; o >>= 1) p += __shfl_down_sync(0xffffffff, p, o);
    __shared__ float lg[E_];
    if (lane == 0) lg[e] = p;
    __syncthreads();
    if (tid == 0) {
        float mx = lg[0];
        for (int i = 1; i < E_; i++) mx = fmaxf(mx, lg[i]);
        float pr[E_]; float s = 0.f;
        for (int i = 0; i < E_; i++) { pr[i] = expf(lg[i] - mx); s += pr[i]; }
        float inv = 1.f / s;
        float b1v = -1.f, b2v = -1.f; int b1i = 0, b2i = 0;
        for (int i = 0; i < E_; i++) {
            float v = pr[i] * inv;
            atomicAdd(&g_probsum[i], v);
            if (v > b1v) { b2v = b1v; b2i = b1i; b1v = v; b1i = i; }
            else if (v > b2v) { b2v = v; b2i = i; }
        }
        g_topidx[t * 2] = b1i; g_topidx[t * 2 + 1] = b2i;
        g_topval[t * 2] = b1v; g_topval[t * 2 + 1] = b2v;
        atomicAdd(&g_counts[b1i], 1);
        atomicAdd(&g_counts[b2i], 1);
    }
}

// merged scan + place (single CTA)
__global__ void place1_kernel() {
    if (threadIdx.x == 0) {
        int o = 0;
        for (int e = 0; e < E_; e++) {
            g_offs[e] = o;
            g_cursor[e] = o;
            o += g_counts[e];
        }
        g_offs[E_] = o;
    }
    __syncthreads();
    for (int t = threadIdx.x; t < NTOK; t += 1024) {
        for (int kk = 0; kk < KSEL; kk++) {
            int e = g_topidx[t * 2 + kk];
            int slot = atomicAdd(&g_cursor[e], 1);
            g_perm[slot] = t;
            g_slotof[t * 2 + kk] = slot;
        }
    }
}

// 2-wide combine: half2 gathers from g_y, float2 residual/out
__global__ void combine_kernel(float* __restrict__ out) {
    int i = blockIdx.x * blockDim.x + threadIdx.x;   // pair index
    if (i >= NTOK * D_ / 2) return;
    int t = i >> 9, d2 = i & 511;
    float2 v = ((const float2*)g_x2)[i];
    float w0 = g_topval[t * 2], w1 = g_topval[t * 2 + 1];
    __half2 y0 = ((const __half2*)(g_y + (size_t)g_slotof[t * 2] * D_))[d2];
    __half2 y1 = ((const __half2*)(g_y + (size_t)g_slotof[t * 2 + 1] * D_))[d2];
    float2 f0 = __half22float2(y0), f1 = __half22float2(y1);
    v.x += w0 * f0.x + w1 * f1.x;
    v.y += w0 * f0.y + w1 * f1.y;
    ((float2*)out)[i] = v;
}
__global__ void finalize_kernel(float* __restrict__ out) {
    if (threadIdx.x == 0) {
        float loss = 0.f;
        for (int e = 0; e < E_; e++)
            loss += ((float)g_counts[e] / (float)NSLOT) * (g_probsum[e] / (float)NTOK);
        loss *= (float)E_;
        out[(size_t)NTOK * D_] = loss;
        for (int e = 0; e < E_; e++)
            out[(size_t)NTOK * D_ + 1 + e] = (float)g_counts[e];
    }
}

// EPI: 0 half; 1 float + residual(addpF=[M,N] fp32); 2 float;
//      3 half exp(v/8) causal + atomic rowsum into addpF[z*S+r];
//      4 half v / addpF[z*S+r].
// mode: 0 none, 1 causal tile-skip, 2 k-clip (modes 1/2: heavy-first y remap).
template <bool TB, int NT, int EPI>
__global__ void __launch_bounds__(128, 2)
hgemm(const __half* __restrict__ A, int lda,
      const __half* __restrict__ B, int ldb,
      void* __restrict__ Cv, int ldc,
      int M, int N, int K,
      long long aO, long long aI, long long bO, long long bI,
      long long cO, long long cI, int zdiv,
      float* __restrict__ addpF, int mode) {
    constexpr int BSTH = NT + 8;
    constexpr int BSZB = TB ? ASZB : (64 * BSTH * 2);
    constexpr int STG  = ASZB + BSZB;
    constexpr int NTW  = NT / 16;
    extern __shared__ __align__(16) unsigned char smraw[];

    int z = blockIdx.z, zo = z / zdiv, zi = z % zdiv;
    A += zo * aO + zi * aI;
    B += zo * bO + zi * bI;

    int by = mode ? ((int)gridDim.y - 1 - (int)blockIdx.y) : (int)blockIdx.y;
    int m0 = by * 128, n0 = blockIdx.x * NT;
    if (mode == 1 && n0 > m0 + 127) return;
    int Keff = (mode == 2) ? min(K, m0 + 128) : K;
    int KT = Keff / BKH;

    int tid = threadIdx.x, wid = tid >> 5, lane = tid & 31;
    int warpM = wid & 1, warpN = wid >> 1;
    int g = lane >> 2, t = lane & 3;
    unsigned smb = (unsigned)__cvta_generic_to_shared(smraw);

    bool av = (m0 + tid) < M;
    const __half* aptr = A + (size_t)(av ? (m0 + tid) : 0) * lda;
    const __half* bptr = nullptr;
    bool bv = true;
    if (TB) {
        bv = (n0 + tid) < N;
        bptr = B + (size_t)(bv ? (n0 + tid) : 0) * ldb;
    }

    float acc[4][NTW][4];
#pragma unroll
    for (int mt = 0; mt < 4; mt++)
#pragma unroll
        for (int nt = 0; nt < NTW; nt++)
#pragma unroll
            for (int r = 0; r < 4; r++) acc[mt][nt][r] = 0.f;

    auto issue = [&](int lt) {
        int s = lt % NSTG;
        unsigned ab = smb + (unsigned)s * STG;
        const __half* as = aptr + lt * BKH;
        unsigned arow = ab + (unsigned)tid * (ASTH * 2);
#pragma unroll
        for (int c = 0; c < 8; c++)
            cpa16(arow + c * 16, as + c * 8, av);
        unsigned bb = ab + ASZB;
        if (TB) {
            const __half* bs = bptr + lt * BKH;
            unsigned br = bb + (unsigned)tid * (ASTH * 2);
#pragma unroll
            for (int c = 0; c < 8; c++)
                cpa16(br + c * 16, bs + c * 8, bv);
        } else {
            int row = tid >> 1;
            int cb = (tid & 1) * (NT / 16);
            const __half* bs = B + (size_t)(lt * BKH + row) * ldb + n0;
            unsigned br = bb + (unsigned)row * (BSTH * 2);
#pragma unroll
            for (int j = 0; j < NT / 16; j++)
                cpa16(br + (cb + j) * 16, bs + (cb + j) * 8, true);
        }
        cp_commit();
    };

#pragma unroll
    for (int i = 0; i < NSTG - 1; i++) {
        if (i < KT) issue(i); else cp_commit();
    }

    for (int kt = 0; kt < KT; kt++) {
        int b = kt % NSTG;
        asm volatile("cp.async.wait_group %0;\n" :: "n"(NSTG - 2));
        __syncthreads();
        if (kt + NSTG - 1 < KT) issue(kt + NSTG - 1); else cp_commit();

        unsigned aBase = smb + (unsigned)b * STG;
        unsigned bBase = aBase + ASZB;
#pragma unroll
        for (int ks = 0; ks < 4; ks++) {
            unsigned afr[4][4];
#pragma unroll
            for (int mt = 0; mt < 4; mt++) {
                int row = warpM * 64 + mt * 16 + (lane & 15);
                int kh = ks * 16 + ((lane >> 4) << 3);
                ldsm4(afr[mt][0], afr[mt][1], afr[mt][2], afr[mt][3],
                      aBase + (unsigned)(row * ASTH + kh) * 2);
            }
            unsigned bfr[NTW][2];
#pragma unroll
            for (int ntp = 0; ntp < NTW / 2; ntp++) {
                unsigned r0, r1, r2, r3;
                if (TB) {
                    int row = warpN * 64 + ntp * 16 + (lane & 15);
                    int kh = ks * 16 + ((lane >> 4) << 3);
                    ldsm4(r0, r1, r2, r3, bBase + (unsigned)(row * ASTH + kh) * 2);
                    bfr[2 * ntp][0] = r0; bfr[2 * ntp + 1][0] = r1;
                    bfr[2 * ntp][1] = r2; bfr[2 * ntp + 1][1] = r3;
                } else {
                    int krow = ks * 16 + (lane & 15);
                    int col = warpN * (NT / 2) + ntp * 16 + ((lane >> 4) << 3);
                    ldsm4t(r0, r1, r2, r3, bBase + (unsigned)(krow * BSTH + col) * 2);
                    bfr[2 * ntp][0] = r0; bfr[2 * ntp][1] = r1;
                    bfr[2 * ntp + 1][0] = r2; bfr[2 * ntp + 1][1] = r3;
                }
            }
#pragma unroll
            for (int mt = 0; mt < 4; mt++)
#pragma unroll
                for (int nt = 0; nt < NTW; nt++)
                    mma16816(acc[mt][nt], afr[mt], bfr[nt]);
        }
        __syncthreads();
    }

#pragma unroll
    for (int mt = 0; mt < 4; mt++) {
#pragma unroll
        for (int half_ = 0; half_ < 2; half_++) {
            int r = m0 + warpM * 64 + mt * 16 + g + half_ * 8;
            float rsum = 0.f;
#pragma unroll
            for (int nt = 0; nt < NTW; nt++) {
                int col = n0 + warpN * (NT / 2) + nt * 8 + 2 * t;
                if (r < M && col < N) {
                    float v0 = acc[mt][nt][half_ * 2 + 0];
                    float v1 = acc[mt][nt][half_ * 2 + 1];
                    size_t cidx = (size_t)(zo * cO + zi * cI) + (size_t)r * ldc + col;
                    if (EPI == 0) {
                        *(__half2*)((__half*)Cv + cidx) = __floats2half2_rn(v0, v1);
                    } else if (EPI == 1) {
                        float2 ad = *(const float2*)(addpF + (size_t)r * ldc + col);
                        float2 o; o.x = v0 + ad.x; o.y = v1 + ad.y;
                        *(float2*)((float*)Cv + cidx) = o;
                    } else if (EPI == 2) {
                        float2 o; o.x = v0; o.y = v1;
                        *(float2*)((float*)Cv + cidx) = o;
                    } else if (EPI == 3) {
                        float e0 = (col     <= r) ? __expf(v0 * 0.125f) : 0.f;
                        float e1 = (col + 1 <= r) ? __expf(v1 * 0.125f) : 0.f;
                        rsum += e0 + e1;
                        *(__half2*)((__half*)Cv + cidx) = __floats2half2_rn(e0, e1);
                    } else {
                        float sc = 1.f / addpF[(size_t)z * S_ + r];
                        *(__half2*)((__half*)Cv + cidx) = __floats2half2_rn(v0 * sc, v1 * sc);
                    }
                }
            }
            if (EPI == 3) {
                rsum += __shfl_down_sync(0xffffffffu, rsum, 2);
                rsum += __shfl_down_sync(0xffffffffu, rsum, 1);
                if (t == 0 && r < M)
                    atomicAdd(&addpF[(size_t)z * S_ + r], rsum);
            }
        }
    }
}

// grouped MoE: 256 thr, 128x256, 3-stage.
// EP 1: half(gelu(acc+bias)) -> g_act. EP 2: half(acc+bias) -> g_y.
template <int EP>
__global__ void __launch_bounds__(256, 1)
moe_hgemm(const __half* __restrict__ H, const __half* __restrict__ W,
          const float* __restrict__ Bias, int Kdim, int Ndim) {
    constexpr int BSTH = 264;
    constexpr int BSZB = 64 * BSTH * 2;
    constexpr int STG  = ASZB + BSZB;
    extern __shared__ __align__(16) unsigned char smraw[];

    int e = blockIdx.z;
    int base = g_offs[e], cnt = g_offs[e + 1] - base;
    int m0 = blockIdx.y * 128;
    if (m0 >= cnt) return;
    int n0 = blockIdx.x * 256;
    const __half* Bmat = W + (size_t)e * (size_t)Kdim * Ndim;

    int tid = threadIdx.x, wid = tid >> 5, lane = tid & 31;
    int warpM = wid & 1, warpN = wid >> 1;
    int g = lane >> 2, t = lane & 3;
    unsigned smb = (unsigned)__cvta_generic_to_shared(smraw);
    float* sBias = (float*)smraw;
    unsigned tb0 = smb + 1024;

    sBias[tid] = Bias[(size_t)e * Ndim + n0 + tid];

    int arow_i = tid >> 1;
    bool av = (m0 + arow_i) < cnt;
    const __half* aptr;
    if (EP == 1) aptr = H + (size_t)(av ? g_perm[base + m0 + arow_i] : 0) * Kdim;
    else         aptr = g_act + (size_t)(av ? (base + m0 + arow_i) : 0) * Kdim;
    int ahalf = (tid & 1) * 32;

    int brow = tid >> 2, bq = tid & 3;

    float acc[4][8][4];
#pragma unroll
    for (int mt = 0; mt < 4; mt++)
#pragma unroll
        for (int nt = 0; nt < 8; nt++)
#pragma unroll
            for (int r = 0; r < 4; r++) acc[mt][nt][r] = 0.f;

    int KT = Kdim / BKH;

    auto issue = [&](int lt) {
        int s = lt % NSTG;
        unsigned ab = tb0 + (unsigned)s * STG;
        const __half* as = aptr + lt * BKH + ahalf;
        unsigned ar = ab + (unsigned)arow_i * (ASTH * 2) + (unsigned)(tid & 1) * 64;
#pragma unroll
        for (int c = 0; c < 4; c++)
            cpa16(ar + c * 16, as + c * 8, av);
        unsigned bb = ab + ASZB;
        const __half* bs = Bmat + (size_t)(lt * BKH + brow) * Ndim + n0 + bq * 64;
        unsigned br = bb + (unsigned)brow * (BSTH * 2) + (unsigned)bq * 128;
#pragma unroll
        for (int c = 0; c < 8; c++)
            cpa16(br + c * 16, bs + c * 8, true);
        cp_commit();
    };

#pragma unroll
    for (int i = 0; i < NSTG - 1; i++) {
        if (i < KT) issue(i); else cp_commit();
    }

    for (int kt = 0; kt < KT; kt++) {
        int b = kt % NSTG;
        asm volatile("cp.async.wait_group %0;\n" :: "n"(NSTG - 2));
        __syncthreads();
        if (kt + NSTG - 1 < KT) issue(kt + NSTG - 1); else cp_commit();

        unsigned aBase = tb0 + (unsigned)b * STG;
        unsigned bBase = aBase + ASZB;
#pragma unroll
        for (int ks = 0; ks < 4; ks++) {
            unsigned afr[4][4];
#pragma unroll
            for (int mt = 0; mt < 4; mt++) {
                int row = warpM * 64 + mt * 16 + (lane & 15);
                int kh = ks * 16 + ((lane >> 4) << 3);
                ldsm4(afr[mt][0], afr[mt][1], afr[mt][2], afr[mt][3],
                      aBase + (unsigned)(row * ASTH + kh) * 2);
            }
            unsigned bfr[8][2];
#pragma unroll
            for (int ntp = 0; ntp < 4; ntp++) {
                unsigned r0, r1, r2, r3;
                int krow = ks * 16 + (lane & 15);
                int col = warpN * 64 + ntp * 16 + ((lane >> 4) << 3);
                ldsm4t(r0, r1, r2, r3, bBase + (unsigned)(krow * BSTH + col) * 2);
                bfr[2 * ntp][0] = r0; bfr[2 * ntp][1] = r1;
                bfr[2 * ntp + 1][0] = r2; bfr[2 * ntp + 1][1] = r3;
            }
#pragma unroll
            for (int mt = 0; mt < 4; mt++)
#pragma unroll
                for (int nt = 0; nt < 8; nt++)
                    mma16816(acc[mt][nt], afr[mt], bfr[nt]);
        }
        __syncthreads();
    }

#pragma unroll
    for (int mt = 0; mt < 4; mt++) {
#pragma unroll
        for (int nt = 0; nt < 8; nt++) {
            int rr = m0 + warpM * 64 + mt * 16 + g;
            int colL = warpN * 64 + nt * 8 + 2 * t;
            int col = n0 + colL;
#pragma unroll
            for (int half_ = 0; half_ < 2; half_++) {
                int r = rr + half_ * 8;
                if (r < cnt) {
                    float v0 = acc[mt][nt][half_ * 2 + 0] + sBias[colL];
                    float v1 = acc[mt][nt][half_ * 2 + 1] + sBias[colL + 1];
                    if (EP == 1) {
                        *(__half2*)(g_act + (size_t)(base + r) * FF_ + col) =
                            __floats2half2_rn(gelu_tanh(v0), gelu_tanh(v1));
                    } else {
                        *(__half2*)(g_y + (size_t)(base + r) * D_ + col) =
                            __floats2half2_rn(v0, v1);
                    }
                }
            }
        }
    }
}

#define SMEM_NF128 (NSTG * (ASZB + 64 * 136 * 2))
#define SMEM_T128  (NSTG * (ASZB + ASZB))
#define SMEM_NF64  (NSTG * (ASZB + 64 * 72 * 2))
#define SMEM_MOE   (1024 + NSTG * (ASZB + 64 * 264 * 2))

extern "C" void kernel_launch(void* const* d_in, const int* in_sizes, int n_in,
                              void* d_out, int out_size) {
    const float* x   = (const float*)d_in[0];
    const float* anw = (const float*)d_in[1];
    const float* wq  = (const float*)d_in[2];
    const float* wk  = (const float*)d_in[3];
    const float* wv  = (const float*)d_in[4];
    const float* wo  = (const float*)d_in[5];
    const float* mnw = (const float*)d_in[6];
    const float* rw  = (const float*)d_in[7];
    const float* w1  = (const float*)d_in[8];
    const float* b1  = (const float*)d_in[9];
    const float* w2  = (const float*)d_in[10];
    const float* b2  = (const float*)d_in[11];
    float* out = (float*)d_out;

    cudaFuncSetAttribute(hgemm<false, 128, 0>, cudaFuncAttributeMaxDynamicSharedMemorySize, SMEM_NF128);
    cudaFuncSetAttribute(hgemm<false, 128, 1>, cudaFuncAttributeMaxDynamicSharedMemorySize, SMEM_NF128);
    cudaFuncSetAttribute(hgemm<true, 128, 3>,  cudaFuncAttributeMaxDynamicSharedMemorySize, SMEM_T128);
    cudaFuncSetAttribute(hgemm<false, 64, 4>,  cudaFuncAttributeMaxDynamicSharedMemorySize, SMEM_NF64);
    cudaFuncSetAttribute(moe_hgemm<1>,         cudaFuncAttributeMaxDynamicSharedMemorySize, SMEM_MOE);
    cudaFuncSetAttribute(moe_hgemm<2>,         cudaFuncAttributeMaxDynamicSharedMemorySize, SMEM_MOE);

    __half *xn, *wqkvh, *woh, *w1h, *w2h, *qkv, *probsH, *ao, *htf;
    float *x2, *rsum;
    cudaGetSymbolAddress((void**)&xn,     g_xn);
    cudaGetSymbolAddress((void**)&wqkvh,  g_wqkvh);
    cudaGetSymbolAddress((void**)&woh,    g_woh);
    cudaGetSymbolAddress((void**)&w1h,    g_w1h);
    cudaGetSymbolAddress((void**)&w2h,    g_w2h);
    cudaGetSymbolAddress((void**)&qkv,    g_qkv);
    cudaGetSymbolAddress((void**)&probsH, g_probsH);
    cudaGetSymbolAddress((void**)&rsum,   g_rowsum);
    cudaGetSymbolAddress((void**)&ao,     g_attnout);
    cudaGetSymbolAddress((void**)&x2,     g_x2);
    cudaGetSymbolAddress((void**)&htf,    g_htf);

    const __half* q = qkv;
    const __half* k = qkv + (size_t)NTOK * D_;
    const __half* v = qkv + 2 * (size_t)NTOK * D_;

    cudaStream_t s2;
    cudaEvent_t evFork, evJoin;
    cudaStreamCreateWithFlags(&s2, cudaStreamNonBlocking);
    cudaEventCreateWithFlags(&evFork, cudaEventDisableTiming);
    cudaEventCreateWithFlags(&evJoin, cudaEventDisableTiming);

    init2_kernel<<<(BB_ * NH_ * S_ + 511) / 512, 512>>>();
    cudaEventRecord(evFork, 0);
    cudaStreamWaitEvent(s2, evFork, 0);

    f2h_kernel<<<4096, 256, 0, s2>>>((const float4*)w1, (uint4*)w1h, (long long)E_ * D_ * FF_ / 8);
    f2h_kernel<<<4096, 256, 0, s2>>>((const float4*)w2, (uint4*)w2h, (long long)E_ * FF_ * D_ / 8);
    cudaEventRecord(evJoin, s2);

    f2h4_kernel<<<dim3(256, 4), 256>>>((const float4*)wq, (const float4*)wk,
                                       (const float4*)wv, (const float4*)wo,
                                       (uint4*)wqkvh, (uint4*)woh);
    rmsnorm_kernel<<<NTOK, 256>>>(x, anw, xn);

    hgemm<false, 128, 0><<<dim3(8, 16, 3), 128, SMEM_NF128>>>(
        xn, D_, wqkvh, D_, qkv, D_, NTOK, D_, D_,
        0, 0, (long long)D_ * D_, 0, (long long)NTOK * D_, 0, 1, nullptr, 0);

    {
        long long sSD = (long long)S_ * D_, sSS = (long long)S_ * S_;
        hgemm<true, 128, 3><<<dim3(8, 8, BB_ * NH_), 128, SMEM_T128>>>(
            q, D_, k, D_, probsH, S_, S_, S_, DH_,
            sSD, DH_, sSD, DH_, NH_ * sSS, sSS, NH_, rsum, 1);
    }

    {
        long long sSD = (long long)S_ * D_, sSS = (long long)S_ * S_;
        hgemm<false, 64, 4><<<dim3(1, 8, BB_ * NH_), 128, SMEM_NF64>>>(
            probsH, S_, v, D_, ao, D_, S_, DH_, S_,
            NH_ * sSS, sSS, sSD, DH_, sSD, DH_, NH_, rsum, 2);
    }

    hgemm<false, 128, 1><<<dim3(8, 16, 1), 128, SMEM_NF128>>>(
        ao, D_, woh, D_, x2, D_, NTOK, D_, D_,
        0, 0, 0, 0, 0, 0, 1, (float*)x, 0);

    rmsrouter_kernel<<<NTOK, 256>>>(x2, mnw, htf, rw);
    place1_kernel<<<1, 1024>>>();

    cudaStreamWaitEvent(0, evJoin, 0);

    moe_hgemm<1><<<dim3(FF_ / 256, NSLOT / 128, E_), 256, SMEM_MOE>>>(htf, w1h, b1, D_, FF_);
    moe_hgemm<2><<<dim3(D_ / 256, NSLOT / 128, E_), 256, SMEM_MOE>>>(nullptr, w2h, b2, FF_, D_);

    combine_kernel<<<(NTOK * D_ / 2 + 255) / 256, 256>>>(out);
    finalize_kernel<<<1, 32>>>(out);
}

// round 15
// speedup vs baseline: 1.6525x; 1.0403x over previous
#include <cuda_runtime.h>
#include <cuda_fp16.h>
#include <math.h>
#include <stdint.h>

#define D_    1024
#define S_    1024
#define BB_   2
#define NTOK  2048
#define NH_   16
#define DH_   64
#define E_    8
#define KSEL  2
#define FF_   4096
#define NSLOT 4096

#define BKH   64
#define ASTH  72
#define ASZB  (128*ASTH*2)
#define NSTG  3

__device__ __half g_xn[NTOK * D_];
__device__ __half g_wqkvh[3 * D_ * D_];
__device__ __half g_woh[D_ * D_];
__device__ __half g_w1h[(size_t)E_ * D_ * FF_];
__device__ __half g_w2h[(size_t)E_ * FF_ * D_];
__device__ __half g_qkv[3 * NTOK * D_];
__device__ __half g_probsH[(size_t)BB_ * NH_ * S_ * S_];
__device__ float  g_rowsum[BB_ * NH_ * S_];
__device__ __half g_attnout[NTOK * D_];
__device__ float  g_x2[NTOK * D_];
__device__ __half g_htf[NTOK * D_];
__device__ __half g_act[(size_t)NSLOT * FF_];
__device__ __half g_y[(size_t)NSLOT * D_];
__device__ float g_topval[NTOK * KSEL];
__device__ int   g_topidx[NTOK * KSEL];
__device__ int   g_slotof[NTOK * KSEL];
__device__ int   g_perm[NSLOT];
__device__ int   g_counts[E_];
__device__ int   g_offs[E_ + 1];
__device__ int   g_cursor[E_];
__device__ float g_probsum[E_];

__device__ __forceinline__ float gelu_tanh(float v) {
    float v3 = v * v * v;
    return 0.5f * v * (1.f + tanhf(0.7978845608028654f * (v + 0.044715f * v3)));
}
__device__ __forceinline__ void cpa16(unsigned dst, const void* src, bool p) {
    int sz = p ? 16 : 0;
    asm volatile("cp.async.cg.shared.global [%0], [%1], 16, %2;\n"
                 :: "r"(dst), "l"(src), "r"(sz));
}
__device__ __forceinline__ void cp_commit() { asm volatile("cp.async.commit_group;\n"); }
__device__ __forceinline__ void ldsm4(unsigned& r0, unsigned& r1, unsigned& r2, unsigned& r3,
                                      unsigned addr) {
    asm volatile("ldmatrix.sync.aligned.m8n8.x4.shared.b16 {%0,%1,%2,%3}, [%4];"
                 : "=r"(r0), "=r"(r1), "=r"(r2), "=r"(r3) : "r"(addr));
}
__device__ __forceinline__ void ldsm4t(unsigned& r0, unsigned& r1, unsigned& r2, unsigned& r3,
                                       unsigned addr) {
    asm volatile("ldmatrix.sync.aligned.m8n8.x4.trans.shared.b16 {%0,%1,%2,%3}, [%4];"
                 : "=r"(r0), "=r"(r1), "=r"(r2), "=r"(r3) : "r"(addr));
}
__device__ __forceinline__ void mma16816(float* d, const unsigned* a, const unsigned* b) {
    asm volatile(
        "mma.sync.aligned.m16n8k16.row.col.f32.f16.f16.f32 "
        "{%0,%1,%2,%3}, {%4,%5,%6,%7}, {%8,%9}, {%0,%1,%2,%3};"
        : "+f"(d[0]), "+f"(d[1]), "+f"(d[2]), "+f"(d[3])
        : "r"(a[0]), "r"(a[1]), "r"(a[2]), "r"(a[3]), "r"(b[0]), "r"(b[1]));
}

__global__ void init2_kernel() {
    int i = blockIdx.x * 512 + threadIdx.x;
    if (i < E_) { g_counts[i] = 0; g_cursor[i] = 0; g_probsum[i] = 0.f; }
    if (i < BB_ * NH_ * S_) g_rowsum[i] = 0.f;
}

__global__ void f2h_kernel(const float4* __restrict__ in, uint4* __restrict__ out,
                           long long n8) {
    for (long long i = blockIdx.x * 256LL + threadIdx.x; i < n8;
         i += (long long)gridDim.x * 256) {
        float4 a = in[2 * i], b = in[2 * i + 1];
        __half2 h0 = __floats2half2_rn(a.x, a.y);
        __half2 h1 = __floats2half2_rn(a.z, a.w);
        __half2 h2 = __floats2half2_rn(b.x, b.y);
        __half2 h3 = __floats2half2_rn(b.z, b.w);
        uint4 o;
        o.x = *(unsigned*)&h0; o.y = *(unsigned*)&h1;
        o.z = *(unsigned*)&h2; o.w = *(unsigned*)&h3;
        out[i] = o;
    }
}
__global__ void f2h4_kernel(const float4* __restrict__ a, const float4* __restrict__ b,
                            const float4* __restrict__ c, const float4* __restrict__ d,
                            uint4* __restrict__ oqkv, uint4* __restrict__ oo) {
    const float4* src[4] = { a, b, c, d };
    long long n8 = (long long)D_ * D_ / 8;
    uint4* dst;
    int z = blockIdx.y;
    if (z < 3) dst = oqkv + (size_t)z * n8;
    else       dst = oo;
    const float4* in = src[z];
    for (long long i = blockIdx.x * 256LL + threadIdx.x; i < n8;
         i += (long long)gridDim.x * 256) {
        float4 va = in[2 * i], vb = in[2 * i + 1];
        __half2 h0 = __floats2half2_rn(va.x, va.y);
        __half2 h1 = __floats2half2_rn(va.z, va.w);
        __half2 h2 = __floats2half2_rn(vb.x, vb.y);
        __half2 h3 = __floats2half2_rn(vb.z, vb.w);
        uint4 o;
        o.x = *(unsigned*)&h0; o.y = *(unsigned*)&h1;
        o.z = *(unsigned*)&h2; o.w = *(unsigned*)&h3;
        dst[i] = o;
    }
}
__global__ void rmsnorm_kernel(const float* __restrict__ X, const float* __restrict__ W,
                               __half* __restrict__ OT) {
    int t = blockIdx.x;
    const float* x = X + (size_t)t * D_;
    float ss = 0.f;
    for (int d = threadIdx.x; d < D_; d += 256) { float v = x[d]; ss += v * v; }
    __shared__ float red[256];
    red[threadIdx.x] = ss; __syncthreads();
    for (int s = 128; s > 0; s >>= 1) {
        if (threadIdx.x < s) red[threadIdx.x] += red[threadIdx.x + s];
        __syncthreads();
    }
    float scale = rsqrtf(red[0] * (1.f / D_) + 1e-6f);
    for (int d = threadIdx.x; d < D_; d += 256)
        OT[(size_t)t * D_ + d] = __float2half_rn(x[d] * scale * W[d]);
}

// fused rmsnorm(x2) -> htf + router
__global__ void rmsrouter_kernel(const float* __restrict__ X, const float* __restrict__ W,
                                 __half* __restrict__ OT, const float* __restrict__ RW) {
    int t = blockIdx.x;
    int tid = threadIdx.x;
    const float* x = X + (size_t)t * D_;
    __shared__ float hv[D_];
    __shared__ float red[256];
    float ss = 0.f;
    for (int d = tid; d < D_; d += 256) { float v = x[d]; ss += v * v; }
    red[tid] = ss; __syncthreads();
    for (int s = 128; s > 0; s >>= 1) {
        if (tid < s) red[tid] += red[tid + s];
        __syncthreads();
    }
    float scale = rsqrtf(red[0] * (1.f / D_) + 1e-6f);
    for (int d = tid; d < D_; d += 256) {
        float v = x[d] * scale * W[d];
        hv[d] = v;
        OT[(size_t)t * D_ + d] = __float2half_rn(v);
    }
    __syncthreads();

    int e = tid >> 5, lane = tid & 31;
    float p = 0.f;
    for (int d = lane; d < D_; d += 32) p += hv[d] * RW[d * E_ + e];
    for (int o = 16; o > 0; o >>= 1) p += __shfl_down_sync(0xffffffff, p, o);
    __shared__ float lg[E_];
    if (lane == 0) lg[e] = p;
    __syncthreads();
    if (tid == 0) {
        float mx = lg[0];
        for (int i = 1; i < E_; i++) mx = fmaxf(mx, lg[i]);
        float pr[E_]; float s = 0.f;
        for (int i = 0; i < E_; i++) { pr[i] = expf(lg[i] - mx); s += pr[i]; }
        float inv = 1.f / s;
        float b1v = -1.f, b2v = -1.f; int b1i = 0, b2i = 0;
        for (int i = 0; i < E_; i++) {
            float v = pr[i] * inv;
            atomicAdd(&g_probsum[i], v);
            if (v > b1v) { b2v = b1v; b2i = b1i; b1v = v; b1i = i; }
            else if (v > b2v) { b2v = v; b2i = i; }
        }
        g_topidx[t * 2] = b1i; g_topidx[t * 2 + 1] = b2i;
        g_topval[t * 2] = b1v; g_topval[t * 2 + 1] = b2v;
        atomicAdd(&g_counts[b1i], 1);
        atomicAdd(&g_counts[b2i], 1);
    }
}

// merged scan + place (single CTA)
__global__ void place1_kernel() {
    if (threadIdx.x == 0) {
        int o = 0;
        for (int e = 0; e < E_; e++) {
            g_offs[e] = o;
            g_cursor[e] = o;
            o += g_counts[e];
        }
        g_offs[E_] = o;
    }
    __syncthreads();
    for (int t = threadIdx.x; t < NTOK; t += 1024) {
        for (int kk = 0; kk < KSEL; kk++) {
            int e = g_topidx[t * 2 + kk];
            int slot = atomicAdd(&g_cursor[e], 1);
            g_perm[slot] = t;
            g_slotof[t * 2 + kk] = slot;
        }
    }
}

// 2-wide combine: half2 gathers from g_y, float2 residual/out
__global__ void combine_kernel(float* __restrict__ out) {
    int i = blockIdx.x * blockDim.x + threadIdx.x;
    if (i >= NTOK * D_ / 2) return;
    int t = i >> 9, d2 = i & 511;
    float2 v = ((const float2*)g_x2)[i];
    float w0 = g_topval[t * 2], w1 = g_topval[t * 2 + 1];
    __half2 y0 = ((const __half2*)(g_y + (size_t)g_slotof[t * 2] * D_))[d2];
    __half2 y1 = ((const __half2*)(g_y + (size_t)g_slotof[t * 2 + 1] * D_))[d2];
    float2 f0 = __half22float2(y0), f1 = __half22float2(y1);
    v.x += w0 * f0.x + w1 * f1.x;
    v.y += w0 * f0.y + w1 * f1.y;
    ((float2*)out)[i] = v;
}
__global__ void finalize_kernel(float* __restrict__ out) {
    if (threadIdx.x == 0) {
        float loss = 0.f;
        for (int e = 0; e < E_; e++)
            loss += ((float)g_counts[e] / (float)NSLOT) * (g_probsum[e] / (float)NTOK);
        loss *= (float)E_;
        out[(size_t)NTOK * D_] = loss;
        for (int e = 0; e < E_; e++)
            out[(size_t)NTOK * D_ + 1 + e] = (float)g_counts[e];
    }
}

// EPI: 0 half; 1 float + residual(addpF=[M,N] fp32); 2 float;
//      3 half exp(v/8) causal + atomic rowsum into addpF[z*S+r];
//      4 half v / addpF[z*S+r].
// mode: 0 none, 1 causal tile-skip, 2 k-clip (modes 1/2: heavy-first y remap).
// Single-sync mainloop: wait, sync, compute, issue(kt+NSTG-1).
template <bool TB, int NT, int EPI>
__global__ void __launch_bounds__(128, 2)
hgemm(const __half* __restrict__ A, int lda,
      const __half* __restrict__ B, int ldb,
      void* __restrict__ Cv, int ldc,
      int M, int N, int K,
      long long aO, long long aI, long long bO, long long bI,
      long long cO, long long cI, int zdiv,
      float* __restrict__ addpF, int mode) {
    constexpr int BSTH = NT + 8;
    constexpr int BSZB = TB ? ASZB : (64 * BSTH * 2);
    constexpr int STG  = ASZB + BSZB;
    constexpr int NTW  = NT / 16;
    extern __shared__ __align__(16) unsigned char smraw[];

    int z = blockIdx.z, zo = z / zdiv, zi = z % zdiv;
    A += zo * aO + zi * aI;
    B += zo * bO + zi * bI;

    int by = mode ? ((int)gridDim.y - 1 - (int)blockIdx.y) : (int)blockIdx.y;
    int m0 = by * 128, n0 = blockIdx.x * NT;
    if (mode == 1 && n0 > m0 + 127) return;
    int Keff = (mode == 2) ? min(K, m0 + 128) : K;
    int KT = Keff / BKH;

    int tid = threadIdx.x, wid = tid >> 5, lane = tid & 31;
    int warpM = wid & 1, warpN = wid >> 1;
    int g = lane >> 2, t = lane & 3;
    unsigned smb = (unsigned)__cvta_generic_to_shared(smraw);

    bool av = (m0 + tid) < M;
    const __half* aptr = A + (size_t)(av ? (m0 + tid) : 0) * lda;
    const __half* bptr = nullptr;
    bool bv = true;
    if (TB) {
        bv = (n0 + tid) < N;
        bptr = B + (size_t)(bv ? (n0 + tid) : 0) * ldb;
    }

    float acc[4][NTW][4];
#pragma unroll
    for (int mt = 0; mt < 4; mt++)
#pragma unroll
        for (int nt = 0; nt < NTW; nt++)
#pragma unroll
            for (int r = 0; r < 4; r++) acc[mt][nt][r] = 0.f;

    auto issue = [&](int lt) {
        int s = lt % NSTG;
        unsigned ab = smb + (unsigned)s * STG;
        const __half* as = aptr + lt * BKH;
        unsigned arow = ab + (unsigned)tid * (ASTH * 2);
#pragma unroll
        for (int c = 0; c < 8; c++)
            cpa16(arow + c * 16, as + c * 8, av);
        unsigned bb = ab + ASZB;
        if (TB) {
            const __half* bs = bptr + lt * BKH;
            unsigned br = bb + (unsigned)tid * (ASTH * 2);
#pragma unroll
            for (int c = 0; c < 8; c++)
                cpa16(br + c * 16, bs + c * 8, bv);
        } else {
            int row = tid >> 1;
            int cb = (tid & 1) * (NT / 16);
            const __half* bs = B + (size_t)(lt * BKH + row) * ldb + n0;
            unsigned br = bb + (unsigned)row * (BSTH * 2);
#pragma unroll
            for (int j = 0; j < NT / 16; j++)
                cpa16(br + (cb + j) * 16, bs + (cb + j) * 8, true);
        }
        cp_commit();
    };

#pragma unroll
    for (int i = 0; i < NSTG - 1; i++) {
        if (i < KT) issue(i); else cp_commit();
    }

    for (int kt = 0; kt < KT; kt++) {
        int b = kt % NSTG;
        asm volatile("cp.async.wait_group %0;\n" :: "n"(NSTG - 2));
        __syncthreads();

        unsigned aBase = smb + (unsigned)b * STG;
        unsigned bBase = aBase + ASZB;
#pragma unroll
        for (int ks = 0; ks < 4; ks++) {
            unsigned afr[4][4];
#pragma unroll
            for (int mt = 0; mt < 4; mt++) {
                int row = warpM * 64 + mt * 16 + (lane & 15);
                int kh = ks * 16 + ((lane >> 4) << 3);
                ldsm4(afr[mt][0], afr[mt][1], afr[mt][2], afr[mt][3],
                      aBase + (unsigned)(row * ASTH + kh) * 2);
            }
            unsigned bfr[NTW][2];
#pragma unroll
            for (int ntp = 0; ntp < NTW / 2; ntp++) {
                unsigned r0, r1, r2, r3;
                if (TB) {
                    int row = warpN * 64 + ntp * 16 + (lane & 15);
                    int kh = ks * 16 + ((lane >> 4) << 3);
                    ldsm4(r0, r1, r2, r3, bBase + (unsigned)(row * ASTH + kh) * 2);
                    bfr[2 * ntp][0] = r0; bfr[2 * ntp + 1][0] = r1;
                    bfr[2 * ntp][1] = r2; bfr[2 * ntp + 1][1] = r3;
                } else {
                    int krow = ks * 16 + (lane & 15);
                    int col = warpN * (NT / 2) + ntp * 16 + ((lane >> 4) << 3);
                    ldsm4t(r0, r1, r2, r3, bBase + (unsigned)(krow * BSTH + col) * 2);
                    bfr[2 * ntp][0] = r0; bfr[2 * ntp][1] = r1;
                    bfr[2 * ntp + 1][0] = r2; bfr[2 * ntp + 1][1] = r3;
                }
            }
#pragma unroll
            for (int mt = 0; mt < 4; mt++)
#pragma unroll
                for (int nt = 0; nt < NTW; nt++)
                    mma16816(acc[mt][nt], afr[mt], bfr[nt]);
        }
        if (kt + NSTG - 1 < KT) issue(kt + NSTG - 1); else cp_commit();
    }

#pragma unroll
    for (int mt = 0; mt < 4; mt++) {
#pragma unroll
        for (int half_ = 0; half_ < 2; half_++) {
            int r = m0 + warpM * 64 + mt * 16 + g + half_ * 8;
            float rsum = 0.f;
#pragma unroll
            for (int nt = 0; nt < NTW; nt++) {
                int col = n0 + warpN * (NT / 2) + nt * 8 + 2 * t;
                if (r < M && col < N) {
                    float v0 = acc[mt][nt][half_ * 2 + 0];
                    float v1 = acc[mt][nt][half_ * 2 + 1];
                    size_t cidx = (size_t)(zo * cO + zi * cI) + (size_t)r * ldc + col;
                    if (EPI == 0) {
                        *(__half2*)((__half*)Cv + cidx) = __floats2half2_rn(v0, v1);
                    } else if (EPI == 1) {
                        float2 ad = *(const float2*)(addpF + (size_t)r * ldc + col);
                        float2 o; o.x = v0 + ad.x; o.y = v1 + ad.y;
                        *(float2*)((float*)Cv + cidx) = o;
                    } else if (EPI == 2) {
                        float2 o; o.x = v0; o.y = v1;
                        *(float2*)((float*)Cv + cidx) = o;
                    } else if (EPI == 3) {
                        float e0 = (col     <= r) ? __expf(v0 * 0.125f) : 0.f;
                        float e1 = (col + 1 <= r) ? __expf(v1 * 0.125f) : 0.f;
                        rsum += e0 + e1;
                        *(__half2*)((__half*)Cv + cidx) = __floats2half2_rn(e0, e1);
                    } else {
                        float sc = 1.f / addpF[(size_t)z * S_ + r];
                        *(__half2*)((__half*)Cv + cidx) = __floats2half2_rn(v0 * sc, v1 * sc);
                    }
                }
            }
            if (EPI == 3) {
                rsum += __shfl_down_sync(0xffffffffu, rsum, 2);
                rsum += __shfl_down_sync(0xffffffffu, rsum, 1);
                if (t == 0 && r < M)
                    atomicAdd(&addpF[(size_t)z * S_ + r], rsum);
            }
        }
    }
}

// grouped MoE: 256 thr, 128x256, 3-stage, single-sync mainloop.
// EP 1: half(gelu(acc+bias)) -> g_act. EP 2: half(acc+bias) -> g_y.
template <int EP>
__global__ void __launch_bounds__(256, 1)
moe_hgemm(const __half* __restrict__ H, const __half* __restrict__ W,
          const float* __restrict__ Bias, int Kdim, int Ndim) {
    constexpr int BSTH = 264;
    constexpr int BSZB = 64 * BSTH * 2;
    constexpr int STG  = ASZB + BSZB;
    extern __shared__ __align__(16) unsigned char smraw[];

    int e = blockIdx.z;
    int base = g_offs[e], cnt = g_offs[e + 1] - base;
    int m0 = blockIdx.y * 128;
    if (m0 >= cnt) return;
    int n0 = blockIdx.x * 256;
    const __half* Bmat = W + (size_t)e * (size_t)Kdim * Ndim;

    int tid = threadIdx.x, wid = tid >> 5, lane = tid & 31;
    int warpM = wid & 1, warpN = wid >> 1;
    int g = lane >> 2, t = lane & 3;
    unsigned smb = (unsigned)__cvta_generic_to_shared(smraw);
    float* sBias = (float*)smraw;
    unsigned tb0 = smb + 1024;

    sBias[tid] = Bias[(size_t)e * Ndim + n0 + tid];

    int arow_i = tid >> 1;
    bool av = (m0 + arow_i) < cnt;
    const __half* aptr;
    if (EP == 1) aptr = H + (size_t)(av ? g_perm[base + m0 + arow_i] : 0) * Kdim;
    else         aptr = g_act + (size_t)(av ? (base + m0 + arow_i) : 0) * Kdim;
    int ahalf = (tid & 1) * 32;

    int brow = tid >> 2, bq = tid & 3;

    float acc[4][8][4];
#pragma unroll
    for (int mt = 0; mt < 4; mt++)
#pragma unroll
        for (int nt = 0; nt < 8; nt++)
#pragma unroll
            for (int r = 0; r < 4; r++) acc[mt][nt][r] = 0.f;

    int KT = Kdim / BKH;

    auto issue = [&](int lt) {
        int s = lt % NSTG;
        unsigned ab = tb0 + (unsigned)s * STG;
        const __half* as = aptr + lt * BKH + ahalf;
        unsigned ar = ab + (unsigned)arow_i * (ASTH * 2) + (unsigned)(tid & 1) * 64;
#pragma unroll
        for (int c = 0; c < 4; c++)
            cpa16(ar + c * 16, as + c * 8, av);
        unsigned bb = ab + ASZB;
        const __half* bs = Bmat + (size_t)(lt * BKH + brow) * Ndim + n0 + bq * 64;
        unsigned br = bb + (unsigned)brow * (BSTH * 2) + (unsigned)bq * 128;
#pragma unroll
        for (int c = 0; c < 8; c++)
            cpa16(br + c * 16, bs + c * 8, true);
        cp_commit();
    };

#pragma unroll
    for (int i = 0; i < NSTG - 1; i++) {
        if (i < KT) issue(i); else cp_commit();
    }

    for (int kt = 0; kt < KT; kt++) {
        int b = kt % NSTG;
        asm volatile("cp.async.wait_group %0;\n" :: "n"(NSTG - 2));
        __syncthreads();

        unsigned aBase = tb0 + (unsigned)b * STG;
        unsigned bBase = aBase + ASZB;
#pragma unroll
        for (int ks = 0; ks < 4; ks++) {
            unsigned afr[4][4];
#pragma unroll
            for (int mt = 0; mt < 4; mt++) {
                int row = warpM * 64 + mt * 16 + (lane & 15);
                int kh = ks * 16 + ((lane >> 4) << 3);
                ldsm4(afr[mt][0], afr[mt][1], afr[mt][2], afr[mt][3],
                      aBase + (unsigned)(row * ASTH + kh) * 2);
            }
            unsigned bfr[8][2];
#pragma unroll
            for (int ntp = 0; ntp < 4; ntp++) {
                unsigned r0, r1, r2, r3;
                int krow = ks * 16 + (lane & 15);
                int col = warpN * 64 + ntp * 16 + ((lane >> 4) << 3);
                ldsm4t(r0, r1, r2, r3, bBase + (unsigned)(krow * BSTH + col) * 2);
                bfr[2 * ntp][0] = r0; bfr[2 * ntp][1] = r1;
                bfr[2 * ntp + 1][0] = r2; bfr[2 * ntp + 1][1] = r3;
            }
#pragma unroll
            for (int mt = 0; mt < 4; mt++)
#pragma unroll
                for (int nt = 0; nt < 8; nt++)
                    mma16816(acc[mt][nt], afr[mt], bfr[nt]);
        }
        if (kt + NSTG - 1 < KT) issue(kt + NSTG - 1); else cp_commit();
    }

#pragma unroll
    for (int mt = 0; mt < 4; mt++) {
#pragma unroll
        for (int nt = 0; nt < 8; nt++) {
            int rr = m0 + warpM * 64 + mt * 16 + g;
            int colL = warpN * 64 + nt * 8 + 2 * t;
            int col = n0 + colL;
#pragma unroll
            for (int half_ = 0; half_ < 2; half_++) {
                int r = rr + half_ * 8;
                if (r < cnt) {
                    float v0 = acc[mt][nt][half_ * 2 + 0] + sBias[colL];
                    float v1 = acc[mt][nt][half_ * 2 + 1] + sBias[colL + 1];
                    if (EP == 1) {
                        *(__half2*)(g_act + (size_t)(base + r) * FF_ + col) =
                            __floats2half2_rn(gelu_tanh(v0), gelu_tanh(v1));
                    } else {
                        *(__half2*)(g_y + (size_t)(base + r) * D_ + col) =
                            __floats2half2_rn(v0, v1);
                    }
                }
            }
        }
    }
}

#define SMEM_NF128 (NSTG * (ASZB + 64 * 136 * 2))
#define SMEM_T128  (NSTG * (ASZB + ASZB))
#define SMEM_NF64  (NSTG * (ASZB + 64 * 72 * 2))
#define SMEM_MOE   (1024 + NSTG * (ASZB + 64 * 264 * 2))

extern "C" void kernel_launch(void* const* d_in, const int* in_sizes, int n_in,
                              void* d_out, int out_size) {
    const float* x   = (const float*)d_in[0];
    const float* anw = (const float*)d_in[1];
    const float* wq  = (const float*)d_in[2];
    const float* wk  = (const float*)d_in[3];
    const float* wv  = (const float*)d_in[4];
    const float* wo  = (const float*)d_in[5];
    const float* mnw = (const float*)d_in[6];
    const float* rw  = (const float*)d_in[7];
    const float* w1  = (const float*)d_in[8];
    const float* b1  = (const float*)d_in[9];
    const float* w2  = (const float*)d_in[10];
    const float* b2  = (const float*)d_in[11];
    float* out = (float*)d_out;

    cudaFuncSetAttribute(hgemm<false, 128, 0>, cudaFuncAttributeMaxDynamicSharedMemorySize, SMEM_NF128);
    cudaFuncSetAttribute(hgemm<false, 128, 1>, cudaFuncAttributeMaxDynamicSharedMemorySize, SMEM_NF128);
    cudaFuncSetAttribute(hgemm<true, 128, 3>,  cudaFuncAttributeMaxDynamicSharedMemorySize, SMEM_T128);
    cudaFuncSetAttribute(hgemm<false, 64, 4>,  cudaFuncAttributeMaxDynamicSharedMemorySize, SMEM_NF64);
    cudaFuncSetAttribute(moe_hgemm<1>,         cudaFuncAttributeMaxDynamicSharedMemorySize, SMEM_MOE);
    cudaFuncSetAttribute(moe_hgemm<2>,         cudaFuncAttributeMaxDynamicSharedMemorySize, SMEM_MOE);

    __half *xn, *wqkvh, *woh, *w1h, *w2h, *qkv, *probsH, *ao, *htf;
    float *x2, *rsum;
    cudaGetSymbolAddress((void**)&xn,     g_xn);
    cudaGetSymbolAddress((void**)&wqkvh,  g_wqkvh);
    cudaGetSymbolAddress((void**)&woh,    g_woh);
    cudaGetSymbolAddress((void**)&w1h,    g_w1h);
    cudaGetSymbolAddress((void**)&w2h,    g_w2h);
    cudaGetSymbolAddress((void**)&qkv,    g_qkv);
    cudaGetSymbolAddress((void**)&probsH, g_probsH);
    cudaGetSymbolAddress((void**)&rsum,   g_rowsum);
    cudaGetSymbolAddress((void**)&ao,     g_attnout);
    cudaGetSymbolAddress((void**)&x2,     g_x2);
    cudaGetSymbolAddress((void**)&htf,    g_htf);

    const __half* q = qkv;
    const __half* k = qkv + (size_t)NTOK * D_;
    const __half* v = qkv + 2 * (size_t)NTOK * D_;

    cudaStream_t s2;
    cudaEvent_t evFork, evJoin1, evJoin2;
    cudaStreamCreateWithFlags(&s2, cudaStreamNonBlocking);
    cudaEventCreateWithFlags(&evFork, cudaEventDisableTiming);
    cudaEventCreateWithFlags(&evJoin1, cudaEventDisableTiming);
    cudaEventCreateWithFlags(&evJoin2, cudaEventDisableTiming);

    init2_kernel<<<(BB_ * NH_ * S_ + 511) / 512, 512>>>();
    cudaEventRecord(evFork, 0);
    cudaStreamWaitEvent(s2, evFork, 0);

    f2h_kernel<<<4096, 256, 0, s2>>>((const float4*)w1, (uint4*)w1h, (long long)E_ * D_ * FF_ / 8);
    cudaEventRecord(evJoin1, s2);
    f2h_kernel<<<4096, 256, 0, s2>>>((const float4*)w2, (uint4*)w2h, (long long)E_ * FF_ * D_ / 8);
    cudaEventRecord(evJoin2, s2);

    f2h4_kernel<<<dim3(256, 4), 256>>>((const float4*)wq, (const float4*)wk,
                                       (const float4*)wv, (const float4*)wo,
                                       (uint4*)wqkvh, (uint4*)woh);
    rmsnorm_kernel<<<NTOK, 256>>>(x, anw, xn);

    hgemm<false, 128, 0><<<dim3(8, 16, 3), 128, SMEM_NF128>>>(
        xn, D_, wqkvh, D_, qkv, D_, NTOK, D_, D_,
        0, 0, (long long)D_ * D_, 0, (long long)NTOK * D_, 0, 1, nullptr, 0);

    {
        long long sSD = (long long)S_ * D_, sSS = (long long)S_ * S_;
        hgemm<true, 128, 3><<<dim3(8, 8, BB_ * NH_), 128, SMEM_T128>>>(
            q, D_, k, D_, probsH, S_, S_, S_, DH_,
            sSD, DH_, sSD, DH_, NH_ * sSS, sSS, NH_, rsum, 1);
    }

    {
        long long sSD = (long long)S_ * D_, sSS = (long long)S_ * S_;
        hgemm<false, 64, 4><<<dim3(1, 8, BB_ * NH_), 128, SMEM_NF64>>>(
            probsH, S_, v, D_, ao, D_, S_, DH_, S_,
            NH_ * sSS, sSS, sSD, DH_, sSD, DH_, NH_, rsum, 2);
    }

    hgemm<false, 128, 1><<<dim3(8, 16, 1), 128, SMEM_NF128>>>(
        ao, D_, woh, D_, x2, D_, NTOK, D_, D_,
        0, 0, 0, 0, 0, 0, 1, (float*)x, 0);

    rmsrouter_kernel<<<NTOK, 256>>>(x2, mnw, htf, rw);
    place1_kernel<<<1, 1024>>>();

    cudaStreamWaitEvent(0, evJoin1, 0);
    moe_hgemm<1><<<dim3(FF_ / 256, NSLOT / 128, E_), 256, SMEM_MOE>>>(htf, w1h, b1, D_, FF_);

    cudaStreamWaitEvent(0, evJoin2, 0);
    moe_hgemm<2><<<dim3(D_ / 256, NSLOT / 128, E_), 256, SMEM_MOE>>>(nullptr, w2h, b2, FF_, D_);

    combine_kernel<<<(NTOK * D_ / 2 + 255) / 256, 256>>>(out);
    finalize_kernel<<<1, 32>>>(out);
}

// round 16
// speedup vs baseline: 1.6903x; 1.0229x over previous
#include <cuda_runtime.h>
#include <cuda_fp16.h>
#include <math.h>
#include <stdint.h>

#define D_    1024
#define S_    1024
#define BB_   2
#define NTOK  2048
#define NH_   16
#define DH_   64
#define E_    8
#define KSEL  2
#define FF_   4096
#define NSLOT 4096

#define BKH   64
#define ASTH  72
#define ASZB  (128*ASTH*2)
#define NSTG  3             // hgemm stages (2 CTA/SM constraint)
#define MSTG  4             // moe stages (1 CTA/SM, smem allows 4)

__device__ __half g_xn[NTOK * D_];
__device__ __half g_wqkvh[3 * D_ * D_];
__device__ __half g_woh[D_ * D_];
__device__ __half g_w1h[(size_t)E_ * D_ * FF_];
__device__ __half g_w2h[(size_t)E_ * FF_ * D_];
__device__ __half g_qkv[3 * NTOK * D_];
__device__ __half g_probsH[(size_t)BB_ * NH_ * S_ * S_];
__device__ float  g_rowsum[BB_ * NH_ * S_];
__device__ __half g_attnout[NTOK * D_];
__device__ float  g_x2[NTOK * D_];
__device__ __half g_htf[NTOK * D_];
__device__ __half g_act[(size_t)NSLOT * FF_];
__device__ __half g_y[(size_t)NSLOT * D_];
__device__ float g_topval[NTOK * KSEL];
__device__ int   g_topidx[NTOK * KSEL];
__device__ int   g_slotof[NTOK * KSEL];
__device__ int   g_perm[NSLOT];
__device__ int   g_counts[E_];
__device__ int   g_offs[E_ + 1];
__device__ int   g_cursor[E_];
__device__ float g_probsum[E_];

__device__ __forceinline__ float gelu_tanh(float v) {
    float v3 = v * v * v;
    return 0.5f * v * (1.f + tanhf(0.7978845608028654f * (v + 0.044715f * v3)));
}
__device__ __forceinline__ void cpa16(unsigned dst, const void* src, bool p) {
    int sz = p ? 16 : 0;
    asm volatile("cp.async.cg.shared.global [%0], [%1], 16, %2;\n"
                 :: "r"(dst), "l"(src), "r"(sz));
}
__device__ __forceinline__ void cp_commit() { asm volatile("cp.async.commit_group;\n"); }
__device__ __forceinline__ void ldsm4(unsigned& r0, unsigned& r1, unsigned& r2, unsigned& r3,
                                      unsigned addr) {
    asm volatile("ldmatrix.sync.aligned.m8n8.x4.shared.b16 {%0,%1,%2,%3}, [%4];"
                 : "=r"(r0), "=r"(r1), "=r"(r2), "=r"(r3) : "r"(addr));
}
__device__ __forceinline__ void ldsm4t(unsigned& r0, unsigned& r1, unsigned& r2, unsigned& r3,
                                       unsigned addr) {
    asm volatile("ldmatrix.sync.aligned.m8n8.x4.trans.shared.b16 {%0,%1,%2,%3}, [%4];"
                 : "=r"(r0), "=r"(r1), "=r"(r2), "=r"(r3) : "r"(addr));
}
__device__ __forceinline__ void mma16816(float* d, const unsigned* a, const unsigned* b) {
    asm volatile(
        "mma.sync.aligned.m16n8k16.row.col.f32.f16.f16.f32 "
        "{%0,%1,%2,%3}, {%4,%5,%6,%7}, {%8,%9}, {%0,%1,%2,%3};"
        : "+f"(d[0]), "+f"(d[1]), "+f"(d[2]), "+f"(d[3])
        : "r"(a[0]), "r"(a[1]), "r"(a[2]), "r"(a[3]), "r"(b[0]), "r"(b[1]));
}

__global__ void init2_kernel() {
    int i = blockIdx.x * 512 + threadIdx.x;
    if (i < E_) { g_counts[i] = 0; g_cursor[i] = 0; g_probsum[i] = 0.f; }
    if (i < BB_ * NH_ * S_) g_rowsum[i] = 0.f;
}

__global__ void f2h_kernel(const float4* __restrict__ in, uint4* __restrict__ out,
                           long long n8) {
    for (long long i = blockIdx.x * 256LL + threadIdx.x; i < n8;
         i += (long long)gridDim.x * 256) {
        float4 a = in[2 * i], b = in[2 * i + 1];
        __half2 h0 = __floats2half2_rn(a.x, a.y);
        __half2 h1 = __floats2half2_rn(a.z, a.w);
        __half2 h2 = __floats2half2_rn(b.x, b.y);
        __half2 h3 = __floats2half2_rn(b.z, b.w);
        uint4 o;
        o.x = *(unsigned*)&h0; o.y = *(unsigned*)&h1;
        o.z = *(unsigned*)&h2; o.w = *(unsigned*)&h3;
        out[i] = o;
    }
}
__global__ void f2h4_kernel(const float4* __restrict__ a, const float4* __restrict__ b,
                            const float4* __restrict__ c, const float4* __restrict__ d,
                            uint4* __restrict__ oqkv, uint4* __restrict__ oo) {
    const float4* src[4] = { a, b, c, d };
    long long n8 = (long long)D_ * D_ / 8;
    uint4* dst;
    int z = blockIdx.y;
    if (z < 3) dst = oqkv + (size_t)z * n8;
    else       dst = oo;
    const float4* in = src[z];
    for (long long i = blockIdx.x * 256LL + threadIdx.x; i < n8;
         i += (long long)gridDim.x * 256) {
        float4 va = in[2 * i], vb = in[2 * i + 1];
        __half2 h0 = __floats2half2_rn(va.x, va.y);
        __half2 h1 = __floats2half2_rn(va.z, va.w);
        __half2 h2 = __floats2half2_rn(vb.x, vb.y);
        __half2 h3 = __floats2half2_rn(vb.z, vb.w);
        uint4 o;
        o.x = *(unsigned*)&h0; o.y = *(unsigned*)&h1;
        o.z = *(unsigned*)&h2; o.w = *(unsigned*)&h3;
        dst[i] = o;
    }
}
__global__ void rmsnorm_kernel(const float* __restrict__ X, const float* __restrict__ W,
                               __half* __restrict__ OT) {
    int t = blockIdx.x;
    const float* x = X + (size_t)t * D_;
    float ss = 0.f;
    for (int d = threadIdx.x; d < D_; d += 256) { float v = x[d]; ss += v * v; }
    __shared__ float red[256];
    red[threadIdx.x] = ss; __syncthreads();
    for (int s = 128; s > 0; s >>= 1) {
        if (threadIdx.x < s) red[threadIdx.x] += red[threadIdx.x + s];
        __syncthreads();
    }
    float scale = rsqrtf(red[0] * (1.f / D_) + 1e-6f);
    for (int d = threadIdx.x; d < D_; d += 256)
        OT[(size_t)t * D_ + d] = __float2half_rn(x[d] * scale * W[d]);
}

__global__ void rmsrouter_kernel(const float* __restrict__ X, const float* __restrict__ W,
                                 __half* __restrict__ OT, const float* __restrict__ RW) {
    int t = blockIdx.x;
    int tid = threadIdx.x;
    const float* x = X + (size_t)t * D_;
    __shared__ float hv[D_];
    __shared__ float red[256];
    float ss = 0.f;
    for (int d = tid; d < D_; d += 256) { float v = x[d]; ss += v * v; }
    red[tid] = ss; __syncthreads();
    for (int s = 128; s > 0; s >>= 1) {
        if (tid < s) red[tid] += red[tid + s];
        __syncthreads();
    }
    float scale = rsqrtf(red[0] * (1.f / D_) + 1e-6f);
    for (int d = tid; d < D_; d += 256) {
        float v = x[d] * scale * W[d];
        hv[d] = v;
        OT[(size_t)t * D_ + d] = __float2half_rn(v);
    }
    __syncthreads();

    int e = tid >> 5, lane = tid & 31;
    float p = 0.f;
    for (int d = lane; d < D_; d += 32) p += hv[d] * RW[d * E_ + e];
    for (int o = 16; o > 0; o >>= 1) p += __shfl_down_sync(0xffffffff, p, o);
    __shared__ float lg[E_];
    if (lane == 0) lg[e] = p;
    __syncthreads();
    if (tid == 0) {
        float mx = lg[0];
        for (int i = 1; i < E_; i++) mx = fmaxf(mx, lg[i]);
        float pr[E_]; float s = 0.f;
        for (int i = 0; i < E_; i++) { pr[i] = expf(lg[i] - mx); s += pr[i]; }
        float inv = 1.f / s;
        float b1v = -1.f, b2v = -1.f; int b1i = 0, b2i = 0;
        for (int i = 0; i < E_; i++) {
            float v = pr[i] * inv;
            atomicAdd(&g_probsum[i], v);
            if (v > b1v) { b2v = b1v; b2i = b1i; b1v = v; b1i = i; }
            else if (v > b2v) { b2v = v; b2i = i; }
        }
        g_topidx[t * 2] = b1i; g_topidx[t * 2 + 1] = b2i;
        g_topval[t * 2] = b1v; g_topval[t * 2 + 1] = b2v;
        atomicAdd(&g_counts[b1i], 1);
        atomicAdd(&g_counts[b2i], 1);
    }
}

__global__ void place1_kernel() {
    if (threadIdx.x == 0) {
        int o = 0;
        for (int e = 0; e < E_; e++) {
            g_offs[e] = o;
            g_cursor[e] = o;
            o += g_counts[e];
        }
        g_offs[E_] = o;
    }
    __syncthreads();
    for (int t = threadIdx.x; t < NTOK; t += 1024) {
        for (int kk = 0; kk < KSEL; kk++) {
            int e = g_topidx[t * 2 + kk];
            int slot = atomicAdd(&g_cursor[e], 1);
            g_perm[slot] = t;
            g_slotof[t * 2 + kk] = slot;
        }
    }
}

__global__ void combine_kernel(float* __restrict__ out) {
    int i = blockIdx.x * blockDim.x + threadIdx.x;
    if (i >= NTOK * D_ / 2) return;
    int t = i >> 9, d2 = i & 511;
    float2 v = ((const float2*)g_x2)[i];
    float w0 = g_topval[t * 2], w1 = g_topval[t * 2 + 1];
    __half2 y0 = ((const __half2*)(g_y + (size_t)g_slotof[t * 2] * D_))[d2];
    __half2 y1 = ((const __half2*)(g_y + (size_t)g_slotof[t * 2 + 1] * D_))[d2];
    float2 f0 = __half22float2(y0), f1 = __half22float2(y1);
    v.x += w0 * f0.x + w1 * f1.x;
    v.y += w0 * f0.y + w1 * f1.y;
    ((float2*)out)[i] = v;
}
__global__ void finalize_kernel(float* __restrict__ out) {
    if (threadIdx.x == 0) {
        float loss = 0.f;
        for (int e = 0; e < E_; e++)
            loss += ((float)g_counts[e] / (float)NSLOT) * (g_probsum[e] / (float)NTOK);
        loss *= (float)E_;
        out[(size_t)NTOK * D_] = loss;
        for (int e = 0; e < E_; e++)
            out[(size_t)NTOK * D_ + 1 + e] = (float)g_counts[e];
    }
}

// EPI: 0 half; 1 float + residual; 2 float; 3 half exp causal + atomic rowsum;
// 4 half v / rowsum. mode: 0 none, 1 causal tile-skip, 2 k-clip (heavy-first).
template <bool TB, int NT, int EPI>
__global__ void __launch_bounds__(128, 2)
hgemm(const __half* __restrict__ A, int lda,
      const __half* __restrict__ B, int ldb,
      void* __restrict__ Cv, int ldc,
      int M, int N, int K,
      long long aO, long long aI, long long bO, long long bI,
      long long cO, long long cI, int zdiv,
      float* __restrict__ addpF, int mode) {
    constexpr int BSTH = NT + 8;
    constexpr int BSZB = TB ? ASZB : (64 * BSTH * 2);
    constexpr int STG  = ASZB + BSZB;
    constexpr int NTW  = NT / 16;
    extern __shared__ __align__(16) unsigned char smraw[];

    int z = blockIdx.z, zo = z / zdiv, zi = z % zdiv;
    A += zo * aO + zi * aI;
    B += zo * bO + zi * bI;

    int by = mode ? ((int)gridDim.y - 1 - (int)blockIdx.y) : (int)blockIdx.y;
    int m0 = by * 128, n0 = blockIdx.x * NT;
    if (mode == 1 && n0 > m0 + 127) return;
    int Keff = (mode == 2) ? min(K, m0 + 128) : K;
    int KT = Keff / BKH;

    int tid = threadIdx.x, wid = tid >> 5, lane = tid & 31;
    int warpM = wid & 1, warpN = wid >> 1;
    int g = lane >> 2, t = lane & 3;
    unsigned smb = (unsigned)__cvta_generic_to_shared(smraw);

    bool av = (m0 + tid) < M;
    const __half* aptr = A + (size_t)(av ? (m0 + tid) : 0) * lda;
    const __half* bptr = nullptr;
    bool bv = true;
    if (TB) {
        bv = (n0 + tid) < N;
        bptr = B + (size_t)(bv ? (n0 + tid) : 0) * ldb;
    }

    float acc[4][NTW][4];
#pragma unroll
    for (int mt = 0; mt < 4; mt++)
#pragma unroll
        for (int nt = 0; nt < NTW; nt++)
#pragma unroll
            for (int r = 0; r < 4; r++) acc[mt][nt][r] = 0.f;

    auto issue = [&](int lt) {
        int s = lt % NSTG;
        unsigned ab = smb + (unsigned)s * STG;
        const __half* as = aptr + lt * BKH;
        unsigned arow = ab + (unsigned)tid * (ASTH * 2);
#pragma unroll
        for (int c = 0; c < 8; c++)
            cpa16(arow + c * 16, as + c * 8, av);
        unsigned bb = ab + ASZB;
        if (TB) {
            const __half* bs = bptr + lt * BKH;
            unsigned br = bb + (unsigned)tid * (ASTH * 2);
#pragma unroll
            for (int c = 0; c < 8; c++)
                cpa16(br + c * 16, bs + c * 8, bv);
        } else {
            int row = tid >> 1;
            int cb = (tid & 1) * (NT / 16);
            const __half* bs = B + (size_t)(lt * BKH + row) * ldb + n0;
            unsigned br = bb + (unsigned)row * (BSTH * 2);
#pragma unroll
            for (int j = 0; j < NT / 16; j++)
                cpa16(br + (cb + j) * 16, bs + (cb + j) * 8, true);
        }
        cp_commit();
    };

#pragma unroll
    for (int i = 0; i < NSTG - 1; i++) {
        if (i < KT) issue(i); else cp_commit();
    }

    for (int kt = 0; kt < KT; kt++) {
        int b = kt % NSTG;
        asm volatile("cp.async.wait_group %0;\n" :: "n"(NSTG - 2));
        __syncthreads();

        unsigned aBase = smb + (unsigned)b * STG;
        unsigned bBase = aBase + ASZB;
#pragma unroll
        for (int ks = 0; ks < 4; ks++) {
            unsigned afr[4][4];
#pragma unroll
            for (int mt = 0; mt < 4; mt++) {
                int row = warpM * 64 + mt * 16 + (lane & 15);
                int kh = ks * 16 + ((lane >> 4) << 3);
                ldsm4(afr[mt][0], afr[mt][1], afr[mt][2], afr[mt][3],
                      aBase + (unsigned)(row * ASTH + kh) * 2);
            }
            unsigned bfr[NTW][2];
#pragma unroll
            for (int ntp = 0; ntp < NTW / 2; ntp++) {
                unsigned r0, r1, r2, r3;
                if (TB) {
                    int row = warpN * 64 + ntp * 16 + (lane & 15);
                    int kh = ks * 16 + ((lane >> 4) << 3);
                    ldsm4(r0, r1, r2, r3, bBase + (unsigned)(row * ASTH + kh) * 2);
                    bfr[2 * ntp][0] = r0; bfr[2 * ntp + 1][0] = r1;
                    bfr[2 * ntp][1] = r2; bfr[2 * ntp + 1][1] = r3;
                } else {
                    int krow = ks * 16 + (lane & 15);
                    int col = warpN * (NT / 2) + ntp * 16 + ((lane >> 4) << 3);
                    ldsm4t(r0, r1, r2, r3, bBase + (unsigned)(krow * BSTH + col) * 2);
                    bfr[2 * ntp][0] = r0; bfr[2 * ntp][1] = r1;
                    bfr[2 * ntp + 1][0] = r2; bfr[2 * ntp + 1][1] = r3;
                }
            }
#pragma unroll
            for (int mt = 0; mt < 4; mt++)
#pragma unroll
                for (int nt = 0; nt < NTW; nt++)
                    mma16816(acc[mt][nt], afr[mt], bfr[nt]);
        }
        if (kt + NSTG - 1 < KT) issue(kt + NSTG - 1); else cp_commit();
    }

#pragma unroll
    for (int mt = 0; mt < 4; mt++) {
#pragma unroll
        for (int half_ = 0; half_ < 2; half_++) {
            int r = m0 + warpM * 64 + mt * 16 + g + half_ * 8;
            float rsum = 0.f;
#pragma unroll
            for (int nt = 0; nt < NTW; nt++) {
                int col = n0 + warpN * (NT / 2) + nt * 8 + 2 * t;
                if (r < M && col < N) {
                    float v0 = acc[mt][nt][half_ * 2 + 0];
                    float v1 = acc[mt][nt][half_ * 2 + 1];
                    size_t cidx = (size_t)(zo * cO + zi * cI) + (size_t)r * ldc + col;
                    if (EPI == 0) {
                        *(__half2*)((__half*)Cv + cidx) = __floats2half2_rn(v0, v1);
                    } else if (EPI == 1) {
                        float2 ad = *(const float2*)(addpF + (size_t)r * ldc + col);
                        float2 o; o.x = v0 + ad.x; o.y = v1 + ad.y;
                        *(float2*)((float*)Cv + cidx) = o;
                    } else if (EPI == 2) {
                        float2 o; o.x = v0; o.y = v1;
                        *(float2*)((float*)Cv + cidx) = o;
                    } else if (EPI == 3) {
                        float e0 = (col     <= r) ? __expf(v0 * 0.125f) : 0.f;
                        float e1 = (col + 1 <= r) ? __expf(v1 * 0.125f) : 0.f;
                        rsum += e0 + e1;
                        *(__half2*)((__half*)Cv + cidx) = __floats2half2_rn(e0, e1);
                    } else {
                        float sc = 1.f / addpF[(size_t)z * S_ + r];
                        *(__half2*)((__half*)Cv + cidx) = __floats2half2_rn(v0 * sc, v1 * sc);
                    }
                }
            }
            if (EPI == 3) {
                rsum += __shfl_down_sync(0xffffffffu, rsum, 2);
                rsum += __shfl_down_sync(0xffffffffu, rsum, 1);
                if (t == 0 && r < M)
                    atomicAdd(&addpF[(size_t)z * S_ + r], rsum);
            }
        }
    }
}

// grouped MoE: 256 thr, 128x256, 4-stage, single-sync mainloop.
template <int EP>
__global__ void __launch_bounds__(256, 1)
moe_hgemm(const __half* __restrict__ H, const __half* __restrict__ W,
          const float* __restrict__ Bias, int Kdim, int Ndim) {
    constexpr int BSTH = 264;
    constexpr int BSZB = 64 * BSTH * 2;
    constexpr int STG  = ASZB + BSZB;
    extern __shared__ __align__(16) unsigned char smraw[];

    int e = blockIdx.z;
    int base = g_offs[e], cnt = g_offs[e + 1] - base;
    int m0 = blockIdx.y * 128;
    if (m0 >= cnt) return;
    int n0 = blockIdx.x * 256;
    const __half* Bmat = W + (size_t)e * (size_t)Kdim * Ndim;

    int tid = threadIdx.x, wid = tid >> 5, lane = tid & 31;
    int warpM = wid & 1, warpN = wid >> 1;
    int g = lane >> 2, t = lane & 3;
    unsigned smb = (unsigned)__cvta_generic_to_shared(smraw);
    float* sBias = (float*)smraw;
    unsigned tb0 = smb + 1024;

    sBias[tid] = Bias[(size_t)e * Ndim + n0 + tid];

    int arow_i = tid >> 1;
    bool av = (m0 + arow_i) < cnt;
    const __half* aptr;
    if (EP == 1) aptr = H + (size_t)(av ? g_perm[base + m0 + arow_i] : 0) * Kdim;
    else         aptr = g_act + (size_t)(av ? (base + m0 + arow_i) : 0) * Kdim;
    int ahalf = (tid & 1) * 32;

    int brow = tid >> 2, bq = tid & 3;

    float acc[4][8][4];
#pragma unroll
    for (int mt = 0; mt < 4; mt++)
#pragma unroll
        for (int nt = 0; nt < 8; nt++)
#pragma unroll
            for (int r = 0; r < 4; r++) acc[mt][nt][r] = 0.f;

    int KT = Kdim / BKH;

    auto issue = [&](int lt) {
        int s = lt % MSTG;
        unsigned ab = tb0 + (unsigned)s * STG;
        const __half* as = aptr + lt * BKH + ahalf;
        unsigned ar = ab + (unsigned)arow_i * (ASTH * 2) + (unsigned)(tid & 1) * 64;
#pragma unroll
        for (int c = 0; c < 4; c++)
            cpa16(ar + c * 16, as + c * 8, av);
        unsigned bb = ab + ASZB;
        const __half* bs = Bmat + (size_t)(lt * BKH + brow) * Ndim + n0 + bq * 64;
        unsigned br = bb + (unsigned)brow * (BSTH * 2) + (unsigned)bq * 128;
#pragma unroll
        for (int c = 0; c < 8; c++)
            cpa16(br + c * 16, bs + c * 8, true);
        cp_commit();
    };

#pragma unroll
    for (int i = 0; i < MSTG - 1; i++) {
        if (i < KT) issue(i); else cp_commit();
    }

    for (int kt = 0; kt < KT; kt++) {
        int b = kt % MSTG;
        asm volatile("cp.async.wait_group %0;\n" :: "n"(MSTG - 2));
        __syncthreads();

        unsigned aBase = tb0 + (unsigned)b * STG;
        unsigned bBase = aBase + ASZB;
#pragma unroll
        for (int ks = 0; ks < 4; ks++) {
            unsigned afr[4][4];
#pragma unroll
            for (int mt = 0; mt < 4; mt++) {
                int row = warpM * 64 + mt * 16 + (lane & 15);
                int kh = ks * 16 + ((lane >> 4) << 3);
                ldsm4(afr[mt][0], afr[mt][1], afr[mt][2], afr[mt][3],
                      aBase + (unsigned)(row * ASTH + kh) * 2);
            }
            unsigned bfr[8][2];
#pragma unroll
            for (int ntp = 0; ntp < 4; ntp++) {
                unsigned r0, r1, r2, r3;
                int krow = ks * 16 + (lane & 15);
                int col = warpN * 64 + ntp * 16 + ((lane >> 4) << 3);
                ldsm4t(r0, r1, r2, r3, bBase + (unsigned)(krow * BSTH + col) * 2);
                bfr[2 * ntp][0] = r0; bfr[2 * ntp][1] = r1;
                bfr[2 * ntp + 1][0] = r2; bfr[2 * ntp + 1][1] = r3;
            }
#pragma unroll
            for (int mt = 0; mt < 4; mt++)
#pragma unroll
                for (int nt = 0; nt < 8; nt++)
                    mma16816(acc[mt][nt], afr[mt], bfr[nt]);
        }
        if (kt + MSTG - 1 < KT) issue(kt + MSTG - 1); else cp_commit();
    }

#pragma unroll
    for (int mt = 0; mt < 4; mt++) {
#pragma unroll
        for (int nt = 0; nt < 8; nt++) {
            int rr = m0 + warpM * 64 + mt * 16 + g;
            int colL = warpN * 64 + nt * 8 + 2 * t;
            int col = n0 + colL;
#pragma unroll
            for (int half_ = 0; half_ < 2; half_++) {
                int r = rr + half_ * 8;
                if (r < cnt) {
                    float v0 = acc[mt][nt][half_ * 2 + 0] + sBias[colL];
                    float v1 = acc[mt][nt][half_ * 2 + 1] + sBias[colL + 1];
                    if (EP == 1) {
                        *(__half2*)(g_act + (size_t)(base + r) * FF_ + col) =
                            __floats2half2_rn(gelu_tanh(v0), gelu_tanh(v1));
                    } else {
                        *(__half2*)(g_y + (size_t)(base + r) * D_ + col) =
                            __floats2half2_rn(v0, v1);
                    }
                }
            }
        }
    }
}

#define SMEM_NF128 (NSTG * (ASZB + 64 * 136 * 2))
#define SMEM_T128  (NSTG * (ASZB + ASZB))
#define SMEM_NF64  (NSTG * (ASZB + 64 * 72 * 2))
#define SMEM_MOE   (1024 + MSTG * (ASZB + 64 * 264 * 2))   // 209920

extern "C" void kernel_launch(void* const* d_in, const int* in_sizes, int n_in,
                              void* d_out, int out_size) {
    const float* x   = (const float*)d_in[0];
    const float* anw = (const float*)d_in[1];
    const float* wq  = (const float*)d_in[2];
    const float* wk  = (const float*)d_in[3];
    const float* wv  = (const float*)d_in[4];
    const float* wo  = (const float*)d_in[5];
    const float* mnw = (const float*)d_in[6];
    const float* rw  = (const float*)d_in[7];
    const float* w1  = (const float*)d_in[8];
    const float* b1  = (const float*)d_in[9];
    const float* w2  = (const float*)d_in[10];
    const float* b2  = (const float*)d_in[11];
    float* out = (float*)d_out;

    cudaFuncSetAttribute(hgemm<false, 128, 0>, cudaFuncAttributeMaxDynamicSharedMemorySize, SMEM_NF128);
    cudaFuncSetAttribute(hgemm<false, 128, 1>, cudaFuncAttributeMaxDynamicSharedMemorySize, SMEM_NF128);
    cudaFuncSetAttribute(hgemm<true, 128, 3>,  cudaFuncAttributeMaxDynamicSharedMemorySize, SMEM_T128);
    cudaFuncSetAttribute(hgemm<false, 64, 4>,  cudaFuncAttributeMaxDynamicSharedMemorySize, SMEM_NF64);
    cudaFuncSetAttribute(moe_hgemm<1>,         cudaFuncAttributeMaxDynamicSharedMemorySize, SMEM_MOE);
    cudaFuncSetAttribute(moe_hgemm<2>,         cudaFuncAttributeMaxDynamicSharedMemorySize, SMEM_MOE);

    __half *xn, *wqkvh, *woh, *w1h, *w2h, *qkv, *probsH, *ao, *htf;
    float *x2, *rsum;
    cudaGetSymbolAddress((void**)&xn,     g_xn);
    cudaGetSymbolAddress((void**)&wqkvh,  g_wqkvh);
    cudaGetSymbolAddress((void**)&woh,    g_woh);
    cudaGetSymbolAddress((void**)&w1h,    g_w1h);
    cudaGetSymbolAddress((void**)&w2h,    g_w2h);
    cudaGetSymbolAddress((void**)&qkv,    g_qkv);
    cudaGetSymbolAddress((void**)&probsH, g_probsH);
    cudaGetSymbolAddress((void**)&rsum,   g_rowsum);
    cudaGetSymbolAddress((void**)&ao,     g_attnout);
    cudaGetSymbolAddress((void**)&x2,     g_x2);
    cudaGetSymbolAddress((void**)&htf,    g_htf);

    const __half* q = qkv;
    const __half* k = qkv + (size_t)NTOK * D_;
    const __half* v = qkv + 2 * (size_t)NTOK * D_;

    cudaStream_t s2;
    cudaEvent_t evFork, evQW, evJoin1, evJoin2;
    cudaStreamCreateWithFlags(&s2, cudaStreamNonBlocking);
    cudaEventCreateWithFlags(&evFork, cudaEventDisableTiming);
    cudaEventCreateWithFlags(&evQW, cudaEventDisableTiming);
    cudaEventCreateWithFlags(&evJoin1, cudaEventDisableTiming);
    cudaEventCreateWithFlags(&evJoin2, cudaEventDisableTiming);

    init2_kernel<<<(BB_ * NH_ * S_ + 511) / 512, 512>>>();
    cudaEventRecord(evFork, 0);
    cudaStreamWaitEvent(s2, evFork, 0);

    // side stream: small converts first (QKV needs them), then big MoE converts
    f2h4_kernel<<<dim3(256, 4), 256, 0, s2>>>((const float4*)wq, (const float4*)wk,
                                              (const float4*)wv, (const float4*)wo,
                                              (uint4*)wqkvh, (uint4*)woh);
    cudaEventRecord(evQW, s2);
    f2h_kernel<<<4096, 256, 0, s2>>>((const float4*)w1, (uint4*)w1h, (long long)E_ * D_ * FF_ / 8);
    cudaEventRecord(evJoin1, s2);
    f2h_kernel<<<4096, 256, 0, s2>>>((const float4*)w2, (uint4*)w2h, (long long)E_ * FF_ * D_ / 8);
    cudaEventRecord(evJoin2, s2);

    // main stream: rmsnorm overlaps f2h4
    rmsnorm_kernel<<<NTOK, 256>>>(x, anw, xn);
    cudaStreamWaitEvent(0, evQW, 0);

    hgemm<false, 128, 0><<<dim3(8, 16, 3), 128, SMEM_NF128>>>(
        xn, D_, wqkvh, D_, qkv, D_, NTOK, D_, D_,
        0, 0, (long long)D_ * D_, 0, (long long)NTOK * D_, 0, 1, nullptr, 0);

    {
        long long sSD = (long long)S_ * D_, sSS = (long long)S_ * S_;
        hgemm<true, 128, 3><<<dim3(8, 8, BB_ * NH_), 128, SMEM_T128>>>(
            q, D_, k, D_, probsH, S_, S_, S_, DH_,
            sSD, DH_, sSD, DH_, NH_ * sSS, sSS, NH_, rsum, 1);
    }

    {
        long long sSD = (long long)S_ * D_, sSS = (long long)S_ * S_;
        hgemm<false, 64, 4><<<dim3(1, 8, BB_ * NH_), 128, SMEM_NF64>>>(
            probsH, S_, v, D_, ao, D_, S_, DH_, S_,
            NH_ * sSS, sSS, sSD, DH_, sSD, DH_, NH_, rsum, 2);
    }

    hgemm<false, 128, 1><<<dim3(8, 16, 1), 128, SMEM_NF128>>>(
        ao, D_, woh, D_, x2, D_, NTOK, D_, D_,
        0, 0, 0, 0, 0, 0, 1, (float*)x, 0);

    rmsrouter_kernel<<<NTOK, 256>>>(x2, mnw, htf, rw);
    place1_kernel<<<1, 1024>>>();

    cudaStreamWaitEvent(0, evJoin1, 0);
    moe_hgemm<1><<<dim3(FF_ / 256, NSLOT / 128, E_), 256, SMEM_MOE>>>(htf, w1h, b1, D_, FF_);

    cudaStreamWaitEvent(0, evJoin2, 0);
    moe_hgemm<2><<<dim3(D_ / 256, NSLOT / 128, E_), 256, SMEM_MOE>>>(nullptr, w2h, b2, FF_, D_);

    combine_kernel<<<(NTOK * D_ / 2 + 255) / 256, 256>>>(out);
    finalize_kernel<<<1, 32>>>(out);
}